// round 1
// baseline (speedup 1.0000x reference)
#include <cuda_runtime.h>
#include <math.h>

#define BATCHN 4
#define SEQ    2048
#define EMBD   512
#define HEADS  8
#define HE     4096            // HEADS * EMBD
#define MROWS  8192            // BATCHN * SEQ

// Scratch (allocation-free: device globals)
__device__ float g_Q [(size_t)MROWS * HE];
__device__ float g_K [(size_t)MROWS * HE];
__device__ float g_V [(size_t)MROWS * HE];
__device__ float g_S [(size_t)BATCHN * HEADS * SEQ * SEQ];
__device__ float g_AO[(size_t)MROWS * HE];

// ---------------------------------------------------------------------------
// Generic batched SGEMM: C = alpha * A(MxK) * op(B) + bias
//   TB=false: B is K x N row-major (ldb = row stride)
//   TB=true : B is N x K row-major (C = A * B^T)
// Batch via blockIdx.z decomposed as (zb, zh) with zh = z % Hdiv.
// BM=BN=128, BK=8, 256 threads, 8x8 microtile per thread.
// ---------------------------------------------------------------------------
template<bool TB>
__global__ __launch_bounds__(256, 2)
void sgemm_kernel(const float* __restrict__ Ag, const float* __restrict__ Bg,
                  float* __restrict__ Cg,
                  int M, int N, int K, int lda, int ldb, int ldc,
                  long sAb, long sAh, long sBb, long sBh, long sCb, long sCh,
                  int Hdiv, float alpha, const float* __restrict__ bias)
{
    const int zb = blockIdx.z / Hdiv;
    const int zh = blockIdx.z % Hdiv;
    const float* A  = Ag + zb * sAb + zh * sAh;
    const float* Bp = Bg + zb * sBb + zh * sBh;
    float*       C  = Cg + zb * sCb + zh * sCh;

    __shared__ float As[8][128];
    __shared__ float Bs[8][128];

    const int tid = threadIdx.x;
    const int m0 = blockIdx.y * 128;
    const int n0 = blockIdx.x * 128;

    // gmem -> smem staging maps
    const int arow = tid >> 1;            // 0..127
    const int acp  = (tid & 1) * 4;       // 0 or 4
    const int bkr  = tid >> 5;            // NN: k-row 0..7
    const int bnc  = (tid & 31) * 4;      // NN: n-col

    // compute tile map (16x16 threads of 8x8)
    const int mm = (tid >> 4) * 8;
    const int nn = (tid & 15) * 8;

    float acc[8][8];
#pragma unroll
    for (int i = 0; i < 8; ++i)
#pragma unroll
        for (int j = 0; j < 8; ++j) acc[i][j] = 0.f;

    float4 pa, pb;
    pa = *(const float4*)(A + (size_t)(m0 + arow) * lda + acp);
    if (TB)
        pb = *(const float4*)(Bp + (size_t)(n0 + arow) * ldb + acp);
    else
        pb = *(const float4*)(Bp + (size_t)bkr * ldb + n0 + bnc);

    const int nt = K >> 3;
    for (int kt = 0; kt < nt; ++kt) {
        // stage current tile to smem
        As[acp + 0][arow] = pa.x; As[acp + 1][arow] = pa.y;
        As[acp + 2][arow] = pa.z; As[acp + 3][arow] = pa.w;
        if (TB) {
            Bs[acp + 0][arow] = pb.x; Bs[acp + 1][arow] = pb.y;
            Bs[acp + 2][arow] = pb.z; Bs[acp + 3][arow] = pb.w;
        } else {
            *(float4*)(&Bs[bkr][bnc]) = pb;
        }
        __syncthreads();

        // prefetch next tile into registers
        if (kt + 1 < nt) {
            const int k0 = (kt + 1) << 3;
            pa = *(const float4*)(A + (size_t)(m0 + arow) * lda + k0 + acp);
            if (TB)
                pb = *(const float4*)(Bp + (size_t)(n0 + arow) * ldb + k0 + acp);
            else
                pb = *(const float4*)(Bp + (size_t)(k0 + bkr) * ldb + n0 + bnc);
        }

#pragma unroll
        for (int kk = 0; kk < 8; ++kk) {
            float a[8], b[8];
            *(float4*)(a)     = *(const float4*)(&As[kk][mm]);
            *(float4*)(a + 4) = *(const float4*)(&As[kk][mm + 4]);
            *(float4*)(b)     = *(const float4*)(&Bs[kk][nn]);
            *(float4*)(b + 4) = *(const float4*)(&Bs[kk][nn + 4]);
#pragma unroll
            for (int i = 0; i < 8; ++i)
#pragma unroll
                for (int j = 0; j < 8; ++j)
                    acc[i][j] = fmaf(a[i], b[j], acc[i][j]);
        }
        __syncthreads();
    }

    // epilogue
#pragma unroll
    for (int i = 0; i < 8; ++i) {
        const size_t cro = (size_t)(m0 + mm + i) * ldc + n0 + nn;
#pragma unroll
        for (int j4 = 0; j4 < 8; j4 += 4) {
            float4 r;
            r.x = alpha * acc[i][j4 + 0];
            r.y = alpha * acc[i][j4 + 1];
            r.z = alpha * acc[i][j4 + 2];
            r.w = alpha * acc[i][j4 + 3];
            if (bias) {
                r.x += bias[n0 + nn + j4 + 0];
                r.y += bias[n0 + nn + j4 + 1];
                r.z += bias[n0 + nn + j4 + 2];
                r.w += bias[n0 + nn + j4 + 3];
            }
            *(float4*)(C + cro + j4) = r;
        }
    }
}

// ---------------------------------------------------------------------------
// Row softmax over SEQ=2048 elements, in place. One block (256 thr) per row.
// ---------------------------------------------------------------------------
__global__ void softmax_rows(float* __restrict__ S)
{
    float* p = S + (size_t)blockIdx.x * SEQ;
    const int tid = threadIdx.x;

    float v[8];
    float mx = -1e30f;
#pragma unroll
    for (int i = 0; i < 8; ++i) {
        v[i] = p[tid + 256 * i];
        mx = fmaxf(mx, v[i]);
    }

    __shared__ float red[256];
    red[tid] = mx;
    __syncthreads();
    for (int s = 128; s > 0; s >>= 1) {
        if (tid < s) red[tid] = fmaxf(red[tid], red[tid + s]);
        __syncthreads();
    }
    mx = red[0];
    __syncthreads();

    float sum = 0.f;
#pragma unroll
    for (int i = 0; i < 8; ++i) {
        v[i] = expf(v[i] - mx);
        sum += v[i];
    }
    red[tid] = sum;
    __syncthreads();
    for (int s = 128; s > 0; s >>= 1) {
        if (tid < s) red[tid] += red[tid + s];
        __syncthreads();
    }
    const float inv = 1.f / red[0];
#pragma unroll
    for (int i = 0; i < 8; ++i)
        p[tid + 256 * i] = v[i] * inv;
}

// ---------------------------------------------------------------------------
// Launch: x,Wq,bq,Wk,bk,Wv,bv,Wo,bo  ->  out [8192, 512] fp32
// ---------------------------------------------------------------------------
extern "C" void kernel_launch(void* const* d_in, const int* in_sizes, int n_in,
                              void* d_out, int out_size)
{
    const float* x  = (const float*)d_in[0];
    const float* Wq = (const float*)d_in[1];
    const float* bq = (const float*)d_in[2];
    const float* Wk = (const float*)d_in[3];
    const float* bk = (const float*)d_in[4];
    const float* Wv = (const float*)d_in[5];
    const float* bv = (const float*)d_in[6];
    const float* Wo = (const float*)d_in[7];
    const float* bo = (const float*)d_in[8];
    float* out = (float*)d_out;

    float *pQ, *pK, *pV, *pS, *pAO;
    cudaGetSymbolAddress((void**)&pQ,  g_Q);
    cudaGetSymbolAddress((void**)&pK,  g_K);
    cudaGetSymbolAddress((void**)&pV,  g_V);
    cudaGetSymbolAddress((void**)&pS,  g_S);
    cudaGetSymbolAddress((void**)&pAO, g_AO);

    const dim3 blk(256);
    const float scale = 1.0f / sqrtf((float)EMBD);   // (k^-1/4)^2 folded into scores

    // 1-3) QKV projections: [8192,512] @ [512,4096] + bias -> [8192,4096]
    {
        dim3 g(HE / 128, MROWS / 128, 1);
        sgemm_kernel<false><<<g, blk>>>(x, Wq, pQ, MROWS, HE, EMBD, EMBD, HE, HE,
                                        0, 0, 0, 0, 0, 0, 1, 1.f, bq);
        sgemm_kernel<false><<<g, blk>>>(x, Wk, pK, MROWS, HE, EMBD, EMBD, HE, HE,
                                        0, 0, 0, 0, 0, 0, 1, 1.f, bk);
        sgemm_kernel<false><<<g, blk>>>(x, Wv, pV, MROWS, HE, EMBD, EMBD, HE, HE,
                                        0, 0, 0, 0, 0, 0, 1, 1.f, bv);
    }

    // 4) scores[b,h] = scale * Q[b,h] @ K[b,h]^T : 32 batches of [2048,512]x[2048,512]^T
    {
        dim3 g(SEQ / 128, SEQ / 128, BATCHN * HEADS);
        sgemm_kernel<true><<<g, blk>>>(pQ, pK, pS, SEQ, SEQ, EMBD, HE, HE, SEQ,
                                       (long)SEQ * HE, (long)EMBD,
                                       (long)SEQ * HE, (long)EMBD,
                                       (long)HEADS * SEQ * SEQ, (long)SEQ * SEQ,
                                       HEADS, scale, nullptr);
    }

    // 5) softmax rows
    softmax_rows<<<BATCHN * HEADS * SEQ, 256>>>(pS);

    // 6) AO[b,h] = W[b,h] @ V[b,h] : [2048,2048] x [2048,512]
    {
        dim3 g(EMBD / 128, SEQ / 128, BATCHN * HEADS);
        sgemm_kernel<false><<<g, blk>>>(pS, pV, pAO, SEQ, EMBD, SEQ, SEQ, HE, HE,
                                        (long)HEADS * SEQ * SEQ, (long)SEQ * SEQ,
                                        (long)SEQ * HE, (long)EMBD,
                                        (long)SEQ * HE, (long)EMBD,
                                        HEADS, 1.f, nullptr);
    }

    // 7) out = AO @ Wo + bo : [8192,4096] x [4096,512]
    {
        dim3 g(EMBD / 128, MROWS / 128, 1);
        sgemm_kernel<false><<<g, blk>>>(pAO, Wo, out, MROWS, EMBD, HE, HE, EMBD, EMBD,
                                        0, 0, 0, 0, 0, 0, 1, 1.f, bo);
    }
}

// round 3
// speedup vs baseline: 2.5739x; 2.5739x over previous
#include <cuda_runtime.h>
#include <math.h>
#include <stdint.h>

#define BATCHN 4
#define SEQ    2048
#define EMBD   512
#define HEADS  8
#define HE     4096            // HEADS * EMBD
#define MROWS  8192            // BATCHN * SEQ

// ---------------------------------------------------------------------------
// Scratch (allocation-free: device globals)
// ---------------------------------------------------------------------------
__device__ float g_Q  [(size_t)MROWS * HE];
__device__ float g_K  [(size_t)MROWS * HE];
__device__ float g_V  [(size_t)MROWS * HE];
__device__ float g_VT [(size_t)BATCHN * HEADS * EMBD * SEQ];   // per-head V^T [512,2048]
__device__ float g_S  [(size_t)BATCHN * HEADS * SEQ * SEQ];
__device__ float g_AO [(size_t)MROWS * HE];
__device__ float g_WqT[(size_t)HE * EMBD];
__device__ float g_WkT[(size_t)HE * EMBD];
__device__ float g_WvT[(size_t)HE * EMBD];
__device__ float g_WoT[(size_t)EMBD * HE];

// ---------------------------------------------------------------------------
// helpers
// ---------------------------------------------------------------------------
__device__ __forceinline__ uint32_t smem_u32(const void* p) {
    uint32_t a;
    asm("{ .reg .u64 t; cvta.to.shared.u64 t, %1; cvt.u32.u64 %0, t; }" : "=r"(a) : "l"(p));
    return a;
}
__device__ __forceinline__ uint32_t f2tf32(float f) {
    uint32_t u;
    asm("cvt.rna.tf32.f32 %0, %1;" : "=r"(u) : "f"(f));
    return u;
}
__device__ __forceinline__ void mma_tf32(float& c0, float& c1, float& c2, float& c3,
                                         uint32_t a0, uint32_t a1, uint32_t a2, uint32_t a3,
                                         uint32_t b0, uint32_t b1) {
    asm volatile("mma.sync.aligned.m16n8k8.row.col.f32.tf32.tf32.f32 "
                 "{%0,%1,%2,%3},{%4,%5,%6,%7},{%8,%9},{%0,%1,%2,%3};"
                 : "+f"(c0), "+f"(c1), "+f"(c2), "+f"(c3)
                 : "r"(a0), "r"(a1), "r"(a2), "r"(a3), "r"(b0), "r"(b1));
}
#define CP_ASYNC16(s, g)  asm volatile("cp.async.cg.shared.global [%0], [%1], 16;" :: "r"(s), "l"(g) : "memory")
#define CP_COMMIT()       asm volatile("cp.async.commit_group;" ::: "memory")
#define CP_WAIT2()        asm volatile("cp.async.wait_group 2;" ::: "memory")

// ---------------------------------------------------------------------------
// tf32 NT GEMM: C[M,N] = alpha * A[M,K] * B[N,K]^T (+ bias)
// A K-major (lda), B K-major (ldb). M%128==0, N%128==0, K%16==0.
// CTA 128x128xBK16, 256 threads, warp tile 64x32 (4x4 m16n8k8), 4-stage cp.async.
// ---------------------------------------------------------------------------
#define BM 128
#define BN 128
#define BK 16
#define RS 20                          // padded row stride (floats): conflict-free
#define TILE_FLOATS (128 * RS)         // 2560 floats = 10240 B per operand tile
#define STAGE_FLOATS (2 * TILE_FLOATS) // A + B
#define NSTAGE 4
#define SMEM_NEED (NSTAGE * STAGE_FLOATS * 4)   // 81920 B

__global__ __launch_bounds__(256, 2)
void tf32_gemm(const float* __restrict__ Ag, const float* __restrict__ Bg,
               float* __restrict__ Cg, int K,
               long lda, long ldb, long ldc,
               long sAb, long sAh, long sBb, long sBh, long sCb, long sCh,
               int Hdiv, float alpha, const float* __restrict__ bias)
{
    extern __shared__ float smem[];
    const uint32_t sbase = smem_u32(smem);

    const int tid  = threadIdx.x;
    const int wid  = tid >> 5;
    const int lane = tid & 31;
    const int wm   = wid >> 2;         // 0..1  -> 64-row slab
    const int wn   = wid & 3;          // 0..3  -> 32-col slab
    const int lg   = lane >> 2;        // 0..7
    const int lr   = lane & 3;         // 0..3

    const int zb = blockIdx.z / Hdiv;
    const int zh = blockIdx.z % Hdiv;
    const float* A = Ag + zb * sAb + zh * sAh;
    const float* B = Bg + zb * sBb + zh * sBh;
    float*       C = Cg + zb * sCb + zh * sCh;

    const int m0 = blockIdx.y * BM;
    const int n0 = blockIdx.x * BN;

    float acc[4][4][4];
#pragma unroll
    for (int i = 0; i < 4; ++i)
#pragma unroll
        for (int j = 0; j < 4; ++j)
#pragma unroll
            for (int l = 0; l < 4; ++l) acc[i][j][l] = 0.f;

    const int NT = K >> 4;

    // stage loader: A 128x16 + B 128x16, 16B chunks, 4 chunks/row
    auto load_stage = [&](int kt) {
        const int ring = kt & (NSTAGE - 1);
        const uint32_t base = sbase + ring * (STAGE_FLOATS * 4);
        const int k0 = kt << 4;
#pragma unroll
        for (int i = 0; i < 2; ++i) {
            int id = tid + i * 256;
            int row = id >> 2, ch = id & 3;
            CP_ASYNC16(base + row * (RS * 4) + ch * 16,
                       A + (size_t)(m0 + row) * lda + k0 + ch * 4);
        }
#pragma unroll
        for (int i = 0; i < 2; ++i) {
            int id = tid + i * 256;
            int row = id >> 2, ch = id & 3;
            CP_ASYNC16(base + TILE_FLOATS * 4 + row * (RS * 4) + ch * 16,
                       B + (size_t)(n0 + row) * ldb + k0 + ch * 4);
        }
        CP_COMMIT();
    };

    load_stage(0); load_stage(1); load_stage(2);

    for (int kt = 0; kt < NT; ++kt) {
        const int ring = kt & (NSTAGE - 1);
        CP_WAIT2();
        __syncthreads();

        // prefetch stage kt+3 (or empty commit to keep wait_group math exact)
        if (kt + 3 < NT) load_stage(kt + 3); else CP_COMMIT();

        const float* sA = smem + ring * STAGE_FLOATS;
        const float* sB = sA + TILE_FLOATS;

#pragma unroll
        for (int ks = 0; ks < 2; ++ks) {
            const int k = ks * 8 + lr;
            uint32_t af[4][4], bf[4][2];
#pragma unroll
            for (int mt = 0; mt < 4; ++mt) {
                const int m = wm * 64 + mt * 16 + lg;
                af[mt][0] = f2tf32(sA[m * RS + k]);
                af[mt][1] = f2tf32(sA[(m + 8) * RS + k]);
                af[mt][2] = f2tf32(sA[m * RS + k + 4]);
                af[mt][3] = f2tf32(sA[(m + 8) * RS + k + 4]);
            }
#pragma unroll
            for (int nt = 0; nt < 4; ++nt) {
                const int n = wn * 32 + nt * 8 + lg;
                bf[nt][0] = f2tf32(sB[n * RS + k]);
                bf[nt][1] = f2tf32(sB[n * RS + k + 4]);
            }
#pragma unroll
            for (int mt = 0; mt < 4; ++mt)
#pragma unroll
                for (int nt = 0; nt < 4; ++nt)
                    mma_tf32(acc[mt][nt][0], acc[mt][nt][1], acc[mt][nt][2], acc[mt][nt][3],
                             af[mt][0], af[mt][1], af[mt][2], af[mt][3],
                             bf[nt][0], bf[nt][1]);
        }
        __syncthreads();
    }

    // epilogue: direct register -> gmem float2 stores
#pragma unroll
    for (int mt = 0; mt < 4; ++mt) {
#pragma unroll
        for (int nt = 0; nt < 4; ++nt) {
            const int r0 = m0 + wm * 64 + mt * 16 + lg;
            const int c0 = n0 + wn * 32 + nt * 8 + 2 * lr;
            float b0v = 0.f, b1v = 0.f;
            if (bias) { b0v = bias[c0]; b1v = bias[c0 + 1]; }
            float2 v0 = make_float2(alpha * acc[mt][nt][0] + b0v,
                                    alpha * acc[mt][nt][1] + b1v);
            float2 v1 = make_float2(alpha * acc[mt][nt][2] + b0v,
                                    alpha * acc[mt][nt][3] + b1v);
            *(float2*)(C + (size_t)r0 * ldc + c0)       = v0;
            *(float2*)(C + (size_t)(r0 + 8) * ldc + c0) = v1;
        }
    }
}

// ---------------------------------------------------------------------------
// batched 32x32 tiled transpose: out[c][r] = in[r][c]
// ---------------------------------------------------------------------------
__global__ void transpose_k(const float* __restrict__ in, float* __restrict__ out,
                            long ld_in, long ld_out,
                            long siB, long siH, long soB, long soH, int Hdiv)
{
    const int zb = blockIdx.z / Hdiv, zh = blockIdx.z % Hdiv;
    in  += zb * siB + zh * siH;
    out += zb * soB + zh * soH;
    __shared__ float t[32][33];
    const int c0 = blockIdx.x * 32, r0 = blockIdx.y * 32;
#pragma unroll
    for (int j = 0; j < 4; ++j)
        t[threadIdx.y + j * 8][threadIdx.x] =
            in[(size_t)(r0 + threadIdx.y + j * 8) * ld_in + c0 + threadIdx.x];
    __syncthreads();
#pragma unroll
    for (int j = 0; j < 4; ++j)
        out[(size_t)(c0 + threadIdx.y + j * 8) * ld_out + r0 + threadIdx.x] =
            t[threadIdx.x][threadIdx.y + j * 8];
}

// ---------------------------------------------------------------------------
// Row softmax over SEQ elements, in place.
// ---------------------------------------------------------------------------
__global__ void softmax_rows(float* __restrict__ S)
{
    float* p = S + (size_t)blockIdx.x * SEQ;
    const int tid = threadIdx.x;
    float v[8];
    float mx = -1e30f;
#pragma unroll
    for (int i = 0; i < 8; ++i) { v[i] = p[tid + 256 * i]; mx = fmaxf(mx, v[i]); }
    __shared__ float red[256];
    red[tid] = mx; __syncthreads();
    for (int s = 128; s > 0; s >>= 1) { if (tid < s) red[tid] = fmaxf(red[tid], red[tid + s]); __syncthreads(); }
    mx = red[0]; __syncthreads();
    float sum = 0.f;
#pragma unroll
    for (int i = 0; i < 8; ++i) { v[i] = expf(v[i] - mx); sum += v[i]; }
    red[tid] = sum; __syncthreads();
    for (int s = 128; s > 0; s >>= 1) { if (tid < s) red[tid] += red[tid + s]; __syncthreads(); }
    const float inv = 1.f / red[0];
#pragma unroll
    for (int i = 0; i < 8; ++i) p[tid + 256 * i] = v[i] * inv;
}

// ---------------------------------------------------------------------------
// Launch
// ---------------------------------------------------------------------------
extern "C" void kernel_launch(void* const* d_in, const int* in_sizes, int n_in,
                              void* d_out, int out_size)
{
    const float* x  = (const float*)d_in[0];
    const float* Wq = (const float*)d_in[1];
    const float* bq = (const float*)d_in[2];
    const float* Wk = (const float*)d_in[3];
    const float* bk = (const float*)d_in[4];
    const float* Wv = (const float*)d_in[5];
    const float* bv = (const float*)d_in[6];
    const float* Wo = (const float*)d_in[7];
    const float* bo = (const float*)d_in[8];
    float* out = (float*)d_out;

    float *pQ, *pK, *pV, *pVT, *pS, *pAO, *pWqT, *pWkT, *pWvT, *pWoT;
    cudaGetSymbolAddress((void**)&pQ,   g_Q);
    cudaGetSymbolAddress((void**)&pK,   g_K);
    cudaGetSymbolAddress((void**)&pV,   g_V);
    cudaGetSymbolAddress((void**)&pVT,  g_VT);
    cudaGetSymbolAddress((void**)&pS,   g_S);
    cudaGetSymbolAddress((void**)&pAO,  g_AO);
    cudaGetSymbolAddress((void**)&pWqT, g_WqT);
    cudaGetSymbolAddress((void**)&pWkT, g_WkT);
    cudaGetSymbolAddress((void**)&pWvT, g_WvT);
    cudaGetSymbolAddress((void**)&pWoT, g_WoT);

    cudaFuncSetAttribute(tf32_gemm, cudaFuncAttributeMaxDynamicSharedMemorySize, SMEM_NEED);

    const float scale = 1.0f / sqrtf((float)EMBD);
    const dim3 tb(32, 8);

    // 0) transpose weights -> K-major B operands
    transpose_k<<<dim3(HE / 32, EMBD / 32, 1), tb>>>(Wq, pWqT, HE, EMBD, 0, 0, 0, 0, 1);
    transpose_k<<<dim3(HE / 32, EMBD / 32, 1), tb>>>(Wk, pWkT, HE, EMBD, 0, 0, 0, 0, 1);
    transpose_k<<<dim3(HE / 32, EMBD / 32, 1), tb>>>(Wv, pWvT, HE, EMBD, 0, 0, 0, 0, 1);
    transpose_k<<<dim3(EMBD / 32, HE / 32, 1), tb>>>(Wo, pWoT, EMBD, HE, 0, 0, 0, 0, 1);

    // 1-3) QKV projections: [8192,512] @ W^T -> [8192,4096]
    {
        dim3 g(HE / BN, MROWS / BM, 1);
        tf32_gemm<<<g, 256, SMEM_NEED>>>(x, pWqT, pQ, EMBD, EMBD, EMBD, HE,
                                         0, 0, 0, 0, 0, 0, 1, 1.f, bq);
        tf32_gemm<<<g, 256, SMEM_NEED>>>(x, pWkT, pK, EMBD, EMBD, EMBD, HE,
                                         0, 0, 0, 0, 0, 0, 1, 1.f, bk);
        tf32_gemm<<<g, 256, SMEM_NEED>>>(x, pWvT, pV, EMBD, EMBD, EMBD, HE,
                                         0, 0, 0, 0, 0, 0, 1, 1.f, bv);
    }

    // 3b) V -> per-head V^T [b,h][512,2048]
    transpose_k<<<dim3(EMBD / 32, SEQ / 32, BATCHN * HEADS), tb>>>(
        pV, pVT, HE, SEQ,
        (long)SEQ * HE, (long)EMBD,
        (long)HEADS * EMBD * SEQ, (long)EMBD * SEQ, HEADS);

    // 4) scores = scale * Q K^T : 32 x [2048,2048,512]
    {
        dim3 g(SEQ / BN, SEQ / BM, BATCHN * HEADS);
        tf32_gemm<<<g, 256, SMEM_NEED>>>(pQ, pK, pS, EMBD, HE, HE, SEQ,
                                         (long)SEQ * HE, (long)EMBD,
                                         (long)SEQ * HE, (long)EMBD,
                                         (long)HEADS * SEQ * SEQ, (long)SEQ * SEQ,
                                         HEADS, scale, nullptr);
    }

    // 5) softmax
    softmax_rows<<<BATCHN * HEADS * SEQ, 256>>>(pS);

    // 6) AO = P @ V : 32 x [2048,512,2048] (B = V^T, K-major)
    {
        dim3 g(EMBD / BN, SEQ / BM, BATCHN * HEADS);
        tf32_gemm<<<g, 256, SMEM_NEED>>>(pS, pVT, pAO, SEQ, SEQ, SEQ, HE,
                                         (long)HEADS * SEQ * SEQ, (long)SEQ * SEQ,
                                         (long)HEADS * EMBD * SEQ, (long)EMBD * SEQ,
                                         (long)SEQ * HE, (long)EMBD,
                                         HEADS, 1.f, nullptr);
    }

    // 7) out = AO @ Wo^T + bo : [8192,512,4096]
    {
        dim3 g(EMBD / BN, MROWS / BM, 1);
        tf32_gemm<<<g, 256, SMEM_NEED>>>(pAO, pWoT, out, HE, HE, HE, EMBD,
                                         0, 0, 0, 0, 0, 0, 1, 1.f, bo);
    }
}

// round 4
// speedup vs baseline: 4.9940x; 1.9402x over previous
#include <cuda_runtime.h>
#include <cuda_fp16.h>
#include <math.h>
#include <stdint.h>

#define BATCHN 4
#define SEQ    2048
#define EMBD   512
#define HEADS  8
#define HE     4096            // HEADS * EMBD
#define MROWS  8192            // BATCHN * SEQ

// ---------------------------------------------------------------------------
// Scratch (allocation-free: device globals)
// ---------------------------------------------------------------------------
__device__ __half g_Xh  [(size_t)MROWS * EMBD];
__device__ __half g_Qh  [(size_t)MROWS * HE];
__device__ __half g_Kh  [(size_t)MROWS * HE];
__device__ __half g_Vh  [(size_t)MROWS * HE];
__device__ __half g_VTh [(size_t)BATCHN * HEADS * EMBD * SEQ];  // per-head V^T [512,2048]
__device__ float  g_S   [(size_t)BATCHN * HEADS * SEQ * SEQ];   // fp32 logits
__device__ __half g_Ph  [(size_t)BATCHN * HEADS * SEQ * SEQ];   // fp16 probs
__device__ __half g_AOh [(size_t)MROWS * HE];
__device__ __half g_WqTh[(size_t)HE * EMBD];
__device__ __half g_WkTh[(size_t)HE * EMBD];
__device__ __half g_WvTh[(size_t)HE * EMBD];
__device__ __half g_WoTh[(size_t)EMBD * HE];

// ---------------------------------------------------------------------------
// helpers
// ---------------------------------------------------------------------------
__device__ __forceinline__ uint32_t smem_u32(const void* p) {
    uint32_t a;
    asm("{ .reg .u64 t; cvta.to.shared.u64 t, %1; cvt.u32.u64 %0, t; }" : "=r"(a) : "l"(p));
    return a;
}
__device__ __forceinline__ void mma_f16(float& c0, float& c1, float& c2, float& c3,
                                        uint32_t a0, uint32_t a1, uint32_t a2, uint32_t a3,
                                        uint32_t b0, uint32_t b1) {
    asm volatile("mma.sync.aligned.m16n8k16.row.col.f32.f16.f16.f32 "
                 "{%0,%1,%2,%3},{%4,%5,%6,%7},{%8,%9},{%0,%1,%2,%3};"
                 : "+f"(c0), "+f"(c1), "+f"(c2), "+f"(c3)
                 : "r"(a0), "r"(a1), "r"(a2), "r"(a3), "r"(b0), "r"(b1));
}
#define CP_ASYNC16(s, g)  asm volatile("cp.async.cg.shared.global [%0], [%1], 16;" :: "r"(s), "l"(g) : "memory")
#define CP_COMMIT()       asm volatile("cp.async.commit_group;" ::: "memory")
#define CP_WAIT2()        asm volatile("cp.async.wait_group 2;" ::: "memory")

// ---------------------------------------------------------------------------
// fp16 NT GEMM, fp32 accum: C[M,N] = alpha * A[M,K] * B[N,K]^T (+ bias)
// A,B fp16 K-major. M%128==0, N%128==0, K%32==0.
// CTA 128x128xBK32(halfs), 256 threads, warp tile 64x32 (4x4 m16n8k16), 4-stage.
// ---------------------------------------------------------------------------
#define BM 128
#define BN 128
#define BKH 32                         // halfs per stage-k (two k16 steps)
#define RSH 40                         // padded row stride in halfs (80B) — conflict-free
#define TILE_HALFS (128 * RSH)         // 5120 halfs = 10240 B
#define STAGE_HALFS (2 * TILE_HALFS)
#define NSTAGE 4
#define SMEM_NEED (NSTAGE * STAGE_HALFS * 2)   // 81920 B

template<typename Tout>
__global__ __launch_bounds__(256, 2)
void h_gemm(const __half* __restrict__ Ag, const __half* __restrict__ Bg,
            Tout* __restrict__ Cg, int K,
            long lda, long ldb, long ldc,
            long sAb, long sAh, long sBb, long sBh, long sCb, long sCh,
            int Hdiv, float alpha, const float* __restrict__ bias)
{
    extern __shared__ __half smem[];
    const uint32_t sbase = smem_u32(smem);

    const int tid  = threadIdx.x;
    const int wid  = tid >> 5;
    const int lane = tid & 31;
    const int wm   = wid >> 2;         // 0..1
    const int wn   = wid & 3;          // 0..3
    const int lg   = lane >> 2;        // 0..7
    const int lr   = lane & 3;         // 0..3

    const int zb = blockIdx.z / Hdiv;
    const int zh = blockIdx.z % Hdiv;
    const __half* A = Ag + zb * sAb + zh * sAh;
    const __half* B = Bg + zb * sBb + zh * sBh;
    Tout*         C = Cg + zb * sCb + zh * sCh;

    const int m0 = blockIdx.y * BM;
    const int n0 = blockIdx.x * BN;

    float acc[4][4][4];
#pragma unroll
    for (int i = 0; i < 4; ++i)
#pragma unroll
        for (int j = 0; j < 4; ++j)
#pragma unroll
            for (int l = 0; l < 4; ++l) acc[i][j][l] = 0.f;

    const int NT = K / BKH;

    // stage loader: A 128x32h + B 128x32h; 4 x 16B chunks per row
    auto load_stage = [&](int kt) {
        const int ring = kt & (NSTAGE - 1);
        const uint32_t base = sbase + ring * (STAGE_HALFS * 2);
        const int k0 = kt * BKH;
#pragma unroll
        for (int i = 0; i < 2; ++i) {
            int id = tid + i * 256;
            int row = id >> 2, ch = id & 3;
            CP_ASYNC16(base + row * (RSH * 2) + ch * 16,
                       A + (size_t)(m0 + row) * lda + k0 + ch * 8);
        }
#pragma unroll
        for (int i = 0; i < 2; ++i) {
            int id = tid + i * 256;
            int row = id >> 2, ch = id & 3;
            CP_ASYNC16(base + TILE_HALFS * 2 + row * (RSH * 2) + ch * 16,
                       B + (size_t)(n0 + row) * ldb + k0 + ch * 8);
        }
        CP_COMMIT();
    };

    load_stage(0); load_stage(1); load_stage(2);

    for (int kt = 0; kt < NT; ++kt) {
        const int ring = kt & (NSTAGE - 1);
        CP_WAIT2();
        __syncthreads();

        if (kt + 3 < NT) load_stage(kt + 3); else CP_COMMIT();

        const __half* sA = smem + ring * STAGE_HALFS;
        const __half* sB = sA + TILE_HALFS;

#pragma unroll
        for (int ks = 0; ks < 2; ++ks) {
            const int kb = ks * 16 + 2 * lr;
            uint32_t af[4][4], bf[4][2];
#pragma unroll
            for (int mt = 0; mt < 4; ++mt) {
                const int m = wm * 64 + mt * 16 + lg;
                af[mt][0] = *(const uint32_t*)(sA + m * RSH + kb);
                af[mt][1] = *(const uint32_t*)(sA + (m + 8) * RSH + kb);
                af[mt][2] = *(const uint32_t*)(sA + m * RSH + kb + 8);
                af[mt][3] = *(const uint32_t*)(sA + (m + 8) * RSH + kb + 8);
            }
#pragma unroll
            for (int nt = 0; nt < 4; ++nt) {
                const int n = wn * 32 + nt * 8 + lg;
                bf[nt][0] = *(const uint32_t*)(sB + n * RSH + kb);
                bf[nt][1] = *(const uint32_t*)(sB + n * RSH + kb + 8);
            }
#pragma unroll
            for (int mt = 0; mt < 4; ++mt)
#pragma unroll
                for (int nt = 0; nt < 4; ++nt)
                    mma_f16(acc[mt][nt][0], acc[mt][nt][1], acc[mt][nt][2], acc[mt][nt][3],
                            af[mt][0], af[mt][1], af[mt][2], af[mt][3],
                            bf[nt][0], bf[nt][1]);
        }
        __syncthreads();
    }

    // epilogue
#pragma unroll
    for (int mt = 0; mt < 4; ++mt) {
#pragma unroll
        for (int nt = 0; nt < 4; ++nt) {
            const int r0 = m0 + wm * 64 + mt * 16 + lg;
            const int c0 = n0 + wn * 32 + nt * 8 + 2 * lr;
            float b0v = 0.f, b1v = 0.f;
            if (bias) { b0v = bias[c0]; b1v = bias[c0 + 1]; }
            float v00 = alpha * acc[mt][nt][0] + b0v;
            float v01 = alpha * acc[mt][nt][1] + b1v;
            float v10 = alpha * acc[mt][nt][2] + b0v;
            float v11 = alpha * acc[mt][nt][3] + b1v;
            if constexpr (sizeof(Tout) == 4) {
                *(float2*)((float*)C + (size_t)r0 * ldc + c0)       = make_float2(v00, v01);
                *(float2*)((float*)C + (size_t)(r0 + 8) * ldc + c0) = make_float2(v10, v11);
            } else {
                *(__half2*)((__half*)C + (size_t)r0 * ldc + c0)       = __float22half2_rn(make_float2(v00, v01));
                *(__half2*)((__half*)C + (size_t)(r0 + 8) * ldc + c0) = __float22half2_rn(make_float2(v10, v11));
            }
        }
    }
}

// ---------------------------------------------------------------------------
// batched 32x32 tiled transpose -> half output
// ---------------------------------------------------------------------------
template<typename Tin>
__global__ void transpose_h(const Tin* __restrict__ in, __half* __restrict__ out,
                            long ld_in, long ld_out,
                            long siB, long siH, long soB, long soH, int Hdiv)
{
    const int zb = blockIdx.z / Hdiv, zh = blockIdx.z % Hdiv;
    in  += zb * siB + zh * siH;
    out += zb * soB + zh * soH;
    __shared__ float t[32][33];
    const int c0 = blockIdx.x * 32, r0 = blockIdx.y * 32;
#pragma unroll
    for (int j = 0; j < 4; ++j)
        t[threadIdx.y + j * 8][threadIdx.x] =
            (float)in[(size_t)(r0 + threadIdx.y + j * 8) * ld_in + c0 + threadIdx.x];
    __syncthreads();
#pragma unroll
    for (int j = 0; j < 4; ++j)
        out[(size_t)(c0 + threadIdx.y + j * 8) * ld_out + r0 + threadIdx.x] =
            __float2half_rn(t[threadIdx.x][threadIdx.y + j * 8]);
}

// fp32 -> fp16 elementwise
__global__ void conv_h(const float* __restrict__ in, __half* __restrict__ out, int n)
{
    int i = blockIdx.x * blockDim.x + threadIdx.x;
    if (i < n) out[i] = __float2half_rn(in[i]);
}

// ---------------------------------------------------------------------------
// Row softmax: fp32 logits in, fp16 probs out. 256 thr, 2048 cols.
// ---------------------------------------------------------------------------
__global__ void softmax_rows(const float* __restrict__ S, __half* __restrict__ P)
{
    const float* p = S + (size_t)blockIdx.x * SEQ;
    __half* q = P + (size_t)blockIdx.x * SEQ;
    const int tid = threadIdx.x;

    float2 v[4];
    float mx = -1e30f;
#pragma unroll
    for (int i = 0; i < 4; ++i) {
        v[i] = *(const float2*)(p + 2 * tid + 512 * i);
        mx = fmaxf(mx, fmaxf(v[i].x, v[i].y));
    }
    __shared__ float red[256];
    red[tid] = mx; __syncthreads();
    for (int s = 128; s > 0; s >>= 1) { if (tid < s) red[tid] = fmaxf(red[tid], red[tid + s]); __syncthreads(); }
    mx = red[0]; __syncthreads();
    float sum = 0.f;
#pragma unroll
    for (int i = 0; i < 4; ++i) {
        v[i].x = expf(v[i].x - mx); v[i].y = expf(v[i].y - mx);
        sum += v[i].x + v[i].y;
    }
    red[tid] = sum; __syncthreads();
    for (int s = 128; s > 0; s >>= 1) { if (tid < s) red[tid] += red[tid + s]; __syncthreads(); }
    const float inv = 1.f / red[0];
#pragma unroll
    for (int i = 0; i < 4; ++i)
        *(__half2*)(q + 2 * tid + 512 * i) =
            __float22half2_rn(make_float2(v[i].x * inv, v[i].y * inv));
}

// ---------------------------------------------------------------------------
// Launch
// ---------------------------------------------------------------------------
extern "C" void kernel_launch(void* const* d_in, const int* in_sizes, int n_in,
                              void* d_out, int out_size)
{
    const float* x  = (const float*)d_in[0];
    const float* Wq = (const float*)d_in[1];
    const float* bq = (const float*)d_in[2];
    const float* Wk = (const float*)d_in[3];
    const float* bk = (const float*)d_in[4];
    const float* Wv = (const float*)d_in[5];
    const float* bv = (const float*)d_in[6];
    const float* Wo = (const float*)d_in[7];
    const float* bo = (const float*)d_in[8];
    float* out = (float*)d_out;

    __half *pXh, *pQh, *pKh, *pVh, *pVTh, *pPh, *pAOh, *pWqTh, *pWkTh, *pWvTh, *pWoTh;
    float *pS;
    cudaGetSymbolAddress((void**)&pXh,   g_Xh);
    cudaGetSymbolAddress((void**)&pQh,   g_Qh);
    cudaGetSymbolAddress((void**)&pKh,   g_Kh);
    cudaGetSymbolAddress((void**)&pVh,   g_Vh);
    cudaGetSymbolAddress((void**)&pVTh,  g_VTh);
    cudaGetSymbolAddress((void**)&pS,    g_S);
    cudaGetSymbolAddress((void**)&pPh,   g_Ph);
    cudaGetSymbolAddress((void**)&pAOh,  g_AOh);
    cudaGetSymbolAddress((void**)&pWqTh, g_WqTh);
    cudaGetSymbolAddress((void**)&pWkTh, g_WkTh);
    cudaGetSymbolAddress((void**)&pWvTh, g_WvTh);
    cudaGetSymbolAddress((void**)&pWoTh, g_WoTh);

    cudaFuncSetAttribute(h_gemm<float>,  cudaFuncAttributeMaxDynamicSharedMemorySize, SMEM_NEED);
    cudaFuncSetAttribute(h_gemm<__half>, cudaFuncAttributeMaxDynamicSharedMemorySize, SMEM_NEED);

    const float scale = 1.0f / sqrtf((float)EMBD);
    const dim3 tb(32, 8);

    // 0) convert x, transpose weights -> fp16 K-major operands
    conv_h<<<(MROWS * EMBD + 255) / 256, 256>>>(x, pXh, MROWS * EMBD);
    transpose_h<float><<<dim3(HE / 32, EMBD / 32, 1), tb>>>(Wq, pWqTh, HE, EMBD, 0, 0, 0, 0, 1);
    transpose_h<float><<<dim3(HE / 32, EMBD / 32, 1), tb>>>(Wk, pWkTh, HE, EMBD, 0, 0, 0, 0, 1);
    transpose_h<float><<<dim3(HE / 32, EMBD / 32, 1), tb>>>(Wv, pWvTh, HE, EMBD, 0, 0, 0, 0, 1);
    transpose_h<float><<<dim3(EMBD / 32, HE / 32, 1), tb>>>(Wo, pWoTh, EMBD, HE, 0, 0, 0, 0, 1);

    // 1-3) QKV projections -> fp16
    {
        dim3 g(HE / BN, MROWS / BM, 1);
        h_gemm<__half><<<g, 256, SMEM_NEED>>>(pXh, pWqTh, pQh, EMBD, EMBD, EMBD, HE,
                                              0, 0, 0, 0, 0, 0, 1, 1.f, bq);
        h_gemm<__half><<<g, 256, SMEM_NEED>>>(pXh, pWkTh, pKh, EMBD, EMBD, EMBD, HE,
                                              0, 0, 0, 0, 0, 0, 1, 1.f, bk);
        h_gemm<__half><<<g, 256, SMEM_NEED>>>(pXh, pWvTh, pVh, EMBD, EMBD, EMBD, HE,
                                              0, 0, 0, 0, 0, 0, 1, 1.f, bv);
    }

    // 3b) V -> per-head V^T [b,h][512,2048] fp16
    transpose_h<__half><<<dim3(EMBD / 32, SEQ / 32, BATCHN * HEADS), tb>>>(
        pVh, pVTh, HE, SEQ,
        (long)SEQ * HE, (long)EMBD,
        (long)HEADS * EMBD * SEQ, (long)EMBD * SEQ, HEADS);

    // 4) scores = scale * Q K^T -> fp32 : 32 x [2048,2048,512]
    {
        dim3 g(SEQ / BN, SEQ / BM, BATCHN * HEADS);
        h_gemm<float><<<g, 256, SMEM_NEED>>>(pQh, pKh, pS, EMBD, HE, HE, SEQ,
                                             (long)SEQ * HE, (long)EMBD,
                                             (long)SEQ * HE, (long)EMBD,
                                             (long)HEADS * SEQ * SEQ, (long)SEQ * SEQ,
                                             HEADS, scale, nullptr);
    }

    // 5) softmax -> fp16 probs
    softmax_rows<<<BATCHN * HEADS * SEQ, 256>>>(pS, pPh);

    // 6) AO = P @ V -> fp16 : 32 x [2048,512,2048]
    {
        dim3 g(EMBD / BN, SEQ / BM, BATCHN * HEADS);
        h_gemm<__half><<<g, 256, SMEM_NEED>>>(pPh, pVTh, pAOh, SEQ, SEQ, SEQ, HE,
                                              (long)HEADS * SEQ * SEQ, (long)SEQ * SEQ,
                                              (long)HEADS * EMBD * SEQ, (long)EMBD * SEQ,
                                              (long)SEQ * HE, (long)EMBD,
                                              HEADS, 1.f, nullptr);
    }

    // 7) out = AO @ Wo^T + bo -> fp32 : [8192,512,4096]
    {
        dim3 g(EMBD / BN, MROWS / BM, 1);
        h_gemm<float><<<g, 256, SMEM_NEED>>>(pAOh, pWoTh, out, HE, HE, HE, EMBD,
                                             0, 0, 0, 0, 0, 0, 1, 1.f, bo);
    }
}

// round 5
// speedup vs baseline: 5.5968x; 1.1207x over previous
#include <cuda_runtime.h>
#include <cuda_fp16.h>
#include <math.h>
#include <stdint.h>

#define BATCHN 4
#define SEQ    2048
#define EMBD   512
#define HEADS  8
#define HE     4096            // HEADS * EMBD
#define MROWS  8192            // BATCHN * SEQ

// ---------------------------------------------------------------------------
// Scratch (allocation-free: device globals)
// ---------------------------------------------------------------------------
__device__ __half g_Xh  [(size_t)MROWS * EMBD];
__device__ __half g_Qh  [(size_t)MROWS * HE];
__device__ __half g_Kh  [(size_t)MROWS * HE];
__device__ __half g_Vh  [(size_t)MROWS * HE];
__device__ __half g_VTh [(size_t)BATCHN * HEADS * EMBD * SEQ];  // per-head V^T [512,2048]
__device__ float  g_S   [(size_t)BATCHN * HEADS * SEQ * SEQ];   // fp32 logits
__device__ __half g_Ph  [(size_t)BATCHN * HEADS * SEQ * SEQ];   // fp16 probs
__device__ __half g_AOh [(size_t)MROWS * HE];
__device__ __half g_WqTh[(size_t)HE * EMBD];
__device__ __half g_WkTh[(size_t)HE * EMBD];
__device__ __half g_WvTh[(size_t)HE * EMBD];
__device__ __half g_WoTh[(size_t)EMBD * HE];

// ---------------------------------------------------------------------------
// helpers
// ---------------------------------------------------------------------------
__device__ __forceinline__ uint32_t smem_u32(const void* p) {
    uint32_t a;
    asm("{ .reg .u64 t; cvta.to.shared.u64 t, %1; cvt.u32.u64 %0, t; }" : "=r"(a) : "l"(p));
    return a;
}
__device__ __forceinline__ void mma_f16(float& c0, float& c1, float& c2, float& c3,
                                        uint32_t a0, uint32_t a1, uint32_t a2, uint32_t a3,
                                        uint32_t b0, uint32_t b1) {
    asm volatile("mma.sync.aligned.m16n8k16.row.col.f32.f16.f16.f32 "
                 "{%0,%1,%2,%3},{%4,%5,%6,%7},{%8,%9},{%0,%1,%2,%3};"
                 : "+f"(c0), "+f"(c1), "+f"(c2), "+f"(c3)
                 : "r"(a0), "r"(a1), "r"(a2), "r"(a3), "r"(b0), "r"(b1));
}
__device__ __forceinline__ void ldm_x4(uint32_t& r0, uint32_t& r1, uint32_t& r2,
                                       uint32_t& r3, uint32_t addr) {
    asm volatile("ldmatrix.sync.aligned.m8n8.x4.shared.b16 {%0,%1,%2,%3}, [%4];"
                 : "=r"(r0), "=r"(r1), "=r"(r2), "=r"(r3) : "r"(addr));
}
#define CP_ASYNC16(s, g)  asm volatile("cp.async.cg.shared.global [%0], [%1], 16;" :: "r"(s), "l"(g) : "memory")
#define CP_COMMIT()       asm volatile("cp.async.commit_group;" ::: "memory")
#define CP_WAIT2()        asm volatile("cp.async.wait_group 2;" ::: "memory")

// ---------------------------------------------------------------------------
// fp16 NT GEMM, fp32 accum: C[M,N] = alpha * A[M,K] * B[N,K]^T (+ bias)
// A,B fp16 K-major. M%128==0, N%128==0, K%32==0.
// CTA 128x128xBK32(halfs), 256 threads, warp tile 64x32 (4x4 m16n8k16),
// 4-stage cp.async, ldmatrix fragment loads, one sync per iteration.
// ---------------------------------------------------------------------------
#define BM 128
#define BN 128
#define BKH 32                         // halfs per stage-k (two k16 steps)
#define RSH 40                         // padded row stride in halfs (80B) — conflict-free
#define TILE_HALFS (128 * RSH)         // 5120 halfs = 10240 B
#define STAGE_HALFS (2 * TILE_HALFS)
#define STAGE_BYTES (STAGE_HALFS * 2)
#define NSTAGE 4
#define SMEM_NEED (NSTAGE * STAGE_BYTES)       // 81920 B

template<typename Tout>
__global__ __launch_bounds__(256, 2)
void h_gemm(const __half* __restrict__ Ag, const __half* __restrict__ Bg,
            Tout* __restrict__ Cg, int K,
            long lda, long ldb, long ldc,
            long sAb, long sAh, long sBb, long sBh, long sCb, long sCh,
            int Hdiv, float alpha, const float* __restrict__ bias)
{
    extern __shared__ __half smem[];
    const uint32_t sbase = smem_u32(smem);

    const int tid  = threadIdx.x;
    const int wid  = tid >> 5;
    const int lane = tid & 31;
    const int wm   = wid >> 2;         // 0..1
    const int wn   = wid & 3;          // 0..3
    const int lg   = lane >> 2;        // 0..7
    const int lr   = lane & 3;         // 0..3

    const int zb = blockIdx.z / Hdiv;
    const int zh = blockIdx.z % Hdiv;
    const __half* A = Ag + zb * sAb + zh * sAh;
    const __half* B = Bg + zb * sBb + zh * sBh;
    Tout*         C = Cg + zb * sCb + zh * sCh;

    const int m0 = blockIdx.y * BM;
    const int n0 = blockIdx.x * BN;

    // per-lane ldmatrix base byte-offsets (within a stage)
    const int arow = lane & 15;
    const int acol = (lane >> 4) << 3;                 // 0 or 8 halfs
    const uint32_t aoff = ((wm * 64 + arow) * RSH + acol) * 2;
    const int brow = (lane & 7) | ((lane >> 4) << 3);  // 0..15
    const int bcol = ((lane >> 3) & 1) << 3;           // 0 or 8 halfs
    const uint32_t boff = TILE_HALFS * 2 + ((wn * 32 + brow) * RSH + bcol) * 2;

    float acc[4][4][4];
#pragma unroll
    for (int i = 0; i < 4; ++i)
#pragma unroll
        for (int j = 0; j < 4; ++j)
#pragma unroll
            for (int l = 0; l < 4; ++l) acc[i][j][l] = 0.f;

    const int NT = K / BKH;

    // stage loader: A 128x32h + B 128x32h; 4 x 16B chunks per row
    auto load_stage = [&](int kt) {
        const int ring = kt & (NSTAGE - 1);
        const uint32_t base = sbase + ring * STAGE_BYTES;
        const int k0 = kt * BKH;
#pragma unroll
        for (int i = 0; i < 2; ++i) {
            int id = tid + i * 256;
            int row = id >> 2, ch = id & 3;
            CP_ASYNC16(base + row * (RSH * 2) + ch * 16,
                       A + (size_t)(m0 + row) * lda + k0 + ch * 8);
        }
#pragma unroll
        for (int i = 0; i < 2; ++i) {
            int id = tid + i * 256;
            int row = id >> 2, ch = id & 3;
            CP_ASYNC16(base + TILE_HALFS * 2 + row * (RSH * 2) + ch * 16,
                       B + (size_t)(n0 + row) * ldb + k0 + ch * 8);
        }
        CP_COMMIT();
    };

    load_stage(0); load_stage(1); load_stage(2);

    for (int kt = 0; kt < NT; ++kt) {
        const int ring = kt & (NSTAGE - 1);
        CP_WAIT2();
        __syncthreads();

        // prefetch stage kt+3 into ring (kt-1)&3 — safe: all warps passed the
        // sync above, so everyone finished reading that ring in iteration kt-1.
        if (kt + 3 < NT) load_stage(kt + 3); else CP_COMMIT();

        const uint32_t stg = sbase + ring * STAGE_BYTES;

#pragma unroll
        for (int ks = 0; ks < 2; ++ks) {
            const uint32_t kb = ks * 32;   // 16 halfs
            uint32_t af[4][4], bf[4][2];
#pragma unroll
            for (int mt = 0; mt < 4; ++mt)
                ldm_x4(af[mt][0], af[mt][1], af[mt][2], af[mt][3],
                       stg + aoff + mt * (16 * RSH * 2) + kb);
#pragma unroll
            for (int np = 0; np < 2; ++np)
                ldm_x4(bf[2 * np][0], bf[2 * np][1], bf[2 * np + 1][0], bf[2 * np + 1][1],
                       stg + boff + np * (16 * RSH * 2) + kb);
#pragma unroll
            for (int mt = 0; mt < 4; ++mt)
#pragma unroll
                for (int nt = 0; nt < 4; ++nt)
                    mma_f16(acc[mt][nt][0], acc[mt][nt][1], acc[mt][nt][2], acc[mt][nt][3],
                            af[mt][0], af[mt][1], af[mt][2], af[mt][3],
                            bf[nt][0], bf[nt][1]);
        }
    }

    // epilogue
#pragma unroll
    for (int mt = 0; mt < 4; ++mt) {
#pragma unroll
        for (int nt = 0; nt < 4; ++nt) {
            const int r0 = m0 + wm * 64 + mt * 16 + lg;
            const int c0 = n0 + wn * 32 + nt * 8 + 2 * lr;
            float b0v = 0.f, b1v = 0.f;
            if (bias) { b0v = bias[c0]; b1v = bias[c0 + 1]; }
            float v00 = alpha * acc[mt][nt][0] + b0v;
            float v01 = alpha * acc[mt][nt][1] + b1v;
            float v10 = alpha * acc[mt][nt][2] + b0v;
            float v11 = alpha * acc[mt][nt][3] + b1v;
            if constexpr (sizeof(Tout) == 4) {
                *(float2*)((float*)C + (size_t)r0 * ldc + c0)       = make_float2(v00, v01);
                *(float2*)((float*)C + (size_t)(r0 + 8) * ldc + c0) = make_float2(v10, v11);
            } else {
                *(__half2*)((__half*)C + (size_t)r0 * ldc + c0)       = __float22half2_rn(make_float2(v00, v01));
                *(__half2*)((__half*)C + (size_t)(r0 + 8) * ldc + c0) = __float22half2_rn(make_float2(v10, v11));
            }
        }
    }
}

// ---------------------------------------------------------------------------
// batched 32x32 tiled transpose -> half output
// ---------------------------------------------------------------------------
template<typename Tin>
__global__ void transpose_h(const Tin* __restrict__ in, __half* __restrict__ out,
                            long ld_in, long ld_out,
                            long siB, long siH, long soB, long soH, int Hdiv)
{
    const int zb = blockIdx.z / Hdiv, zh = blockIdx.z % Hdiv;
    in  += zb * siB + zh * siH;
    out += zb * soB + zh * soH;
    __shared__ float t[32][33];
    const int c0 = blockIdx.x * 32, r0 = blockIdx.y * 32;
#pragma unroll
    for (int j = 0; j < 4; ++j)
        t[threadIdx.y + j * 8][threadIdx.x] =
            (float)in[(size_t)(r0 + threadIdx.y + j * 8) * ld_in + c0 + threadIdx.x];
    __syncthreads();
#pragma unroll
    for (int j = 0; j < 4; ++j)
        out[(size_t)(c0 + threadIdx.y + j * 8) * ld_out + r0 + threadIdx.x] =
            __float2half_rn(t[threadIdx.x][threadIdx.y + j * 8]);
}

// fp32 -> fp16 elementwise
__global__ void conv_h(const float* __restrict__ in, __half* __restrict__ out, int n)
{
    int i = blockIdx.x * blockDim.x + threadIdx.x;
    if (i < n) out[i] = __float2half_rn(in[i]);
}

// ---------------------------------------------------------------------------
// Row softmax: fp32 logits in, fp16 probs out. 256 thr, 2048 cols.
// ---------------------------------------------------------------------------
__global__ void softmax_rows(const float* __restrict__ S, __half* __restrict__ P)
{
    const float* p = S + (size_t)blockIdx.x * SEQ;
    __half* q = P + (size_t)blockIdx.x * SEQ;
    const int tid = threadIdx.x;

    float2 v[4];
    float mx = -1e30f;
#pragma unroll
    for (int i = 0; i < 4; ++i) {
        v[i] = *(const float2*)(p + 2 * tid + 512 * i);
        mx = fmaxf(mx, fmaxf(v[i].x, v[i].y));
    }
    __shared__ float red[256];
    red[tid] = mx; __syncthreads();
    for (int s = 128; s > 0; s >>= 1) { if (tid < s) red[tid] = fmaxf(red[tid], red[tid + s]); __syncthreads(); }
    mx = red[0]; __syncthreads();
    float sum = 0.f;
#pragma unroll
    for (int i = 0; i < 4; ++i) {
        v[i].x = expf(v[i].x - mx); v[i].y = expf(v[i].y - mx);
        sum += v[i].x + v[i].y;
    }
    red[tid] = sum; __syncthreads();
    for (int s = 128; s > 0; s >>= 1) { if (tid < s) red[tid] += red[tid + s]; __syncthreads(); }
    const float inv = 1.f / red[0];
#pragma unroll
    for (int i = 0; i < 4; ++i)
        *(__half2*)(q + 2 * tid + 512 * i) =
            __float22half2_rn(make_float2(v[i].x * inv, v[i].y * inv));
}

// ---------------------------------------------------------------------------
// Launch
// ---------------------------------------------------------------------------
extern "C" void kernel_launch(void* const* d_in, const int* in_sizes, int n_in,
                              void* d_out, int out_size)
{
    const float* x  = (const float*)d_in[0];
    const float* Wq = (const float*)d_in[1];
    const float* bq = (const float*)d_in[2];
    const float* Wk = (const float*)d_in[3];
    const float* bk = (const float*)d_in[4];
    const float* Wv = (const float*)d_in[5];
    const float* bv = (const float*)d_in[6];
    const float* Wo = (const float*)d_in[7];
    const float* bo = (const float*)d_in[8];
    float* out = (float*)d_out;

    __half *pXh, *pQh, *pKh, *pVh, *pVTh, *pPh, *pAOh, *pWqTh, *pWkTh, *pWvTh, *pWoTh;
    float *pS;
    cudaGetSymbolAddress((void**)&pXh,   g_Xh);
    cudaGetSymbolAddress((void**)&pQh,   g_Qh);
    cudaGetSymbolAddress((void**)&pKh,   g_Kh);
    cudaGetSymbolAddress((void**)&pVh,   g_Vh);
    cudaGetSymbolAddress((void**)&pVTh,  g_VTh);
    cudaGetSymbolAddress((void**)&pS,    g_S);
    cudaGetSymbolAddress((void**)&pPh,   g_Ph);
    cudaGetSymbolAddress((void**)&pAOh,  g_AOh);
    cudaGetSymbolAddress((void**)&pWqTh, g_WqTh);
    cudaGetSymbolAddress((void**)&pWkTh, g_WkTh);
    cudaGetSymbolAddress((void**)&pWvTh, g_WvTh);
    cudaGetSymbolAddress((void**)&pWoTh, g_WoTh);

    cudaFuncSetAttribute(h_gemm<float>,  cudaFuncAttributeMaxDynamicSharedMemorySize, SMEM_NEED);
    cudaFuncSetAttribute(h_gemm<__half>, cudaFuncAttributeMaxDynamicSharedMemorySize, SMEM_NEED);

    const float scale = 1.0f / sqrtf((float)EMBD);
    const dim3 tb(32, 8);

    // 0) convert x, transpose weights -> fp16 K-major operands
    conv_h<<<(MROWS * EMBD + 255) / 256, 256>>>(x, pXh, MROWS * EMBD);
    transpose_h<float><<<dim3(HE / 32, EMBD / 32, 1), tb>>>(Wq, pWqTh, HE, EMBD, 0, 0, 0, 0, 1);
    transpose_h<float><<<dim3(HE / 32, EMBD / 32, 1), tb>>>(Wk, pWkTh, HE, EMBD, 0, 0, 0, 0, 1);
    transpose_h<float><<<dim3(HE / 32, EMBD / 32, 1), tb>>>(Wv, pWvTh, HE, EMBD, 0, 0, 0, 0, 1);
    transpose_h<float><<<dim3(EMBD / 32, HE / 32, 1), tb>>>(Wo, pWoTh, EMBD, HE, 0, 0, 0, 0, 1);

    // 1-3) QKV projections -> fp16
    {
        dim3 g(HE / BN, MROWS / BM, 1);
        h_gemm<__half><<<g, 256, SMEM_NEED>>>(pXh, pWqTh, pQh, EMBD, EMBD, EMBD, HE,
                                              0, 0, 0, 0, 0, 0, 1, 1.f, bq);
        h_gemm<__half><<<g, 256, SMEM_NEED>>>(pXh, pWkTh, pKh, EMBD, EMBD, EMBD, HE,
                                              0, 0, 0, 0, 0, 0, 1, 1.f, bk);
        h_gemm<__half><<<g, 256, SMEM_NEED>>>(pXh, pWvTh, pVh, EMBD, EMBD, EMBD, HE,
                                              0, 0, 0, 0, 0, 0, 1, 1.f, bv);
    }

    // 3b) V -> per-head V^T [b,h][512,2048] fp16
    transpose_h<__half><<<dim3(EMBD / 32, SEQ / 32, BATCHN * HEADS), tb>>>(
        pVh, pVTh, HE, SEQ,
        (long)SEQ * HE, (long)EMBD,
        (long)HEADS * EMBD * SEQ, (long)EMBD * SEQ, HEADS);

    // 4) scores = scale * Q K^T -> fp32 : 32 x [2048,2048,512]
    {
        dim3 g(SEQ / BN, SEQ / BM, BATCHN * HEADS);
        h_gemm<float><<<g, 256, SMEM_NEED>>>(pQh, pKh, pS, EMBD, HE, HE, SEQ,
                                             (long)SEQ * HE, (long)EMBD,
                                             (long)SEQ * HE, (long)EMBD,
                                             (long)HEADS * SEQ * SEQ, (long)SEQ * SEQ,
                                             HEADS, scale, nullptr);
    }

    // 5) softmax -> fp16 probs
    softmax_rows<<<BATCHN * HEADS * SEQ, 256>>>(pS, pPh);

    // 6) AO = P @ V -> fp16 : 32 x [2048,512,2048]
    {
        dim3 g(EMBD / BN, SEQ / BM, BATCHN * HEADS);
        h_gemm<__half><<<g, 256, SMEM_NEED>>>(pPh, pVTh, pAOh, SEQ, SEQ, SEQ, HE,
                                              (long)HEADS * SEQ * SEQ, (long)SEQ * SEQ,
                                              (long)HEADS * EMBD * SEQ, (long)EMBD * SEQ,
                                              (long)SEQ * HE, (long)EMBD,
                                              HEADS, 1.f, nullptr);
    }

    // 7) out = AO @ Wo^T + bo -> fp32 : [8192,512,4096]
    {
        dim3 g(EMBD / BN, MROWS / BM, 1);
        h_gemm<float><<<g, 256, SMEM_NEED>>>(pAOh, pWoTh, out, HE, HE, HE, EMBD,
                                             0, 0, 0, 0, 0, 0, 1, 1.f, bo);
    }
}

// round 6
// speedup vs baseline: 6.0555x; 1.0820x over previous
#include <cuda_runtime.h>
#include <cuda_fp16.h>
#include <math.h>
#include <stdint.h>

#define BATCHN 4
#define SEQ    2048
#define EMBD   512
#define HEADS  8
#define HE     4096            // HEADS * EMBD
#define MROWS  8192            // BATCHN * SEQ

// ---------------------------------------------------------------------------
// Scratch (allocation-free: device globals)
// ---------------------------------------------------------------------------
__device__ __half g_Xh [(size_t)MROWS * EMBD];
__device__ __half g_Qh [(size_t)MROWS * HE];
__device__ __half g_Kh [(size_t)MROWS * HE];
__device__ __half g_Vh [(size_t)MROWS * HE];
__device__ __half g_Ph [(size_t)BATCHN * HEADS * SEQ * SEQ];   // fp16 logits -> probs
__device__ __half g_AOh[(size_t)MROWS * HE];
__device__ __half g_Wqh[(size_t)EMBD * HE];
__device__ __half g_Wkh[(size_t)EMBD * HE];
__device__ __half g_Wvh[(size_t)EMBD * HE];
__device__ __half g_Woh[(size_t)HE * EMBD];

// ---------------------------------------------------------------------------
// helpers
// ---------------------------------------------------------------------------
__device__ __forceinline__ uint32_t smem_u32(const void* p) {
    uint32_t a;
    asm("{ .reg .u64 t; cvta.to.shared.u64 t, %1; cvt.u32.u64 %0, t; }" : "=r"(a) : "l"(p));
    return a;
}
__device__ __forceinline__ void mma_f16(float& c0, float& c1, float& c2, float& c3,
                                        uint32_t a0, uint32_t a1, uint32_t a2, uint32_t a3,
                                        uint32_t b0, uint32_t b1) {
    asm volatile("mma.sync.aligned.m16n8k16.row.col.f32.f16.f16.f32 "
                 "{%0,%1,%2,%3},{%4,%5,%6,%7},{%8,%9},{%0,%1,%2,%3};"
                 : "+f"(c0), "+f"(c1), "+f"(c2), "+f"(c3)
                 : "r"(a0), "r"(a1), "r"(a2), "r"(a3), "r"(b0), "r"(b1));
}
__device__ __forceinline__ void ldm_x4(uint32_t& r0, uint32_t& r1, uint32_t& r2,
                                       uint32_t& r3, uint32_t addr) {
    asm volatile("ldmatrix.sync.aligned.m8n8.x4.shared.b16 {%0,%1,%2,%3}, [%4];"
                 : "=r"(r0), "=r"(r1), "=r"(r2), "=r"(r3) : "r"(addr));
}
__device__ __forceinline__ void ldm_x4_t(uint32_t& r0, uint32_t& r1, uint32_t& r2,
                                         uint32_t& r3, uint32_t addr) {
    asm volatile("ldmatrix.sync.aligned.m8n8.x4.trans.shared.b16 {%0,%1,%2,%3}, [%4];"
                 : "=r"(r0), "=r"(r1), "=r"(r2), "=r"(r3) : "r"(addr));
}
#define CP_ASYNC16(s, g)  asm volatile("cp.async.cg.shared.global [%0], [%1], 16;" :: "r"(s), "l"(g) : "memory")
#define CP_COMMIT()       asm volatile("cp.async.commit_group;" ::: "memory")
#define CP_WAIT2()        asm volatile("cp.async.wait_group 2;" ::: "memory")

// ---------------------------------------------------------------------------
// fp16 GEMM, fp32 accum: C[M,N] = alpha * A[M,K] * op(B) (+ bias)
//   TRB=true : B is [N,K] (K-major)  -> C = A B^T   (non-trans ldmatrix)
//   TRB=false: B is [K,N] (N-major)  -> C = A B     (trans ldmatrix)
// CTA 128x128xBK32(halfs), 256 threads, warp tile 64x32 (4x4 m16n8k16),
// 4-stage cp.async, one sync per iteration.
// ---------------------------------------------------------------------------
#define BM 128
#define BN 128
#define BKH 32
#define RSH 40                          // A / NT-B padded row stride (halfs)
#define RBH 136                         // NN-B padded row stride (halfs)
#define ATILE_BYTES (128 * RSH * 2)     // 10240
#define SMEM_MAX (4 * (ATILE_BYTES + 128 * RSH * 2))   // 81920 (largest variant)

template<typename Tout, bool TRB>
__global__ __launch_bounds__(256, 2)
void h_gemm(const __half* __restrict__ Ag, const __half* __restrict__ Bg,
            Tout* __restrict__ Cg, int K,
            long lda, long ldb, long ldc,
            long sAb, long sAh, long sBb, long sBh, long sCb, long sCh,
            int Hdiv, float alpha, const float* __restrict__ bias)
{
    constexpr uint32_t BTILE_BYTES = TRB ? (128 * RSH * 2) : (32 * RBH * 2);
    constexpr uint32_t STAGE_BYTES = ATILE_BYTES + BTILE_BYTES;

    extern __shared__ __half smem[];
    const uint32_t sbase = smem_u32(smem);

    const int tid  = threadIdx.x;
    const int wid  = tid >> 5;
    const int lane = tid & 31;
    const int wm   = wid >> 2;         // 0..1
    const int wn   = wid & 3;          // 0..3
    const int lg   = lane >> 2;        // 0..7
    const int lr   = lane & 3;         // 0..3

    const int zb = blockIdx.z / Hdiv;
    const int zh = blockIdx.z % Hdiv;
    const __half* A = Ag + zb * sAb + zh * sAh;
    const __half* B = Bg + zb * sBb + zh * sBh;
    Tout*         C = Cg + zb * sCb + zh * sCh;

    const int m0 = blockIdx.y * BM;
    const int n0 = blockIdx.x * BN;

    // A ldmatrix base (per-lane byte offset within a stage)
    const int arow = lane & 15;
    const int acol = (lane >> 4) << 3;
    const uint32_t aoff = ((wm * 64 + arow) * RSH + acol) * 2;

    // B ldmatrix base
    uint32_t boff;
    if constexpr (TRB) {
        const int brow = (lane & 7) | ((lane >> 4) << 3);
        const int bcol = ((lane >> 3) & 1) << 3;
        boff = ATILE_BYTES + ((wn * 32 + brow) * RSH + bcol) * 2;
    } else {
        // lane l -> matrix m = l>>3 (m&1 = k-half, m>>1 = n-block), row r = l&7
        const int krow = (lane & 7) + 8 * ((lane >> 3) & 1);
        const int ncol = wn * 32 + 8 * (lane >> 4);
        boff = ATILE_BYTES + krow * (RBH * 2) + ncol * 2;
    }

    float acc[4][4][4];
#pragma unroll
    for (int i = 0; i < 4; ++i)
#pragma unroll
        for (int j = 0; j < 4; ++j)
#pragma unroll
            for (int l = 0; l < 4; ++l) acc[i][j][l] = 0.f;

    const int NT = K / BKH;

    auto load_stage = [&](int kt) {
        const int ring = kt & 3;
        const uint32_t base = sbase + ring * STAGE_BYTES;
        const int k0 = kt * BKH;
        // A: 128 rows x 32 halfs, 4 x 16B chunks per row
#pragma unroll
        for (int i = 0; i < 2; ++i) {
            int id = tid + i * 256;
            int row = id >> 2, ch = id & 3;
            CP_ASYNC16(base + row * (RSH * 2) + ch * 16,
                       A + (size_t)(m0 + row) * lda + k0 + ch * 8);
        }
        if constexpr (TRB) {
            // B: 128 n-rows x 32 halfs
#pragma unroll
            for (int i = 0; i < 2; ++i) {
                int id = tid + i * 256;
                int row = id >> 2, ch = id & 3;
                CP_ASYNC16(base + ATILE_BYTES + row * (RSH * 2) + ch * 16,
                           B + (size_t)(n0 + row) * ldb + k0 + ch * 8);
            }
        } else {
            // B: 32 k-rows x 128 halfs, 16 x 16B chunks per row
#pragma unroll
            for (int i = 0; i < 2; ++i) {
                int id = tid + i * 256;
                int row = id >> 4, ch = id & 15;
                CP_ASYNC16(base + ATILE_BYTES + row * (RBH * 2) + ch * 16,
                           B + (size_t)(k0 + row) * ldb + n0 + ch * 8);
            }
        }
        CP_COMMIT();
    };

    load_stage(0); load_stage(1); load_stage(2);

    for (int kt = 0; kt < NT; ++kt) {
        const int ring = kt & 3;
        CP_WAIT2();
        __syncthreads();

        if (kt + 3 < NT) load_stage(kt + 3); else CP_COMMIT();

        const uint32_t stg = sbase + ring * STAGE_BYTES;

#pragma unroll
        for (int ks = 0; ks < 2; ++ks) {
            uint32_t af[4][4], bf[4][2];
#pragma unroll
            for (int mt = 0; mt < 4; ++mt)
                ldm_x4(af[mt][0], af[mt][1], af[mt][2], af[mt][3],
                       stg + aoff + mt * (16 * RSH * 2) + ks * 32);
            if constexpr (TRB) {
#pragma unroll
                for (int np = 0; np < 2; ++np)
                    ldm_x4(bf[2 * np][0], bf[2 * np][1], bf[2 * np + 1][0], bf[2 * np + 1][1],
                           stg + boff + np * (16 * RSH * 2) + ks * 32);
            } else {
#pragma unroll
                for (int np = 0; np < 2; ++np)
                    ldm_x4_t(bf[2 * np][0], bf[2 * np][1], bf[2 * np + 1][0], bf[2 * np + 1][1],
                             stg + boff + ks * (16 * RBH * 2) + np * 32);
            }
#pragma unroll
            for (int mt = 0; mt < 4; ++mt)
#pragma unroll
                for (int nt = 0; nt < 4; ++nt)
                    mma_f16(acc[mt][nt][0], acc[mt][nt][1], acc[mt][nt][2], acc[mt][nt][3],
                            af[mt][0], af[mt][1], af[mt][2], af[mt][3],
                            bf[nt][0], bf[nt][1]);
        }
    }

    // epilogue
#pragma unroll
    for (int mt = 0; mt < 4; ++mt) {
#pragma unroll
        for (int nt = 0; nt < 4; ++nt) {
            const int r0 = m0 + wm * 64 + mt * 16 + lg;
            const int c0 = n0 + wn * 32 + nt * 8 + 2 * lr;
            float b0v = 0.f, b1v = 0.f;
            if (bias) { b0v = bias[c0]; b1v = bias[c0 + 1]; }
            float v00 = alpha * acc[mt][nt][0] + b0v;
            float v01 = alpha * acc[mt][nt][1] + b1v;
            float v10 = alpha * acc[mt][nt][2] + b0v;
            float v11 = alpha * acc[mt][nt][3] + b1v;
            if constexpr (sizeof(Tout) == 4) {
                *(float2*)((float*)C + (size_t)r0 * ldc + c0)       = make_float2(v00, v01);
                *(float2*)((float*)C + (size_t)(r0 + 8) * ldc + c0) = make_float2(v10, v11);
            } else {
                *(__half2*)((__half*)C + (size_t)r0 * ldc + c0)       = __float22half2_rn(make_float2(v00, v01));
                *(__half2*)((__half*)C + (size_t)(r0 + 8) * ldc + c0) = __float22half2_rn(make_float2(v10, v11));
            }
        }
    }
}

// fp32 -> fp16 elementwise (vectorized x2)
__global__ void conv_h(const float* __restrict__ in, __half* __restrict__ out, int n2)
{
    int i = blockIdx.x * blockDim.x + threadIdx.x;
    if (i < n2) {
        float2 v = *(const float2*)(in + 2 * i);
        *(__half2*)(out + 2 * i) = __float22half2_rn(v);
    }
}

// ---------------------------------------------------------------------------
// Row softmax in place on fp16 logits. 256 thr, 2048 cols.
// ---------------------------------------------------------------------------
__global__ void softmax_rows(__half* __restrict__ P)
{
    __half* q = P + (size_t)blockIdx.x * SEQ;
    const int tid = threadIdx.x;

    float2 v[4];
    float mx = -1e30f;
#pragma unroll
    for (int i = 0; i < 4; ++i) {
        v[i] = __half22float2(*(const __half2*)(q + 2 * tid + 512 * i));
        mx = fmaxf(mx, fmaxf(v[i].x, v[i].y));
    }
    __shared__ float red[256];
    red[tid] = mx; __syncthreads();
    for (int s = 128; s > 0; s >>= 1) { if (tid < s) red[tid] = fmaxf(red[tid], red[tid + s]); __syncthreads(); }
    mx = red[0]; __syncthreads();
    float sum = 0.f;
#pragma unroll
    for (int i = 0; i < 4; ++i) {
        v[i].x = __expf(v[i].x - mx); v[i].y = __expf(v[i].y - mx);
        sum += v[i].x + v[i].y;
    }
    red[tid] = sum; __syncthreads();
    for (int s = 128; s > 0; s >>= 1) { if (tid < s) red[tid] += red[tid + s]; __syncthreads(); }
    const float inv = 1.f / red[0];
#pragma unroll
    for (int i = 0; i < 4; ++i)
        *(__half2*)(q + 2 * tid + 512 * i) =
            __float22half2_rn(make_float2(v[i].x * inv, v[i].y * inv));
}

// ---------------------------------------------------------------------------
// Launch
// ---------------------------------------------------------------------------
extern "C" void kernel_launch(void* const* d_in, const int* in_sizes, int n_in,
                              void* d_out, int out_size)
{
    const float* x  = (const float*)d_in[0];
    const float* Wq = (const float*)d_in[1];
    const float* bq = (const float*)d_in[2];
    const float* Wk = (const float*)d_in[3];
    const float* bk = (const float*)d_in[4];
    const float* Wv = (const float*)d_in[5];
    const float* bv = (const float*)d_in[6];
    const float* Wo = (const float*)d_in[7];
    const float* bo = (const float*)d_in[8];
    float* out = (float*)d_out;

    __half *pXh, *pQh, *pKh, *pVh, *pPh, *pAOh, *pWqh, *pWkh, *pWvh, *pWoh;
    cudaGetSymbolAddress((void**)&pXh,  g_Xh);
    cudaGetSymbolAddress((void**)&pQh,  g_Qh);
    cudaGetSymbolAddress((void**)&pKh,  g_Kh);
    cudaGetSymbolAddress((void**)&pVh,  g_Vh);
    cudaGetSymbolAddress((void**)&pPh,  g_Ph);
    cudaGetSymbolAddress((void**)&pAOh, g_AOh);
    cudaGetSymbolAddress((void**)&pWqh, g_Wqh);
    cudaGetSymbolAddress((void**)&pWkh, g_Wkh);
    cudaGetSymbolAddress((void**)&pWvh, g_Wvh);
    cudaGetSymbolAddress((void**)&pWoh, g_Woh);

    cudaFuncSetAttribute((const void*)h_gemm<__half, false>, cudaFuncAttributeMaxDynamicSharedMemorySize, SMEM_MAX);
    cudaFuncSetAttribute((const void*)h_gemm<__half, true>,  cudaFuncAttributeMaxDynamicSharedMemorySize, SMEM_MAX);
    cudaFuncSetAttribute((const void*)h_gemm<float, false>,  cudaFuncAttributeMaxDynamicSharedMemorySize, SMEM_MAX);

    const float scale = 1.0f / sqrtf((float)EMBD);

    // 0) convert inputs/weights to fp16 (layouts unchanged)
    conv_h<<<(MROWS * EMBD / 2 + 255) / 256, 256>>>(x,  pXh,  MROWS * EMBD / 2);
    conv_h<<<(EMBD * HE / 2 + 255) / 256, 256>>>(Wq, pWqh, EMBD * HE / 2);
    conv_h<<<(EMBD * HE / 2 + 255) / 256, 256>>>(Wk, pWkh, EMBD * HE / 2);
    conv_h<<<(EMBD * HE / 2 + 255) / 256, 256>>>(Wv, pWvh, EMBD * HE / 2);
    conv_h<<<(HE * EMBD / 2 + 255) / 256, 256>>>(Wo, pWoh, HE * EMBD / 2);

    // 1-3) QKV projections (NN: B = W [512 x 4096])
    {
        dim3 g(HE / BN, MROWS / BM, 1);
        h_gemm<__half, false><<<g, 256, SMEM_MAX>>>(pXh, pWqh, pQh, EMBD, EMBD, HE, HE,
                                                    0, 0, 0, 0, 0, 0, 1, 1.f, bq);
        h_gemm<__half, false><<<g, 256, SMEM_MAX>>>(pXh, pWkh, pKh, EMBD, EMBD, HE, HE,
                                                    0, 0, 0, 0, 0, 0, 1, 1.f, bk);
        h_gemm<__half, false><<<g, 256, SMEM_MAX>>>(pXh, pWvh, pVh, EMBD, EMBD, HE, HE,
                                                    0, 0, 0, 0, 0, 0, 1, 1.f, bv);
    }

    // 4) logits = scale * Q K^T -> fp16 (NT: B = K [s x emb] K-major)
    {
        dim3 g(SEQ / BN, SEQ / BM, BATCHN * HEADS);
        h_gemm<__half, true><<<g, 256, SMEM_MAX>>>(pQh, pKh, pPh, EMBD, HE, HE, SEQ,
                                                   (long)SEQ * HE, (long)EMBD,
                                                   (long)SEQ * HE, (long)EMBD,
                                                   (long)HEADS * SEQ * SEQ, (long)SEQ * SEQ,
                                                   HEADS, scale, nullptr);
    }

    // 5) softmax in place (fp16)
    softmax_rows<<<BATCHN * HEADS * SEQ, 256>>>(pPh);

    // 6) AO = P @ V (NN: B = V [s x emb] per head)
    {
        dim3 g(EMBD / BN, SEQ / BM, BATCHN * HEADS);
        h_gemm<__half, false><<<g, 256, SMEM_MAX>>>(pPh, pVh, pAOh, SEQ, SEQ, HE, HE,
                                                    (long)HEADS * SEQ * SEQ, (long)SEQ * SEQ,
                                                    (long)SEQ * HE, (long)EMBD,
                                                    (long)SEQ * HE, (long)EMBD,
                                                    HEADS, 1.f, nullptr);
    }

    // 7) out = AO @ Wo + bo (NN: B = Wo [4096 x 512])
    {
        dim3 g(EMBD / BN, MROWS / BM, 1);
        h_gemm<float, false><<<g, 256, SMEM_MAX>>>(pAOh, pWoh, out, HE, HE, EMBD, EMBD,
                                                   0, 0, 0, 0, 0, 0, 1, 1.f, bo);
    }
}

// round 7
// speedup vs baseline: 6.0617x; 1.0010x over previous
#include <cuda_runtime.h>
#include <cuda_fp16.h>
#include <math.h>
#include <stdint.h>

#define BATCHN 4
#define SEQ    2048
#define EMBD   512
#define HEADS  8
#define HE     4096            // HEADS * EMBD
#define MROWS  8192            // BATCHN * SEQ

// ---------------------------------------------------------------------------
// Scratch (allocation-free: device globals)
// ---------------------------------------------------------------------------
__device__ __half g_Xh [(size_t)MROWS * EMBD];
__device__ __half g_Qh [(size_t)MROWS * HE];
__device__ __half g_Kh [(size_t)MROWS * HE];
__device__ __half g_Vh [(size_t)MROWS * HE];
__device__ __half g_Ph [(size_t)BATCHN * HEADS * SEQ * SEQ];   // fp16 logits -> probs
__device__ __half g_AOh[(size_t)MROWS * HE];
__device__ __half g_Wqh[(size_t)EMBD * HE];
__device__ __half g_Wkh[(size_t)EMBD * HE];
__device__ __half g_Wvh[(size_t)EMBD * HE];
__device__ __half g_Woh[(size_t)HE * EMBD];

// ---------------------------------------------------------------------------
// helpers
// ---------------------------------------------------------------------------
__device__ __forceinline__ uint32_t smem_u32(const void* p) {
    uint32_t a;
    asm("{ .reg .u64 t; cvta.to.shared.u64 t, %1; cvt.u32.u64 %0, t; }" : "=r"(a) : "l"(p));
    return a;
}
__device__ __forceinline__ void mma_f16(float& c0, float& c1, float& c2, float& c3,
                                        uint32_t a0, uint32_t a1, uint32_t a2, uint32_t a3,
                                        uint32_t b0, uint32_t b1) {
    asm volatile("mma.sync.aligned.m16n8k16.row.col.f32.f16.f16.f32 "
                 "{%0,%1,%2,%3},{%4,%5,%6,%7},{%8,%9},{%0,%1,%2,%3};"
                 : "+f"(c0), "+f"(c1), "+f"(c2), "+f"(c3)
                 : "r"(a0), "r"(a1), "r"(a2), "r"(a3), "r"(b0), "r"(b1));
}
__device__ __forceinline__ void ldm_x4(uint32_t& r0, uint32_t& r1, uint32_t& r2,
                                       uint32_t& r3, uint32_t addr) {
    asm volatile("ldmatrix.sync.aligned.m8n8.x4.shared.b16 {%0,%1,%2,%3}, [%4];"
                 : "=r"(r0), "=r"(r1), "=r"(r2), "=r"(r3) : "r"(addr));
}
__device__ __forceinline__ void ldm_x4_t(uint32_t& r0, uint32_t& r1, uint32_t& r2,
                                         uint32_t& r3, uint32_t addr) {
    asm volatile("ldmatrix.sync.aligned.m8n8.x4.trans.shared.b16 {%0,%1,%2,%3}, [%4];"
                 : "=r"(r0), "=r"(r1), "=r"(r2), "=r"(r3) : "r"(addr));
}
#define CP_ASYNC16(s, g)  asm volatile("cp.async.cg.shared.global [%0], [%1], 16;" :: "r"(s), "l"(g) : "memory")
#define CP_COMMIT()       asm volatile("cp.async.commit_group;" ::: "memory")
#define CP_WAIT2()        asm volatile("cp.async.wait_group 2;" ::: "memory")

// ---------------------------------------------------------------------------
// fp16 GEMM, fp32 accum: C[M,N] = alpha * A[M,K] * op(B) (+ bias)
//   TRB=true : B is [N,K] (K-major)  -> C = A B^T   (non-trans ldmatrix)
//   TRB=false: B is [K,N] (N-major)  -> C = A B     (trans ldmatrix)
// CTA 128x128xBK32(halfs), 256 threads, warp tile 64x32 (4x4 m16n8k16),
// 4-stage cp.async, one sync per iteration.
// ---------------------------------------------------------------------------
#define BM 128
#define BN 128
#define BKH 32
#define RSH 40                          // A / NT-B padded row stride (halfs)
#define RBH 136                         // NN-B padded row stride (halfs)
#define ATILE_BYTES (128 * RSH * 2)     // 10240
#define SMEM_MAX (4 * (ATILE_BYTES + 128 * RSH * 2))   // 81920 (largest variant)

template<typename Tout, bool TRB>
__global__ __launch_bounds__(256, 2)
void h_gemm(const __half* __restrict__ Ag, const __half* __restrict__ Bg,
            Tout* __restrict__ Cg, int K,
            long lda, long ldb, long ldc,
            long sAb, long sAh, long sBb, long sBh, long sCb, long sCh,
            int Hdiv, float alpha, const float* __restrict__ bias)
{
    constexpr uint32_t BTILE_BYTES = TRB ? (128 * RSH * 2) : (32 * RBH * 2);
    constexpr uint32_t STAGE_BYTES = ATILE_BYTES + BTILE_BYTES;

    extern __shared__ __half smem[];
    const uint32_t sbase = smem_u32(smem);

    const int tid  = threadIdx.x;
    const int wid  = tid >> 5;
    const int lane = tid & 31;
    const int wm   = wid >> 2;         // 0..1
    const int wn   = wid & 3;          // 0..3
    const int lg   = lane >> 2;        // 0..7
    const int lr   = lane & 3;         // 0..3

    const int zb = blockIdx.z / Hdiv;
    const int zh = blockIdx.z % Hdiv;
    const __half* A = Ag + zb * sAb + zh * sAh;
    const __half* B = Bg + zb * sBb + zh * sBh;
    Tout*         C = Cg + zb * sCb + zh * sCh;

    const int m0 = blockIdx.y * BM;
    const int n0 = blockIdx.x * BN;

    // A ldmatrix base (per-lane byte offset within a stage)
    const int arow = lane & 15;
    const int acol = (lane >> 4) << 3;
    const uint32_t aoff = ((wm * 64 + arow) * RSH + acol) * 2;

    // B ldmatrix base
    uint32_t boff;
    if constexpr (TRB) {
        const int brow = (lane & 7) | ((lane >> 4) << 3);
        const int bcol = ((lane >> 3) & 1) << 3;
        boff = ATILE_BYTES + ((wn * 32 + brow) * RSH + bcol) * 2;
    } else {
        const int krow = (lane & 7) + 8 * ((lane >> 3) & 1);
        const int ncol = wn * 32 + 8 * (lane >> 4);
        boff = ATILE_BYTES + krow * (RBH * 2) + ncol * 2;
    }

    float acc[4][4][4];
#pragma unroll
    for (int i = 0; i < 4; ++i)
#pragma unroll
        for (int j = 0; j < 4; ++j)
#pragma unroll
            for (int l = 0; l < 4; ++l) acc[i][j][l] = 0.f;

    const int NT = K / BKH;

    auto load_stage = [&](int kt) {
        const int ring = kt & 3;
        const uint32_t base = sbase + ring * STAGE_BYTES;
        const int k0 = kt * BKH;
#pragma unroll
        for (int i = 0; i < 2; ++i) {
            int id = tid + i * 256;
            int row = id >> 2, ch = id & 3;
            CP_ASYNC16(base + row * (RSH * 2) + ch * 16,
                       A + (size_t)(m0 + row) * lda + k0 + ch * 8);
        }
        if constexpr (TRB) {
#pragma unroll
            for (int i = 0; i < 2; ++i) {
                int id = tid + i * 256;
                int row = id >> 2, ch = id & 3;
                CP_ASYNC16(base + ATILE_BYTES + row * (RSH * 2) + ch * 16,
                           B + (size_t)(n0 + row) * ldb + k0 + ch * 8);
            }
        } else {
#pragma unroll
            for (int i = 0; i < 2; ++i) {
                int id = tid + i * 256;
                int row = id >> 4, ch = id & 15;
                CP_ASYNC16(base + ATILE_BYTES + row * (RBH * 2) + ch * 16,
                           B + (size_t)(k0 + row) * ldb + n0 + ch * 8);
            }
        }
        CP_COMMIT();
    };

    load_stage(0); load_stage(1); load_stage(2);

    for (int kt = 0; kt < NT; ++kt) {
        const int ring = kt & 3;
        CP_WAIT2();
        __syncthreads();

        if (kt + 3 < NT) load_stage(kt + 3); else CP_COMMIT();

        const uint32_t stg = sbase + ring * STAGE_BYTES;

#pragma unroll
        for (int ks = 0; ks < 2; ++ks) {
            uint32_t af[4][4], bf[4][2];
#pragma unroll
            for (int mt = 0; mt < 4; ++mt)
                ldm_x4(af[mt][0], af[mt][1], af[mt][2], af[mt][3],
                       stg + aoff + mt * (16 * RSH * 2) + ks * 32);
            if constexpr (TRB) {
#pragma unroll
                for (int np = 0; np < 2; ++np)
                    ldm_x4(bf[2 * np][0], bf[2 * np][1], bf[2 * np + 1][0], bf[2 * np + 1][1],
                           stg + boff + np * (16 * RSH * 2) + ks * 32);
            } else {
#pragma unroll
                for (int np = 0; np < 2; ++np)
                    ldm_x4_t(bf[2 * np][0], bf[2 * np][1], bf[2 * np + 1][0], bf[2 * np + 1][1],
                             stg + boff + ks * (16 * RBH * 2) + np * 32);
            }
#pragma unroll
            for (int mt = 0; mt < 4; ++mt)
#pragma unroll
                for (int nt = 0; nt < 4; ++nt)
                    mma_f16(acc[mt][nt][0], acc[mt][nt][1], acc[mt][nt][2], acc[mt][nt][3],
                            af[mt][0], af[mt][1], af[mt][2], af[mt][3],
                            bf[nt][0], bf[nt][1]);
        }
    }

    // epilogue
#pragma unroll
    for (int mt = 0; mt < 4; ++mt) {
#pragma unroll
        for (int nt = 0; nt < 4; ++nt) {
            const int r0 = m0 + wm * 64 + mt * 16 + lg;
            const int c0 = n0 + wn * 32 + nt * 8 + 2 * lr;
            float b0v = 0.f, b1v = 0.f;
            if (bias) { b0v = bias[c0]; b1v = bias[c0 + 1]; }
            float v00 = alpha * acc[mt][nt][0] + b0v;
            float v01 = alpha * acc[mt][nt][1] + b1v;
            float v10 = alpha * acc[mt][nt][2] + b0v;
            float v11 = alpha * acc[mt][nt][3] + b1v;
            if constexpr (sizeof(Tout) == 4) {
                *(float2*)((float*)C + (size_t)r0 * ldc + c0)       = make_float2(v00, v01);
                *(float2*)((float*)C + (size_t)(r0 + 8) * ldc + c0) = make_float2(v10, v11);
            } else {
                *(__half2*)((__half*)C + (size_t)r0 * ldc + c0)       = __float22half2_rn(make_float2(v00, v01));
                *(__half2*)((__half*)C + (size_t)(r0 + 8) * ldc + c0) = __float22half2_rn(make_float2(v10, v11));
            }
        }
    }
}

// fp32 -> fp16 elementwise (vectorized x2)
__global__ void conv_h(const float* __restrict__ in, __half* __restrict__ out, int n2)
{
    int i = blockIdx.x * blockDim.x + threadIdx.x;
    if (i < n2) {
        float2 v = *(const float2*)(in + 2 * i);
        *(__half2*)(out + 2 * i) = __float22half2_rn(v);
    }
}

// ---------------------------------------------------------------------------
// Row softmax in place on fp16 logits. 256 thr, 2048 cols.
// ---------------------------------------------------------------------------
__global__ void softmax_rows(__half* __restrict__ P)
{
    __half* q = P + (size_t)blockIdx.x * SEQ;
    const int tid = threadIdx.x;

    float2 v[4];
    float mx = -1e30f;
#pragma unroll
    for (int i = 0; i < 4; ++i) {
        v[i] = __half22float2(*(const __half2*)(q + 2 * tid + 512 * i));
        mx = fmaxf(mx, fmaxf(v[i].x, v[i].y));
    }
    __shared__ float red[256];
    red[tid] = mx; __syncthreads();
    for (int s = 128; s > 0; s >>= 1) { if (tid < s) red[tid] = fmaxf(red[tid], red[tid + s]); __syncthreads(); }
    mx = red[0]; __syncthreads();
    float sum = 0.f;
#pragma unroll
    for (int i = 0; i < 4; ++i) {
        v[i].x = __expf(v[i].x - mx); v[i].y = __expf(v[i].y - mx);
        sum += v[i].x + v[i].y;
    }
    red[tid] = sum; __syncthreads();
    for (int s = 128; s > 0; s >>= 1) { if (tid < s) red[tid] += red[tid + s]; __syncthreads(); }
    const float inv = 1.f / red[0];
#pragma unroll
    for (int i = 0; i < 4; ++i)
        *(__half2*)(q + 2 * tid + 512 * i) =
            __float22half2_rn(make_float2(v[i].x * inv, v[i].y * inv));
}

// ---------------------------------------------------------------------------
// Launch — graph fork/join: V path overlaps the softmax window.
// ---------------------------------------------------------------------------
extern "C" void kernel_launch(void* const* d_in, const int* in_sizes, int n_in,
                              void* d_out, int out_size)
{
    const float* x  = (const float*)d_in[0];
    const float* Wq = (const float*)d_in[1];
    const float* bq = (const float*)d_in[2];
    const float* Wk = (const float*)d_in[3];
    const float* bk = (const float*)d_in[4];
    const float* Wv = (const float*)d_in[5];
    const float* bv = (const float*)d_in[6];
    const float* Wo = (const float*)d_in[7];
    const float* bo = (const float*)d_in[8];
    float* out = (float*)d_out;

    __half *pXh, *pQh, *pKh, *pVh, *pPh, *pAOh, *pWqh, *pWkh, *pWvh, *pWoh;
    cudaGetSymbolAddress((void**)&pXh,  g_Xh);
    cudaGetSymbolAddress((void**)&pQh,  g_Qh);
    cudaGetSymbolAddress((void**)&pKh,  g_Kh);
    cudaGetSymbolAddress((void**)&pVh,  g_Vh);
    cudaGetSymbolAddress((void**)&pPh,  g_Ph);
    cudaGetSymbolAddress((void**)&pAOh, g_AOh);
    cudaGetSymbolAddress((void**)&pWqh, g_Wqh);
    cudaGetSymbolAddress((void**)&pWkh, g_Wkh);
    cudaGetSymbolAddress((void**)&pWvh, g_Wvh);
    cudaGetSymbolAddress((void**)&pWoh, g_Woh);

    cudaFuncSetAttribute((const void*)h_gemm<__half, false>, cudaFuncAttributeMaxDynamicSharedMemorySize, SMEM_MAX);
    cudaFuncSetAttribute((const void*)h_gemm<__half, true>,  cudaFuncAttributeMaxDynamicSharedMemorySize, SMEM_MAX);
    cudaFuncSetAttribute((const void*)h_gemm<float, false>,  cudaFuncAttributeMaxDynamicSharedMemorySize, SMEM_MAX);

    // Side stream + events (host objects, created once; no device memory).
    static cudaStream_t s1 = nullptr;
    static cudaEvent_t evFork = nullptr, evJoin = nullptr;
    if (s1 == nullptr) {
        cudaStreamCreateWithFlags(&s1, cudaStreamNonBlocking);
        cudaEventCreateWithFlags(&evFork, cudaEventDisableTiming);
        cudaEventCreateWithFlags(&evJoin, cudaEventDisableTiming);
    }

    const float scale = 1.0f / sqrtf((float)EMBD);

    // 0) convert x + Wq + Wk (main stream). Wv/Wo convert later on side stream.
    conv_h<<<(MROWS * EMBD / 2 + 255) / 256, 256>>>(x,  pXh,  MROWS * EMBD / 2);
    conv_h<<<(EMBD * HE / 2 + 255) / 256, 256>>>(Wq, pWqh, EMBD * HE / 2);
    conv_h<<<(EMBD * HE / 2 + 255) / 256, 256>>>(Wk, pWkh, EMBD * HE / 2);

    // 1-2) Q, K projections (NN: B = W [512 x 4096])
    {
        dim3 g(HE / BN, MROWS / BM, 1);
        h_gemm<__half, false><<<g, 256, SMEM_MAX>>>(pXh, pWqh, pQh, EMBD, EMBD, HE, HE,
                                                    0, 0, 0, 0, 0, 0, 1, 1.f, bq);
        h_gemm<__half, false><<<g, 256, SMEM_MAX>>>(pXh, pWkh, pKh, EMBD, EMBD, HE, HE,
                                                    0, 0, 0, 0, 0, 0, 1, 1.f, bk);
    }

    // 3) logits = scale * Q K^T -> fp16 (NT)
    {
        dim3 g(SEQ / BN, SEQ / BM, BATCHN * HEADS);
        h_gemm<__half, true><<<g, 256, SMEM_MAX>>>(pQh, pKh, pPh, EMBD, HE, HE, SEQ,
                                                   (long)SEQ * HE, (long)EMBD,
                                                   (long)SEQ * HE, (long)EMBD,
                                                   (long)HEADS * SEQ * SEQ, (long)SEQ * SEQ,
                                                   HEADS, scale, nullptr);
    }

    // Fork AFTER scores: the V path then co-runs with the memory-bound softmax,
    // filling the tensor-idle window (forking earlier would just steal tensor
    // throughput from Q/K/scores with zero net gain).
    cudaEventRecord(evFork, 0);
    cudaStreamWaitEvent(s1, evFork, 0);

    // side stream: conv Wv -> V projection -> conv Wo
    conv_h<<<(EMBD * HE / 2 + 255) / 256, 256, 0, s1>>>(Wv, pWvh, EMBD * HE / 2);
    {
        dim3 g(HE / BN, MROWS / BM, 1);
        h_gemm<__half, false><<<g, 256, SMEM_MAX, s1>>>(pXh, pWvh, pVh, EMBD, EMBD, HE, HE,
                                                        0, 0, 0, 0, 0, 0, 1, 1.f, bv);
    }
    conv_h<<<(HE * EMBD / 2 + 255) / 256, 256, 0, s1>>>(Wo, pWoh, HE * EMBD / 2);
    cudaEventRecord(evJoin, s1);

    // main stream: softmax in place (fp16), concurrent with V path
    softmax_rows<<<BATCHN * HEADS * SEQ, 256>>>(pPh);

    // join before AV
    cudaStreamWaitEvent(0, evJoin, 0);

    // 4) AO = P @ V (NN: B = V [s x emb] per head)
    {
        dim3 g(EMBD / BN, SEQ / BM, BATCHN * HEADS);
        h_gemm<__half, false><<<g, 256, SMEM_MAX>>>(pPh, pVh, pAOh, SEQ, SEQ, HE, HE,
                                                    (long)HEADS * SEQ * SEQ, (long)SEQ * SEQ,
                                                    (long)SEQ * HE, (long)EMBD,
                                                    (long)SEQ * HE, (long)EMBD,
                                                    HEADS, 1.f, nullptr);
    }

    // 5) out = AO @ Wo + bo (NN: B = Wo [4096 x 512])
    {
        dim3 g(EMBD / BN, MROWS / BM, 1);
        h_gemm<float, false><<<g, 256, SMEM_MAX>>>(pAOh, pWoh, out, HE, HE, EMBD, EMBD,
                                                   0, 0, 0, 0, 0, 0, 1, 1.f, bo);
    }
}

// round 8
// speedup vs baseline: 6.6665x; 1.0998x over previous
#include <cuda_runtime.h>
#include <cuda_fp16.h>
#include <math.h>
#include <stdint.h>

#define BATCHN 4
#define SEQ    2048
#define EMBD   512
#define HEADS  8
#define HE     4096            // HEADS * EMBD
#define MROWS  8192            // BATCHN * SEQ

// ---------------------------------------------------------------------------
// Scratch (allocation-free: device globals)
// ---------------------------------------------------------------------------
__device__ __half g_Xh [(size_t)MROWS * EMBD];
__device__ __half g_Qh [(size_t)MROWS * HE];
__device__ __half g_Kh [(size_t)MROWS * HE];
__device__ __half g_Vh [(size_t)MROWS * HE];
__device__ __half g_Ph [(size_t)BATCHN * HEADS * SEQ * SEQ];   // fp16 logits -> probs
__device__ __half g_AOh[(size_t)MROWS * HE];
__device__ __half g_Wqh[(size_t)EMBD * HE];
__device__ __half g_Wkh[(size_t)EMBD * HE];
__device__ __half g_Wvh[(size_t)EMBD * HE];
__device__ __half g_Woh[(size_t)HE * EMBD];

// ---------------------------------------------------------------------------
// helpers
// ---------------------------------------------------------------------------
__device__ __forceinline__ uint32_t smem_u32(const void* p) {
    uint32_t a;
    asm("{ .reg .u64 t; cvta.to.shared.u64 t, %1; cvt.u32.u64 %0, t; }" : "=r"(a) : "l"(p));
    return a;
}
__device__ __forceinline__ void mma_f16(float& c0, float& c1, float& c2, float& c3,
                                        uint32_t a0, uint32_t a1, uint32_t a2, uint32_t a3,
                                        uint32_t b0, uint32_t b1) {
    asm volatile("mma.sync.aligned.m16n8k16.row.col.f32.f16.f16.f32 "
                 "{%0,%1,%2,%3},{%4,%5,%6,%7},{%8,%9},{%0,%1,%2,%3};"
                 : "+f"(c0), "+f"(c1), "+f"(c2), "+f"(c3)
                 : "r"(a0), "r"(a1), "r"(a2), "r"(a3), "r"(b0), "r"(b1));
}
__device__ __forceinline__ void ldm_x4(uint32_t& r0, uint32_t& r1, uint32_t& r2,
                                       uint32_t& r3, uint32_t addr) {
    asm volatile("ldmatrix.sync.aligned.m8n8.x4.shared.b16 {%0,%1,%2,%3}, [%4];"
                 : "=r"(r0), "=r"(r1), "=r"(r2), "=r"(r3) : "r"(addr));
}
__device__ __forceinline__ void ldm_x4_t(uint32_t& r0, uint32_t& r1, uint32_t& r2,
                                         uint32_t& r3, uint32_t addr) {
    asm volatile("ldmatrix.sync.aligned.m8n8.x4.trans.shared.b16 {%0,%1,%2,%3}, [%4];"
                 : "=r"(r0), "=r"(r1), "=r"(r2), "=r"(r3) : "r"(addr));
}
#define CP_ASYNC16(s, g)  asm volatile("cp.async.cg.shared.global [%0], [%1], 16;" :: "r"(s), "l"(g) : "memory")
#define CP_COMMIT()       asm volatile("cp.async.commit_group;" ::: "memory")
#define CP_WAIT2()        asm volatile("cp.async.wait_group 2;" ::: "memory")

// ---------------------------------------------------------------------------
// fp16 GEMM, fp32 accum: C[M,N] = alpha * A[M,K] * op(B) (+ bias)
//   TRB=true : B is [N,K] (K-major)  -> C = A B^T   (non-trans ldmatrix)
//   TRB=false: B is [K,N] (N-major)  -> C = A B     (trans ldmatrix)
// CTA 128x128xBK32(halfs), 128 threads, warp tile 64x64 (2x2 warps, 4x8
// m16n8k16 per warp), 4-stage cp.async, one sync per iteration.
// ---------------------------------------------------------------------------
#define BM 128
#define BN 128
#define BKH 32
#define RSH 40                          // A / NT-B padded row stride (halfs)
#define RBH 136                         // NN-B padded row stride (halfs)
#define ATILE_BYTES (128 * RSH * 2)     // 10240
#define SMEM_MAX (4 * (ATILE_BYTES + 128 * RSH * 2))   // 81920 (largest variant)

template<typename Tout, bool TRB>
__global__ __launch_bounds__(128, 2)
void h_gemm(const __half* __restrict__ Ag, const __half* __restrict__ Bg,
            Tout* __restrict__ Cg, int K,
            long lda, long ldb, long ldc,
            long sAb, long sAh, long sBb, long sBh, long sCb, long sCh,
            int Hdiv, float alpha, const float* __restrict__ bias)
{
    constexpr uint32_t BTILE_BYTES = TRB ? (128 * RSH * 2) : (32 * RBH * 2);
    constexpr uint32_t STAGE_BYTES = ATILE_BYTES + BTILE_BYTES;

    extern __shared__ __half smem[];
    const uint32_t sbase = smem_u32(smem);

    const int tid  = threadIdx.x;
    const int wid  = tid >> 5;
    const int lane = tid & 31;
    const int wm   = wid >> 1;         // 0..1 -> 64-row slab
    const int wn   = wid & 1;          // 0..1 -> 64-col slab
    const int lg   = lane >> 2;        // 0..7
    const int lr   = lane & 3;         // 0..3

    const int zb = blockIdx.z / Hdiv;
    const int zh = blockIdx.z % Hdiv;
    const __half* A = Ag + zb * sAb + zh * sAh;
    const __half* B = Bg + zb * sBb + zh * sBh;
    Tout*         C = Cg + zb * sCb + zh * sCh;

    const int m0 = blockIdx.y * BM;
    const int n0 = blockIdx.x * BN;

    // A ldmatrix base (per-lane byte offset within a stage)
    const int arow = lane & 15;
    const int acol = (lane >> 4) << 3;
    const uint32_t aoff = ((wm * 64 + arow) * RSH + acol) * 2;

    // B ldmatrix base
    uint32_t boff;
    if constexpr (TRB) {
        const int brow = (lane & 7) | ((lane >> 4) << 3);
        const int bcol = ((lane >> 3) & 1) << 3;
        boff = ATILE_BYTES + ((wn * 64 + brow) * RSH + bcol) * 2;
    } else {
        const int krow = (lane & 7) + 8 * ((lane >> 3) & 1);
        const int ncol = wn * 64 + 8 * (lane >> 4);
        boff = ATILE_BYTES + krow * (RBH * 2) + ncol * 2;
    }

    float acc[4][8][4];
#pragma unroll
    for (int i = 0; i < 4; ++i)
#pragma unroll
        for (int j = 0; j < 8; ++j)
#pragma unroll
            for (int l = 0; l < 4; ++l) acc[i][j][l] = 0.f;

    const int NT = K / BKH;

    auto load_stage = [&](int kt) {
        const int ring = kt & 3;
        const uint32_t base = sbase + ring * STAGE_BYTES;
        const int k0 = kt * BKH;
        // A: 128 rows x 32 halfs, 4 x 16B chunks per row (512 tasks / 128 thr)
#pragma unroll
        for (int i = 0; i < 4; ++i) {
            int id = tid + i * 128;
            int row = id >> 2, ch = id & 3;
            CP_ASYNC16(base + row * (RSH * 2) + ch * 16,
                       A + (size_t)(m0 + row) * lda + k0 + ch * 8);
        }
        if constexpr (TRB) {
#pragma unroll
            for (int i = 0; i < 4; ++i) {
                int id = tid + i * 128;
                int row = id >> 2, ch = id & 3;
                CP_ASYNC16(base + ATILE_BYTES + row * (RSH * 2) + ch * 16,
                           B + (size_t)(n0 + row) * ldb + k0 + ch * 8);
            }
        } else {
            // B: 32 k-rows x 128 halfs, 16 x 16B chunks per row
#pragma unroll
            for (int i = 0; i < 4; ++i) {
                int id = tid + i * 128;
                int row = id >> 4, ch = id & 15;
                CP_ASYNC16(base + ATILE_BYTES + row * (RBH * 2) + ch * 16,
                           B + (size_t)(k0 + row) * ldb + n0 + ch * 8);
            }
        }
        CP_COMMIT();
    };

    load_stage(0); load_stage(1); load_stage(2);

    for (int kt = 0; kt < NT; ++kt) {
        const int ring = kt & 3;
        CP_WAIT2();
        __syncthreads();

        if (kt + 3 < NT) load_stage(kt + 3); else CP_COMMIT();

        const uint32_t stg = sbase + ring * STAGE_BYTES;

#pragma unroll
        for (int ks = 0; ks < 2; ++ks) {
            uint32_t af[4][4], bf[8][2];
#pragma unroll
            for (int mt = 0; mt < 4; ++mt)
                ldm_x4(af[mt][0], af[mt][1], af[mt][2], af[mt][3],
                       stg + aoff + mt * (16 * RSH * 2) + ks * 32);
            if constexpr (TRB) {
#pragma unroll
                for (int np = 0; np < 4; ++np)
                    ldm_x4(bf[2 * np][0], bf[2 * np][1], bf[2 * np + 1][0], bf[2 * np + 1][1],
                           stg + boff + np * (16 * RSH * 2) + ks * 32);
            } else {
#pragma unroll
                for (int np = 0; np < 4; ++np)
                    ldm_x4_t(bf[2 * np][0], bf[2 * np][1], bf[2 * np + 1][0], bf[2 * np + 1][1],
                             stg + boff + ks * (16 * RBH * 2) + np * 32);
            }
#pragma unroll
            for (int mt = 0; mt < 4; ++mt)
#pragma unroll
                for (int nt = 0; nt < 8; ++nt)
                    mma_f16(acc[mt][nt][0], acc[mt][nt][1], acc[mt][nt][2], acc[mt][nt][3],
                            af[mt][0], af[mt][1], af[mt][2], af[mt][3],
                            bf[nt][0], bf[nt][1]);
        }
    }

    // epilogue
#pragma unroll
    for (int mt = 0; mt < 4; ++mt) {
#pragma unroll
        for (int nt = 0; nt < 8; ++nt) {
            const int r0 = m0 + wm * 64 + mt * 16 + lg;
            const int c0 = n0 + wn * 64 + nt * 8 + 2 * lr;
            float b0v = 0.f, b1v = 0.f;
            if (bias) { b0v = bias[c0]; b1v = bias[c0 + 1]; }
            float v00 = alpha * acc[mt][nt][0] + b0v;
            float v01 = alpha * acc[mt][nt][1] + b1v;
            float v10 = alpha * acc[mt][nt][2] + b0v;
            float v11 = alpha * acc[mt][nt][3] + b1v;
            if constexpr (sizeof(Tout) == 4) {
                *(float2*)((float*)C + (size_t)r0 * ldc + c0)       = make_float2(v00, v01);
                *(float2*)((float*)C + (size_t)(r0 + 8) * ldc + c0) = make_float2(v10, v11);
            } else {
                *(__half2*)((__half*)C + (size_t)r0 * ldc + c0)       = __float22half2_rn(make_float2(v00, v01));
                *(__half2*)((__half*)C + (size_t)(r0 + 8) * ldc + c0) = __float22half2_rn(make_float2(v10, v11));
            }
        }
    }
}

// fp32 -> fp16 elementwise (vectorized x2)
__global__ void conv_h(const float* __restrict__ in, __half* __restrict__ out, int n2)
{
    int i = blockIdx.x * blockDim.x + threadIdx.x;
    if (i < n2) {
        float2 v = *(const float2*)(in + 2 * i);
        *(__half2*)(out + 2 * i) = __float22half2_rn(v);
    }
}

// ---------------------------------------------------------------------------
// Row softmax in place on fp16 logits. 256 thr, 2048 cols.
// ---------------------------------------------------------------------------
__global__ void softmax_rows(__half* __restrict__ P)
{
    __half* q = P + (size_t)blockIdx.x * SEQ;
    const int tid = threadIdx.x;

    float2 v[4];
    float mx = -1e30f;
#pragma unroll
    for (int i = 0; i < 4; ++i) {
        v[i] = __half22float2(*(const __half2*)(q + 2 * tid + 512 * i));
        mx = fmaxf(mx, fmaxf(v[i].x, v[i].y));
    }
    __shared__ float red[256];
    red[tid] = mx; __syncthreads();
    for (int s = 128; s > 0; s >>= 1) { if (tid < s) red[tid] = fmaxf(red[tid], red[tid + s]); __syncthreads(); }
    mx = red[0]; __syncthreads();
    float sum = 0.f;
#pragma unroll
    for (int i = 0; i < 4; ++i) {
        v[i].x = __expf(v[i].x - mx); v[i].y = __expf(v[i].y - mx);
        sum += v[i].x + v[i].y;
    }
    red[tid] = sum; __syncthreads();
    for (int s = 128; s > 0; s >>= 1) { if (tid < s) red[tid] += red[tid + s]; __syncthreads(); }
    const float inv = 1.f / red[0];
#pragma unroll
    for (int i = 0; i < 4; ++i)
        *(__half2*)(q + 2 * tid + 512 * i) =
            __float22half2_rn(make_float2(v[i].x * inv, v[i].y * inv));
}

// ---------------------------------------------------------------------------
// Launch — graph fork/join: V path overlaps the softmax window.
// ---------------------------------------------------------------------------
extern "C" void kernel_launch(void* const* d_in, const int* in_sizes, int n_in,
                              void* d_out, int out_size)
{
    const float* x  = (const float*)d_in[0];
    const float* Wq = (const float*)d_in[1];
    const float* bq = (const float*)d_in[2];
    const float* Wk = (const float*)d_in[3];
    const float* bk = (const float*)d_in[4];
    const float* Wv = (const float*)d_in[5];
    const float* bv = (const float*)d_in[6];
    const float* Wo = (const float*)d_in[7];
    const float* bo = (const float*)d_in[8];
    float* out = (float*)d_out;

    __half *pXh, *pQh, *pKh, *pVh, *pPh, *pAOh, *pWqh, *pWkh, *pWvh, *pWoh;
    cudaGetSymbolAddress((void**)&pXh,  g_Xh);
    cudaGetSymbolAddress((void**)&pQh,  g_Qh);
    cudaGetSymbolAddress((void**)&pKh,  g_Kh);
    cudaGetSymbolAddress((void**)&pVh,  g_Vh);
    cudaGetSymbolAddress((void**)&pPh,  g_Ph);
    cudaGetSymbolAddress((void**)&pAOh, g_AOh);
    cudaGetSymbolAddress((void**)&pWqh, g_Wqh);
    cudaGetSymbolAddress((void**)&pWkh, g_Wkh);
    cudaGetSymbolAddress((void**)&pWvh, g_Wvh);
    cudaGetSymbolAddress((void**)&pWoh, g_Woh);

    cudaFuncSetAttribute((const void*)h_gemm<__half, false>, cudaFuncAttributeMaxDynamicSharedMemorySize, SMEM_MAX);
    cudaFuncSetAttribute((const void*)h_gemm<__half, true>,  cudaFuncAttributeMaxDynamicSharedMemorySize, SMEM_MAX);
    cudaFuncSetAttribute((const void*)h_gemm<float, false>,  cudaFuncAttributeMaxDynamicSharedMemorySize, SMEM_MAX);

    // Side stream + events (host objects, created once; no device memory).
    static cudaStream_t s1 = nullptr;
    static cudaEvent_t evFork = nullptr, evJoin = nullptr;
    if (s1 == nullptr) {
        cudaStreamCreateWithFlags(&s1, cudaStreamNonBlocking);
        cudaEventCreateWithFlags(&evFork, cudaEventDisableTiming);
        cudaEventCreateWithFlags(&evJoin, cudaEventDisableTiming);
    }

    const float scale = 1.0f / sqrtf((float)EMBD);

    // 0) convert x + Wq + Wk (main stream). Wv/Wo convert later on side stream.
    conv_h<<<(MROWS * EMBD / 2 + 255) / 256, 256>>>(x,  pXh,  MROWS * EMBD / 2);
    conv_h<<<(EMBD * HE / 2 + 255) / 256, 256>>>(Wq, pWqh, EMBD * HE / 2);
    conv_h<<<(EMBD * HE / 2 + 255) / 256, 256>>>(Wk, pWkh, EMBD * HE / 2);

    // 1-2) Q, K projections (NN: B = W [512 x 4096])
    {
        dim3 g(HE / BN, MROWS / BM, 1);
        h_gemm<__half, false><<<g, 128, SMEM_MAX>>>(pXh, pWqh, pQh, EMBD, EMBD, HE, HE,
                                                    0, 0, 0, 0, 0, 0, 1, 1.f, bq);
        h_gemm<__half, false><<<g, 128, SMEM_MAX>>>(pXh, pWkh, pKh, EMBD, EMBD, HE, HE,
                                                    0, 0, 0, 0, 0, 0, 1, 1.f, bk);
    }

    // 3) logits = scale * Q K^T -> fp16 (NT)
    {
        dim3 g(SEQ / BN, SEQ / BM, BATCHN * HEADS);
        h_gemm<__half, true><<<g, 128, SMEM_MAX>>>(pQh, pKh, pPh, EMBD, HE, HE, SEQ,
                                                   (long)SEQ * HE, (long)EMBD,
                                                   (long)SEQ * HE, (long)EMBD,
                                                   (long)HEADS * SEQ * SEQ, (long)SEQ * SEQ,
                                                   HEADS, scale, nullptr);
    }

    // Fork AFTER scores: V path co-runs with the memory-bound softmax.
    cudaEventRecord(evFork, 0);
    cudaStreamWaitEvent(s1, evFork, 0);

    // side stream: conv Wv -> V projection -> conv Wo
    conv_h<<<(EMBD * HE / 2 + 255) / 256, 256, 0, s1>>>(Wv, pWvh, EMBD * HE / 2);
    {
        dim3 g(HE / BN, MROWS / BM, 1);
        h_gemm<__half, false><<<g, 128, SMEM_MAX, s1>>>(pXh, pWvh, pVh, EMBD, EMBD, HE, HE,
                                                        0, 0, 0, 0, 0, 0, 1, 1.f, bv);
    }
    conv_h<<<(HE * EMBD / 2 + 255) / 256, 256, 0, s1>>>(Wo, pWoh, HE * EMBD / 2);
    cudaEventRecord(evJoin, s1);

    // main stream: softmax in place (fp16), concurrent with V path
    softmax_rows<<<BATCHN * HEADS * SEQ, 256>>>(pPh);

    // join before AV
    cudaStreamWaitEvent(0, evJoin, 0);

    // 4) AO = P @ V (NN: B = V [s x emb] per head)
    {
        dim3 g(EMBD / BN, SEQ / BM, BATCHN * HEADS);
        h_gemm<__half, false><<<g, 128, SMEM_MAX>>>(pPh, pVh, pAOh, SEQ, SEQ, HE, HE,
                                                    (long)HEADS * SEQ * SEQ, (long)SEQ * SEQ,
                                                    (long)SEQ * HE, (long)EMBD,
                                                    (long)SEQ * HE, (long)EMBD,
                                                    HEADS, 1.f, nullptr);
    }

    // 5) out = AO @ Wo + bo (NN: B = Wo [4096 x 512])
    {
        dim3 g(EMBD / BN, MROWS / BM, 1);
        h_gemm<float, false><<<g, 128, SMEM_MAX>>>(pAOh, pWoh, out, HE, HE, EMBD, EMBD,
                                                   0, 0, 0, 0, 0, 0, 1, 1.f, bo);
    }
}

// round 9
// speedup vs baseline: 7.1537x; 1.0731x over previous
#include <cuda_runtime.h>
#include <cuda_fp16.h>
#include <math.h>
#include <stdint.h>

#define BATCHN 4
#define SEQ    2048
#define EMBD   512
#define HEADS  8
#define HE     4096            // HEADS * EMBD
#define MROWS  8192            // BATCHN * SEQ

// ---------------------------------------------------------------------------
// Scratch (allocation-free: device globals)
// ---------------------------------------------------------------------------
__device__ __half g_Xh [(size_t)MROWS * EMBD];
__device__ __half g_Qh [(size_t)MROWS * HE];
__device__ __half g_Kh [(size_t)MROWS * HE];
__device__ __half g_Vh [(size_t)MROWS * HE];
__device__ __half g_Ph [(size_t)BATCHN * HEADS * SEQ * SEQ];   // fp16 logits -> probs
__device__ __half g_AOh[(size_t)MROWS * HE];
__device__ __half g_Wqh[(size_t)EMBD * HE];
__device__ __half g_Wkh[(size_t)EMBD * HE];
__device__ __half g_Wvh[(size_t)EMBD * HE];
__device__ __half g_Woh[(size_t)HE * EMBD];

// ---------------------------------------------------------------------------
// helpers
// ---------------------------------------------------------------------------
__device__ __forceinline__ uint32_t smem_u32(const void* p) {
    uint32_t a;
    asm("{ .reg .u64 t; cvta.to.shared.u64 t, %1; cvt.u32.u64 %0, t; }" : "=r"(a) : "l"(p));
    return a;
}
__device__ __forceinline__ void mma_f16(float& c0, float& c1, float& c2, float& c3,
                                        uint32_t a0, uint32_t a1, uint32_t a2, uint32_t a3,
                                        uint32_t b0, uint32_t b1) {
    asm volatile("mma.sync.aligned.m16n8k16.row.col.f32.f16.f16.f32 "
                 "{%0,%1,%2,%3},{%4,%5,%6,%7},{%8,%9},{%0,%1,%2,%3};"
                 : "+f"(c0), "+f"(c1), "+f"(c2), "+f"(c3)
                 : "r"(a0), "r"(a1), "r"(a2), "r"(a3), "r"(b0), "r"(b1));
}
__device__ __forceinline__ void ldm_x4(uint32_t& r0, uint32_t& r1, uint32_t& r2,
                                       uint32_t& r3, uint32_t addr) {
    asm volatile("ldmatrix.sync.aligned.m8n8.x4.shared.b16 {%0,%1,%2,%3}, [%4];"
                 : "=r"(r0), "=r"(r1), "=r"(r2), "=r"(r3) : "r"(addr));
}
__device__ __forceinline__ void ldm_x4_t(uint32_t& r0, uint32_t& r1, uint32_t& r2,
                                         uint32_t& r3, uint32_t addr) {
    asm volatile("ldmatrix.sync.aligned.m8n8.x4.trans.shared.b16 {%0,%1,%2,%3}, [%4];"
                 : "=r"(r0), "=r"(r1), "=r"(r2), "=r"(r3) : "r"(addr));
}
#define CP_ASYNC16(s, g)  asm volatile("cp.async.cg.shared.global [%0], [%1], 16;" :: "r"(s), "l"(g) : "memory")
#define CP_COMMIT()       asm volatile("cp.async.commit_group;" ::: "memory")
#define CP_WAIT1()        asm volatile("cp.async.wait_group 1;" ::: "memory")

// ---------------------------------------------------------------------------
// fp16 GEMM, fp32 accum: C[M,N] = alpha * A[M,K] * op(B) (+ bias)
//   TRB=true : B is [N,K] (K-major)  -> C = A B^T   (non-trans ldmatrix)
//   TRB=false: B is [K,N] (N-major)  -> C = A B     (trans ldmatrix)
// CTA 128x128xBK32(halfs), 128 threads, warp tile 64x64 (2x2 warps, 4x8
// m16n8k16 per warp), 4-stage cp.async, cross-iteration fragment prefetch.
// ---------------------------------------------------------------------------
#define BM 128
#define BN 128
#define BKH 32
#define RSH 40                          // A / NT-B padded row stride (halfs)
#define RBH 136                         // NN-B padded row stride (halfs)
#define ATILE_BYTES (128 * RSH * 2)     // 10240
#define SMEM_MAX (4 * (ATILE_BYTES + 128 * RSH * 2))   // 81920 (largest variant)

template<typename Tout, bool TRB>
__global__ __launch_bounds__(128, 2)
void h_gemm(const __half* __restrict__ Ag, const __half* __restrict__ Bg,
            Tout* __restrict__ Cg, int K,
            long lda, long ldb, long ldc,
            long sAb, long sAh, long sBb, long sBh, long sCb, long sCh,
            int Hdiv, float alpha, const float* __restrict__ bias)
{
    constexpr uint32_t BTILE_BYTES = TRB ? (128 * RSH * 2) : (32 * RBH * 2);
    constexpr uint32_t STAGE_BYTES = ATILE_BYTES + BTILE_BYTES;

    extern __shared__ __half smem[];
    const uint32_t sbase = smem_u32(smem);

    const int tid  = threadIdx.x;
    const int wid  = tid >> 5;
    const int lane = tid & 31;
    const int wm   = wid >> 1;         // 0..1 -> 64-row slab
    const int wn   = wid & 1;          // 0..1 -> 64-col slab
    const int lg   = lane >> 2;        // 0..7
    const int lr   = lane & 3;         // 0..3

    const int zb = blockIdx.z / Hdiv;
    const int zh = blockIdx.z % Hdiv;
    const __half* A = Ag + zb * sAb + zh * sAh;
    const __half* B = Bg + zb * sBb + zh * sBh;
    Tout*         C = Cg + zb * sCb + zh * sCh;

    const int m0 = blockIdx.y * BM;
    const int n0 = blockIdx.x * BN;

    // A ldmatrix base (per-lane byte offset within a stage)
    const int arow = lane & 15;
    const int acol = (lane >> 4) << 3;
    const uint32_t aoff = ((wm * 64 + arow) * RSH + acol) * 2;

    // B ldmatrix base
    uint32_t boff;
    if constexpr (TRB) {
        const int brow = (lane & 7) | ((lane >> 4) << 3);
        const int bcol = ((lane >> 3) & 1) << 3;
        boff = ATILE_BYTES + ((wn * 64 + brow) * RSH + bcol) * 2;
    } else {
        const int krow = (lane & 7) + 8 * ((lane >> 3) & 1);
        const int ncol = wn * 64 + 8 * (lane >> 4);
        boff = ATILE_BYTES + krow * (RBH * 2) + ncol * 2;
    }

    float acc[4][8][4];
#pragma unroll
    for (int i = 0; i < 4; ++i)
#pragma unroll
        for (int j = 0; j < 8; ++j)
#pragma unroll
            for (int l = 0; l < 4; ++l) acc[i][j][l] = 0.f;

    const int NT = K / BKH;

    auto load_stage = [&](int kt) {
        const int ring = kt & 3;
        const uint32_t base = sbase + ring * STAGE_BYTES;
        const int k0 = kt * BKH;
#pragma unroll
        for (int i = 0; i < 4; ++i) {
            int id = tid + i * 128;
            int row = id >> 2, ch = id & 3;
            CP_ASYNC16(base + row * (RSH * 2) + ch * 16,
                       A + (size_t)(m0 + row) * lda + k0 + ch * 8);
        }
        if constexpr (TRB) {
#pragma unroll
            for (int i = 0; i < 4; ++i) {
                int id = tid + i * 128;
                int row = id >> 2, ch = id & 3;
                CP_ASYNC16(base + ATILE_BYTES + row * (RSH * 2) + ch * 16,
                           B + (size_t)(n0 + row) * ldb + k0 + ch * 8);
            }
        } else {
#pragma unroll
            for (int i = 0; i < 4; ++i) {
                int id = tid + i * 128;
                int row = id >> 4, ch = id & 15;
                CP_ASYNC16(base + ATILE_BYTES + row * (RBH * 2) + ch * 16,
                           B + (size_t)(k0 + row) * ldb + n0 + ch * 8);
            }
        }
        CP_COMMIT();
    };

    // fragment loader: frags for half-tile ks (0/1) of the stage at 'stg'
    auto ldm_all = [&](uint32_t stg, int ks, uint32_t af[4][4], uint32_t bf[8][2]) {
#pragma unroll
        for (int mt = 0; mt < 4; ++mt)
            ldm_x4(af[mt][0], af[mt][1], af[mt][2], af[mt][3],
                   stg + aoff + mt * (16 * RSH * 2) + ks * 32);
        if constexpr (TRB) {
#pragma unroll
            for (int np = 0; np < 4; ++np)
                ldm_x4(bf[2 * np][0], bf[2 * np][1], bf[2 * np + 1][0], bf[2 * np + 1][1],
                       stg + boff + np * (16 * RSH * 2) + ks * 32);
        } else {
#pragma unroll
            for (int np = 0; np < 4; ++np)
                ldm_x4_t(bf[2 * np][0], bf[2 * np][1], bf[2 * np + 1][0], bf[2 * np + 1][1],
                         stg + boff + ks * (16 * RBH * 2) + np * 32);
        }
    };

    auto mma_all = [&](uint32_t af[4][4], uint32_t bf[8][2]) {
#pragma unroll
        for (int mt = 0; mt < 4; ++mt)
#pragma unroll
            for (int nt = 0; nt < 8; ++nt)
                mma_f16(acc[mt][nt][0], acc[mt][nt][1], acc[mt][nt][2], acc[mt][nt][3],
                        af[mt][0], af[mt][1], af[mt][2], af[mt][3],
                        bf[nt][0], bf[nt][1]);
    };

    load_stage(0); load_stage(1); load_stage(2);

    // Prologue: stages 0 and 1 complete + published; preload (kt=0, ks=0) frags.
    CP_WAIT1();
    __syncthreads();

    uint32_t afA[4][4], bfA[8][2], afB[4][4], bfB[8][2];
    ldm_all(sbase, 0, afA, bfA);

    for (int kt = 0; kt < NT; ++kt) {
        const uint32_t stg = sbase + (kt & 3) * STAGE_BYTES;

        // Refill ring (kt+3)&3 == (kt-1)&3: all warps finished reading stage
        // kt-1 before the barrier that ended iteration kt-1.
        if (kt + 3 < NT) load_stage(kt + 3); else CP_COMMIT();

        ldm_all(stg, 1, afB, bfB);          // (kt, ks=1)
        mma_all(afA, bfA);                  // (kt, ks=0) — loaded last iteration

        // Prefetch (kt+1, ks=0): stage kt+1 is complete+published (invariant),
        // and writes only target ring (kt+3)&3 != (kt+1)&3.
        const int ktn = (kt + 1 < NT) ? kt + 1 : kt;
        ldm_all(sbase + (ktn & 3) * STAGE_BYTES, 0, afA, bfA);
        mma_all(afB, bfB);                  // (kt, ks=1)

        // Establish invariant for kt+1: stages kt+1, kt+2 complete + published.
        CP_WAIT1();
        __syncthreads();
    }

    // epilogue
#pragma unroll
    for (int mt = 0; mt < 4; ++mt) {
#pragma unroll
        for (int nt = 0; nt < 8; ++nt) {
            const int r0 = m0 + wm * 64 + mt * 16 + lg;
            const int c0 = n0 + wn * 64 + nt * 8 + 2 * lr;
            float b0v = 0.f, b1v = 0.f;
            if (bias) { b0v = bias[c0]; b1v = bias[c0 + 1]; }
            float v00 = alpha * acc[mt][nt][0] + b0v;
            float v01 = alpha * acc[mt][nt][1] + b1v;
            float v10 = alpha * acc[mt][nt][2] + b0v;
            float v11 = alpha * acc[mt][nt][3] + b1v;
            if constexpr (sizeof(Tout) == 4) {
                *(float2*)((float*)C + (size_t)r0 * ldc + c0)       = make_float2(v00, v01);
                *(float2*)((float*)C + (size_t)(r0 + 8) * ldc + c0) = make_float2(v10, v11);
            } else {
                *(__half2*)((__half*)C + (size_t)r0 * ldc + c0)       = __float22half2_rn(make_float2(v00, v01));
                *(__half2*)((__half*)C + (size_t)(r0 + 8) * ldc + c0) = __float22half2_rn(make_float2(v10, v11));
            }
        }
    }
}

// fp32 -> fp16 elementwise (vectorized x2)
__global__ void conv_h(const float* __restrict__ in, __half* __restrict__ out, int n2)
{
    int i = blockIdx.x * blockDim.x + threadIdx.x;
    if (i < n2) {
        float2 v = *(const float2*)(in + 2 * i);
        *(__half2*)(out + 2 * i) = __float22half2_rn(v);
    }
}

// ---------------------------------------------------------------------------
// Row softmax in place on fp16 logits. 256 thr, 2048 cols.
// ---------------------------------------------------------------------------
__global__ void softmax_rows(__half* __restrict__ P)
{
    __half* q = P + (size_t)blockIdx.x * SEQ;
    const int tid = threadIdx.x;

    float2 v[4];
    float mx = -1e30f;
#pragma unroll
    for (int i = 0; i < 4; ++i) {
        v[i] = __half22float2(*(const __half2*)(q + 2 * tid + 512 * i));
        mx = fmaxf(mx, fmaxf(v[i].x, v[i].y));
    }
    __shared__ float red[256];
    red[tid] = mx; __syncthreads();
    for (int s = 128; s > 0; s >>= 1) { if (tid < s) red[tid] = fmaxf(red[tid], red[tid + s]); __syncthreads(); }
    mx = red[0]; __syncthreads();
    float sum = 0.f;
#pragma unroll
    for (int i = 0; i < 4; ++i) {
        v[i].x = __expf(v[i].x - mx); v[i].y = __expf(v[i].y - mx);
        sum += v[i].x + v[i].y;
    }
    red[tid] = sum; __syncthreads();
    for (int s = 128; s > 0; s >>= 1) { if (tid < s) red[tid] += red[tid + s]; __syncthreads(); }
    const float inv = 1.f / red[0];
#pragma unroll
    for (int i = 0; i < 4; ++i)
        *(__half2*)(q + 2 * tid + 512 * i) =
            __float22half2_rn(make_float2(v[i].x * inv, v[i].y * inv));
}

// ---------------------------------------------------------------------------
// Launch — graph fork/join: V path overlaps the softmax window.
// ---------------------------------------------------------------------------
extern "C" void kernel_launch(void* const* d_in, const int* in_sizes, int n_in,
                              void* d_out, int out_size)
{
    const float* x  = (const float*)d_in[0];
    const float* Wq = (const float*)d_in[1];
    const float* bq = (const float*)d_in[2];
    const float* Wk = (const float*)d_in[3];
    const float* bk = (const float*)d_in[4];
    const float* Wv = (const float*)d_in[5];
    const float* bv = (const float*)d_in[6];
    const float* Wo = (const float*)d_in[7];
    const float* bo = (const float*)d_in[8];
    float* out = (float*)d_out;

    __half *pXh, *pQh, *pKh, *pVh, *pPh, *pAOh, *pWqh, *pWkh, *pWvh, *pWoh;
    cudaGetSymbolAddress((void**)&pXh,  g_Xh);
    cudaGetSymbolAddress((void**)&pQh,  g_Qh);
    cudaGetSymbolAddress((void**)&pKh,  g_Kh);
    cudaGetSymbolAddress((void**)&pVh,  g_Vh);
    cudaGetSymbolAddress((void**)&pPh,  g_Ph);
    cudaGetSymbolAddress((void**)&pAOh, g_AOh);
    cudaGetSymbolAddress((void**)&pWqh, g_Wqh);
    cudaGetSymbolAddress((void**)&pWkh, g_Wkh);
    cudaGetSymbolAddress((void**)&pWvh, g_Wvh);
    cudaGetSymbolAddress((void**)&pWoh, g_Woh);

    cudaFuncSetAttribute((const void*)h_gemm<__half, false>, cudaFuncAttributeMaxDynamicSharedMemorySize, SMEM_MAX);
    cudaFuncSetAttribute((const void*)h_gemm<__half, true>,  cudaFuncAttributeMaxDynamicSharedMemorySize, SMEM_MAX);
    cudaFuncSetAttribute((const void*)h_gemm<float, false>,  cudaFuncAttributeMaxDynamicSharedMemorySize, SMEM_MAX);

    // Side stream + events (host objects, created once; no device memory).
    static cudaStream_t s1 = nullptr;
    static cudaEvent_t evFork = nullptr, evJoin = nullptr;
    if (s1 == nullptr) {
        cudaStreamCreateWithFlags(&s1, cudaStreamNonBlocking);
        cudaEventCreateWithFlags(&evFork, cudaEventDisableTiming);
        cudaEventCreateWithFlags(&evJoin, cudaEventDisableTiming);
    }

    const float scale = 1.0f / sqrtf((float)EMBD);

    // 0) convert x + Wq + Wk (main stream). Wv/Wo convert later on side stream.
    conv_h<<<(MROWS * EMBD / 2 + 255) / 256, 256>>>(x,  pXh,  MROWS * EMBD / 2);
    conv_h<<<(EMBD * HE / 2 + 255) / 256, 256>>>(Wq, pWqh, EMBD * HE / 2);
    conv_h<<<(EMBD * HE / 2 + 255) / 256, 256>>>(Wk, pWkh, EMBD * HE / 2);

    // 1-2) Q, K projections (NN: B = W [512 x 4096])
    {
        dim3 g(HE / BN, MROWS / BM, 1);
        h_gemm<__half, false><<<g, 128, SMEM_MAX>>>(pXh, pWqh, pQh, EMBD, EMBD, HE, HE,
                                                    0, 0, 0, 0, 0, 0, 1, 1.f, bq);
        h_gemm<__half, false><<<g, 128, SMEM_MAX>>>(pXh, pWkh, pKh, EMBD, EMBD, HE, HE,
                                                    0, 0, 0, 0, 0, 0, 1, 1.f, bk);
    }

    // 3) logits = scale * Q K^T -> fp16 (NT)
    {
        dim3 g(SEQ / BN, SEQ / BM, BATCHN * HEADS);
        h_gemm<__half, true><<<g, 128, SMEM_MAX>>>(pQh, pKh, pPh, EMBD, HE, HE, SEQ,
                                                   (long)SEQ * HE, (long)EMBD,
                                                   (long)SEQ * HE, (long)EMBD,
                                                   (long)HEADS * SEQ * SEQ, (long)SEQ * SEQ,
                                                   HEADS, scale, nullptr);
    }

    // Fork AFTER scores: V path co-runs with the memory-bound softmax.
    cudaEventRecord(evFork, 0);
    cudaStreamWaitEvent(s1, evFork, 0);

    // side stream: conv Wv -> V projection -> conv Wo
    conv_h<<<(EMBD * HE / 2 + 255) / 256, 256, 0, s1>>>(Wv, pWvh, EMBD * HE / 2);
    {
        dim3 g(HE / BN, MROWS / BM, 1);
        h_gemm<__half, false><<<g, 128, SMEM_MAX, s1>>>(pXh, pWvh, pVh, EMBD, EMBD, HE, HE,
                                                        0, 0, 0, 0, 0, 0, 1, 1.f, bv);
    }
    conv_h<<<(HE * EMBD / 2 + 255) / 256, 256, 0, s1>>>(Wo, pWoh, HE * EMBD / 2);
    cudaEventRecord(evJoin, s1);

    // main stream: softmax in place (fp16), concurrent with V path
    softmax_rows<<<BATCHN * HEADS * SEQ, 256>>>(pPh);

    // join before AV
    cudaStreamWaitEvent(0, evJoin, 0);

    // 4) AO = P @ V (NN: B = V [s x emb] per head)
    {
        dim3 g(EMBD / BN, SEQ / BM, BATCHN * HEADS);
        h_gemm<__half, false><<<g, 128, SMEM_MAX>>>(pPh, pVh, pAOh, SEQ, SEQ, HE, HE,
                                                    (long)HEADS * SEQ * SEQ, (long)SEQ * SEQ,
                                                    (long)SEQ * HE, (long)EMBD,
                                                    (long)SEQ * HE, (long)EMBD,
                                                    HEADS, 1.f, nullptr);
    }

    // 5) out = AO @ Wo + bo (NN: B = Wo [4096 x 512])
    {
        dim3 g(EMBD / BN, MROWS / BM, 1);
        h_gemm<float, false><<<g, 128, SMEM_MAX>>>(pAOh, pWoh, out, HE, HE, EMBD, EMBD,
                                                   0, 0, 0, 0, 0, 0, 1, 1.f, bo);
    }
}

// round 10
// speedup vs baseline: 7.4023x; 1.0347x over previous
#include <cuda_runtime.h>
#include <cuda_fp16.h>
#include <math.h>
#include <stdint.h>

#define BATCHN 4
#define SEQ    2048
#define EMBD   512
#define HEADS  8
#define HE     4096            // HEADS * EMBD
#define MROWS  8192            // BATCHN * SEQ

// ---------------------------------------------------------------------------
// Scratch (allocation-free: device globals)
// ---------------------------------------------------------------------------
__device__ __half g_Xh [(size_t)MROWS * EMBD];
__device__ __half g_Qh [(size_t)MROWS * HE];
__device__ __half g_Kh [(size_t)MROWS * HE];
__device__ __half g_Vh [(size_t)MROWS * HE];
__device__ __half g_Ph [(size_t)BATCHN * HEADS * SEQ * SEQ];   // fp16 logits -> probs
__device__ __half g_AOh[(size_t)MROWS * HE];
__device__ __half g_Wqh[(size_t)EMBD * HE];
__device__ __half g_Wkh[(size_t)EMBD * HE];
__device__ __half g_Wvh[(size_t)EMBD * HE];
__device__ __half g_Woh[(size_t)HE * EMBD];

// ---------------------------------------------------------------------------
// helpers
// ---------------------------------------------------------------------------
__device__ __forceinline__ uint32_t smem_u32(const void* p) {
    uint32_t a;
    asm("{ .reg .u64 t; cvta.to.shared.u64 t, %1; cvt.u32.u64 %0, t; }" : "=r"(a) : "l"(p));
    return a;
}
__device__ __forceinline__ void mma_f16(float& c0, float& c1, float& c2, float& c3,
                                        uint32_t a0, uint32_t a1, uint32_t a2, uint32_t a3,
                                        uint32_t b0, uint32_t b1) {
    asm volatile("mma.sync.aligned.m16n8k16.row.col.f32.f16.f16.f32 "
                 "{%0,%1,%2,%3},{%4,%5,%6,%7},{%8,%9},{%0,%1,%2,%3};"
                 : "+f"(c0), "+f"(c1), "+f"(c2), "+f"(c3)
                 : "r"(a0), "r"(a1), "r"(a2), "r"(a3), "r"(b0), "r"(b1));
}
__device__ __forceinline__ void ldm_x4(uint32_t& r0, uint32_t& r1, uint32_t& r2,
                                       uint32_t& r3, uint32_t addr) {
    asm volatile("ldmatrix.sync.aligned.m8n8.x4.shared.b16 {%0,%1,%2,%3}, [%4];"
                 : "=r"(r0), "=r"(r1), "=r"(r2), "=r"(r3) : "r"(addr));
}
__device__ __forceinline__ void ldm_x4_t(uint32_t& r0, uint32_t& r1, uint32_t& r2,
                                         uint32_t& r3, uint32_t addr) {
    asm volatile("ldmatrix.sync.aligned.m8n8.x4.trans.shared.b16 {%0,%1,%2,%3}, [%4];"
                 : "=r"(r0), "=r"(r1), "=r"(r2), "=r"(r3) : "r"(addr));
}
#define CP_ASYNC16(s, g)  asm volatile("cp.async.cg.shared.global [%0], [%1], 16;" :: "r"(s), "l"(g) : "memory")
#define CP_COMMIT()       asm volatile("cp.async.commit_group;" ::: "memory")
#define CP_WAIT1()        asm volatile("cp.async.wait_group 1;" ::: "memory")

// ---------------------------------------------------------------------------
// fp16 GEMM, fp32 accum: C[M,N] = alpha * A[M,K] * op(B) (+ bias)
//   TRB=true : B is [N,K] (K-major)  -> C = A B^T   (non-trans ldmatrix)
//   TRB=false: B is [K,N] (N-major)  -> C = A B     (trans ldmatrix)
// CTA 128x128xBK64(halfs), 128 threads, warp tile 64x64 (2x2 warps, 4x8
// m16n8k16 per warp), 3-stage cp.async, cross-iteration fragment prefetch,
// 4 ks-chunks per kt with alternating frag buffers.
// ---------------------------------------------------------------------------
#define BM 128
#define BN 128
#define BKH 64                          // halfs per stage-k (four k16 steps)
#define RSH 72                          // A / NT-B padded row stride (halfs)
#define RBH 136                         // NN-B padded row stride (halfs)
#define ATILE_BYTES (128 * RSH * 2)     // 18432
#define NSTAGE 3
#define SMEM_MAX (NSTAGE * (ATILE_BYTES + 128 * RSH * 2))   // 110592 (TRB variant)

template<typename Tout, bool TRB>
__global__ __launch_bounds__(128, 2)
void h_gemm(const __half* __restrict__ Ag, const __half* __restrict__ Bg,
            Tout* __restrict__ Cg, int K,
            long lda, long ldb, long ldc,
            long sAb, long sAh, long sBb, long sBh, long sCb, long sCh,
            int Hdiv, float alpha, const float* __restrict__ bias)
{
    constexpr uint32_t BTILE_BYTES = TRB ? (128 * RSH * 2) : (64 * RBH * 2);
    constexpr uint32_t STAGE_BYTES = ATILE_BYTES + BTILE_BYTES;

    extern __shared__ __half smem[];
    const uint32_t sbase = smem_u32(smem);

    const int tid  = threadIdx.x;
    const int wid  = tid >> 5;
    const int lane = tid & 31;
    const int wm   = wid >> 1;         // 0..1 -> 64-row slab
    const int wn   = wid & 1;          // 0..1 -> 64-col slab
    const int lg   = lane >> 2;        // 0..7
    const int lr   = lane & 3;         // 0..3

    const int zb = blockIdx.z / Hdiv;
    const int zh = blockIdx.z % Hdiv;
    const __half* A = Ag + zb * sAb + zh * sAh;
    const __half* B = Bg + zb * sBb + zh * sBh;
    Tout*         C = Cg + zb * sCb + zh * sCh;

    const int m0 = blockIdx.y * BM;
    const int n0 = blockIdx.x * BN;

    // A ldmatrix base (per-lane byte offset within a stage)
    const int arow = lane & 15;
    const int acol = (lane >> 4) << 3;
    const uint32_t aoff = ((wm * 64 + arow) * RSH + acol) * 2;

    // B ldmatrix base
    uint32_t boff;
    if constexpr (TRB) {
        const int brow = (lane & 7) | ((lane >> 4) << 3);
        const int bcol = ((lane >> 3) & 1) << 3;
        boff = ATILE_BYTES + ((wn * 64 + brow) * RSH + bcol) * 2;
    } else {
        const int krow = (lane & 7) + 8 * ((lane >> 3) & 1);
        const int ncol = wn * 64 + 8 * (lane >> 4);
        boff = ATILE_BYTES + krow * (RBH * 2) + ncol * 2;
    }

    float acc[4][8][4];
#pragma unroll
    for (int i = 0; i < 4; ++i)
#pragma unroll
        for (int j = 0; j < 8; ++j)
#pragma unroll
            for (int l = 0; l < 4; ++l) acc[i][j][l] = 0.f;

    const int NT = K / BKH;

    auto load_stage = [&](int kt) {
        const int ring = kt % NSTAGE;
        const uint32_t base = sbase + ring * STAGE_BYTES;
        const int k0 = kt * BKH;
        // A: 128 rows x 64 halfs (128B), 8 x 16B chunks per row
#pragma unroll
        for (int i = 0; i < 8; ++i) {
            int id = tid + i * 128;
            int row = id >> 3, ch = id & 7;
            CP_ASYNC16(base + row * (RSH * 2) + ch * 16,
                       A + (size_t)(m0 + row) * lda + k0 + ch * 8);
        }
        if constexpr (TRB) {
            // B: 128 n-rows x 64 halfs
#pragma unroll
            for (int i = 0; i < 8; ++i) {
                int id = tid + i * 128;
                int row = id >> 3, ch = id & 7;
                CP_ASYNC16(base + ATILE_BYTES + row * (RSH * 2) + ch * 16,
                           B + (size_t)(n0 + row) * ldb + k0 + ch * 8);
            }
        } else {
            // B: 64 k-rows x 128 halfs (256B), 16 x 16B chunks per row
#pragma unroll
            for (int i = 0; i < 8; ++i) {
                int id = tid + i * 128;
                int row = id >> 4, ch = id & 15;
                CP_ASYNC16(base + ATILE_BYTES + row * (RBH * 2) + ch * 16,
                           B + (size_t)(k0 + row) * ldb + n0 + ch * 8);
            }
        }
        CP_COMMIT();
    };

    // fragment loader: frags for k16-chunk ks (0..3) of the stage at 'stg'
    auto ldm_all = [&](uint32_t stg, int ks, uint32_t af[4][4], uint32_t bf[8][2]) {
#pragma unroll
        for (int mt = 0; mt < 4; ++mt)
            ldm_x4(af[mt][0], af[mt][1], af[mt][2], af[mt][3],
                   stg + aoff + mt * (16 * RSH * 2) + ks * 32);
        if constexpr (TRB) {
#pragma unroll
            for (int np = 0; np < 4; ++np)
                ldm_x4(bf[2 * np][0], bf[2 * np][1], bf[2 * np + 1][0], bf[2 * np + 1][1],
                       stg + boff + np * (16 * RSH * 2) + ks * 32);
        } else {
#pragma unroll
            for (int np = 0; np < 4; ++np)
                ldm_x4_t(bf[2 * np][0], bf[2 * np][1], bf[2 * np + 1][0], bf[2 * np + 1][1],
                         stg + boff + ks * (16 * RBH * 2) + np * 32);
        }
    };

    auto mma_all = [&](uint32_t af[4][4], uint32_t bf[8][2]) {
#pragma unroll
        for (int mt = 0; mt < 4; ++mt)
#pragma unroll
            for (int nt = 0; nt < 8; ++nt)
                mma_f16(acc[mt][nt][0], acc[mt][nt][1], acc[mt][nt][2], acc[mt][nt][3],
                        af[mt][0], af[mt][1], af[mt][2], af[mt][3],
                        bf[nt][0], bf[nt][1]);
    };

    load_stage(0); load_stage(1);

    // Prologue: stage 0 complete + published; preload (kt=0, ks=0) frags.
    CP_WAIT1();
    __syncthreads();

    uint32_t afA[4][4], bfA[8][2], afB[4][4], bfB[8][2];
    ldm_all(sbase, 0, afA, bfA);

    for (int kt = 0; kt < NT; ++kt) {
        const uint32_t stg = sbase + (kt % NSTAGE) * STAGE_BYTES;

        // Refill ring (kt+2)%3 == (kt-1)%3: readers of stage kt-1 finished
        // before the barrier at the end of body kt-1.
        if (kt + 2 < NT) load_stage(kt + 2); else CP_COMMIT();

        ldm_all(stg, 1, afB, bfB);  mma_all(afA, bfA);   // ks0 (prefetched)
        ldm_all(stg, 2, afA, bfA);  mma_all(afB, bfB);   // ks1
        ldm_all(stg, 3, afB, bfB);  mma_all(afA, bfA);   // ks2

        // Ensure stage kt+1 complete (outstanding: only this body's group),
        // then publish across warps before prefetching from it.
        CP_WAIT1();
        __syncthreads();

        const int ktn = (kt + 1 < NT) ? kt + 1 : kt;
        ldm_all(sbase + (ktn % NSTAGE) * STAGE_BYTES, 0, afA, bfA);  // (kt+1, ks0)
        mma_all(afB, bfB);                                           // ks3
    }

    // epilogue
#pragma unroll
    for (int mt = 0; mt < 4; ++mt) {
#pragma unroll
        for (int nt = 0; nt < 8; ++nt) {
            const int r0 = m0 + wm * 64 + mt * 16 + lg;
            const int c0 = n0 + wn * 64 + nt * 8 + 2 * lr;
            float b0v = 0.f, b1v = 0.f;
            if (bias) { b0v = bias[c0]; b1v = bias[c0 + 1]; }
            float v00 = alpha * acc[mt][nt][0] + b0v;
            float v01 = alpha * acc[mt][nt][1] + b1v;
            float v10 = alpha * acc[mt][nt][2] + b0v;
            float v11 = alpha * acc[mt][nt][3] + b1v;
            if constexpr (sizeof(Tout) == 4) {
                *(float2*)((float*)C + (size_t)r0 * ldc + c0)       = make_float2(v00, v01);
                *(float2*)((float*)C + (size_t)(r0 + 8) * ldc + c0) = make_float2(v10, v11);
            } else {
                *(__half2*)((__half*)C + (size_t)r0 * ldc + c0)       = __float22half2_rn(make_float2(v00, v01));
                *(__half2*)((__half*)C + (size_t)(r0 + 8) * ldc + c0) = __float22half2_rn(make_float2(v10, v11));
            }
        }
    }
}

// fp32 -> fp16 elementwise (vectorized x2)
__global__ void conv_h(const float* __restrict__ in, __half* __restrict__ out, int n2)
{
    int i = blockIdx.x * blockDim.x + threadIdx.x;
    if (i < n2) {
        float2 v = *(const float2*)(in + 2 * i);
        *(__half2*)(out + 2 * i) = __float22half2_rn(v);
    }
}

// ---------------------------------------------------------------------------
// Row softmax in place on fp16 logits. 256 thr, 2048 cols.
// ---------------------------------------------------------------------------
__global__ void softmax_rows(__half* __restrict__ P)
{
    __half* q = P + (size_t)blockIdx.x * SEQ;
    const int tid = threadIdx.x;

    float2 v[4];
    float mx = -1e30f;
#pragma unroll
    for (int i = 0; i < 4; ++i) {
        v[i] = __half22float2(*(const __half2*)(q + 2 * tid + 512 * i));
        mx = fmaxf(mx, fmaxf(v[i].x, v[i].y));
    }
    __shared__ float red[256];
    red[tid] = mx; __syncthreads();
    for (int s = 128; s > 0; s >>= 1) { if (tid < s) red[tid] = fmaxf(red[tid], red[tid + s]); __syncthreads(); }
    mx = red[0]; __syncthreads();
    float sum = 0.f;
#pragma unroll
    for (int i = 0; i < 4; ++i) {
        v[i].x = __expf(v[i].x - mx); v[i].y = __expf(v[i].y - mx);
        sum += v[i].x + v[i].y;
    }
    red[tid] = sum; __syncthreads();
    for (int s = 128; s > 0; s >>= 1) { if (tid < s) red[tid] += red[tid + s]; __syncthreads(); }
    const float inv = 1.f / red[0];
#pragma unroll
    for (int i = 0; i < 4; ++i)
        *(__half2*)(q + 2 * tid + 512 * i) =
            __float22half2_rn(make_float2(v[i].x * inv, v[i].y * inv));
}

// ---------------------------------------------------------------------------
// Launch — graph fork/join: V path overlaps the softmax window.
// ---------------------------------------------------------------------------
extern "C" void kernel_launch(void* const* d_in, const int* in_sizes, int n_in,
                              void* d_out, int out_size)
{
    const float* x  = (const float*)d_in[0];
    const float* Wq = (const float*)d_in[1];
    const float* bq = (const float*)d_in[2];
    const float* Wk = (const float*)d_in[3];
    const float* bk = (const float*)d_in[4];
    const float* Wv = (const float*)d_in[5];
    const float* bv = (const float*)d_in[6];
    const float* Wo = (const float*)d_in[7];
    const float* bo = (const float*)d_in[8];
    float* out = (float*)d_out;

    __half *pXh, *pQh, *pKh, *pVh, *pPh, *pAOh, *pWqh, *pWkh, *pWvh, *pWoh;
    cudaGetSymbolAddress((void**)&pXh,  g_Xh);
    cudaGetSymbolAddress((void**)&pQh,  g_Qh);
    cudaGetSymbolAddress((void**)&pKh,  g_Kh);
    cudaGetSymbolAddress((void**)&pVh,  g_Vh);
    cudaGetSymbolAddress((void**)&pPh,  g_Ph);
    cudaGetSymbolAddress((void**)&pAOh, g_AOh);
    cudaGetSymbolAddress((void**)&pWqh, g_Wqh);
    cudaGetSymbolAddress((void**)&pWkh, g_Wkh);
    cudaGetSymbolAddress((void**)&pWvh, g_Wvh);
    cudaGetSymbolAddress((void**)&pWoh, g_Woh);

    cudaFuncSetAttribute((const void*)h_gemm<__half, false>, cudaFuncAttributeMaxDynamicSharedMemorySize, SMEM_MAX);
    cudaFuncSetAttribute((const void*)h_gemm<__half, true>,  cudaFuncAttributeMaxDynamicSharedMemorySize, SMEM_MAX);
    cudaFuncSetAttribute((const void*)h_gemm<float, false>,  cudaFuncAttributeMaxDynamicSharedMemorySize, SMEM_MAX);

    // Side stream + events (host objects, created once; no device memory).
    static cudaStream_t s1 = nullptr;
    static cudaEvent_t evFork = nullptr, evJoin = nullptr;
    if (s1 == nullptr) {
        cudaStreamCreateWithFlags(&s1, cudaStreamNonBlocking);
        cudaEventCreateWithFlags(&evFork, cudaEventDisableTiming);
        cudaEventCreateWithFlags(&evJoin, cudaEventDisableTiming);
    }

    const float scale = 1.0f / sqrtf((float)EMBD);

    // 0) convert x + Wq + Wk (main stream). Wv/Wo convert later on side stream.
    conv_h<<<(MROWS * EMBD / 2 + 255) / 256, 256>>>(x,  pXh,  MROWS * EMBD / 2);
    conv_h<<<(EMBD * HE / 2 + 255) / 256, 256>>>(Wq, pWqh, EMBD * HE / 2);
    conv_h<<<(EMBD * HE / 2 + 255) / 256, 256>>>(Wk, pWkh, EMBD * HE / 2);

    // 1-2) Q, K projections (NN: B = W [512 x 4096])
    {
        dim3 g(HE / BN, MROWS / BM, 1);
        h_gemm<__half, false><<<g, 128, SMEM_MAX>>>(pXh, pWqh, pQh, EMBD, EMBD, HE, HE,
                                                    0, 0, 0, 0, 0, 0, 1, 1.f, bq);
        h_gemm<__half, false><<<g, 128, SMEM_MAX>>>(pXh, pWkh, pKh, EMBD, EMBD, HE, HE,
                                                    0, 0, 0, 0, 0, 0, 1, 1.f, bk);
    }

    // 3) logits = scale * Q K^T -> fp16 (NT)
    {
        dim3 g(SEQ / BN, SEQ / BM, BATCHN * HEADS);
        h_gemm<__half, true><<<g, 128, SMEM_MAX>>>(pQh, pKh, pPh, EMBD, HE, HE, SEQ,
                                                   (long)SEQ * HE, (long)EMBD,
                                                   (long)SEQ * HE, (long)EMBD,
                                                   (long)HEADS * SEQ * SEQ, (long)SEQ * SEQ,
                                                   HEADS, scale, nullptr);
    }

    // Fork AFTER scores: V path co-runs with the memory-bound softmax.
    cudaEventRecord(evFork, 0);
    cudaStreamWaitEvent(s1, evFork, 0);

    // side stream: conv Wv -> V projection -> conv Wo
    conv_h<<<(EMBD * HE / 2 + 255) / 256, 256, 0, s1>>>(Wv, pWvh, EMBD * HE / 2);
    {
        dim3 g(HE / BN, MROWS / BM, 1);
        h_gemm<__half, false><<<g, 128, SMEM_MAX, s1>>>(pXh, pWvh, pVh, EMBD, EMBD, HE, HE,
                                                        0, 0, 0, 0, 0, 0, 1, 1.f, bv);
    }
    conv_h<<<(HE * EMBD / 2 + 255) / 256, 256, 0, s1>>>(Wo, pWoh, HE * EMBD / 2);
    cudaEventRecord(evJoin, s1);

    // main stream: softmax in place (fp16), concurrent with V path
    softmax_rows<<<BATCHN * HEADS * SEQ, 256>>>(pPh);

    // join before AV
    cudaStreamWaitEvent(0, evJoin, 0);

    // 4) AO = P @ V (NN: B = V [s x emb] per head)
    {
        dim3 g(EMBD / BN, SEQ / BM, BATCHN * HEADS);
        h_gemm<__half, false><<<g, 128, SMEM_MAX>>>(pPh, pVh, pAOh, SEQ, SEQ, HE, HE,
                                                    (long)HEADS * SEQ * SEQ, (long)SEQ * SEQ,
                                                    (long)SEQ * HE, (long)EMBD,
                                                    (long)SEQ * HE, (long)EMBD,
                                                    HEADS, 1.f, nullptr);
    }

    // 5) out = AO @ Wo + bo (NN: B = Wo [4096 x 512])
    {
        dim3 g(EMBD / BN, MROWS / BM, 1);
        h_gemm<float, false><<<g, 128, SMEM_MAX>>>(pAOh, pWoh, out, HE, HE, EMBD, EMBD,
                                                   0, 0, 0, 0, 0, 0, 1, 1.f, bo);
    }
}

// round 11
// speedup vs baseline: 7.4763x; 1.0100x over previous
#include <cuda_runtime.h>
#include <cuda_fp16.h>
#include <math.h>
#include <stdint.h>

#define BATCHN 4
#define SEQ    2048
#define EMBD   512
#define HEADS  8
#define HE     4096            // HEADS * EMBD
#define MROWS  8192            // BATCHN * SEQ

// ---------------------------------------------------------------------------
// Scratch (allocation-free: device globals)
// ---------------------------------------------------------------------------
__device__ __half g_Xh [(size_t)MROWS * EMBD];
__device__ __half g_Qh [(size_t)MROWS * HE];
__device__ __half g_Kh [(size_t)MROWS * HE];
__device__ __half g_Vh [(size_t)MROWS * HE];
__device__ __half g_Ph [(size_t)BATCHN * HEADS * SEQ * SEQ];   // fp16 logits -> probs
__device__ __half g_AOh[(size_t)MROWS * HE];
__device__ __half g_Wqh[(size_t)EMBD * HE];
__device__ __half g_Wkh[(size_t)EMBD * HE];
__device__ __half g_Wvh[(size_t)EMBD * HE];
__device__ __half g_Woh[(size_t)HE * EMBD];

// ---------------------------------------------------------------------------
// helpers
// ---------------------------------------------------------------------------
__device__ __forceinline__ uint32_t smem_u32(const void* p) {
    uint32_t a;
    asm("{ .reg .u64 t; cvta.to.shared.u64 t, %1; cvt.u32.u64 %0, t; }" : "=r"(a) : "l"(p));
    return a;
}
__device__ __forceinline__ void mma_f16(float& c0, float& c1, float& c2, float& c3,
                                        uint32_t a0, uint32_t a1, uint32_t a2, uint32_t a3,
                                        uint32_t b0, uint32_t b1) {
    asm volatile("mma.sync.aligned.m16n8k16.row.col.f32.f16.f16.f32 "
                 "{%0,%1,%2,%3},{%4,%5,%6,%7},{%8,%9},{%0,%1,%2,%3};"
                 : "+f"(c0), "+f"(c1), "+f"(c2), "+f"(c3)
                 : "r"(a0), "r"(a1), "r"(a2), "r"(a3), "r"(b0), "r"(b1));
}
__device__ __forceinline__ void ldm_x4(uint32_t& r0, uint32_t& r1, uint32_t& r2,
                                       uint32_t& r3, uint32_t addr) {
    asm volatile("ldmatrix.sync.aligned.m8n8.x4.shared.b16 {%0,%1,%2,%3}, [%4];"
                 : "=r"(r0), "=r"(r1), "=r"(r2), "=r"(r3) : "r"(addr));
}
__device__ __forceinline__ void ldm_x4_t(uint32_t& r0, uint32_t& r1, uint32_t& r2,
                                         uint32_t& r3, uint32_t addr) {
    asm volatile("ldmatrix.sync.aligned.m8n8.x4.trans.shared.b16 {%0,%1,%2,%3}, [%4];"
                 : "=r"(r0), "=r"(r1), "=r"(r2), "=r"(r3) : "r"(addr));
}
#define CP_ASYNC16(s, g)  asm volatile("cp.async.cg.shared.global [%0], [%1], 16;" :: "r"(s), "l"(g) : "memory")
#define CP_COMMIT()       asm volatile("cp.async.commit_group;" ::: "memory")
#define CP_WAIT1()        asm volatile("cp.async.wait_group 1;" ::: "memory")

// ---------------------------------------------------------------------------
// fp16 GEMM, fp32 accum: C[M,N] = alpha * A[M,K] * op(B) (+ bias)
//   TRB=true : B is [N,K] (K-major)  -> C = A B^T   (non-trans ldmatrix)
//   TRB=false: B is [K,N] (N-major)  -> C = A B     (trans ldmatrix)
// CTA 128x128xBK64(halfs), 128 threads, warp tile 64x64 (2x2 warps, 4x8
// m16n8k16 per warp), 3-stage cp.async, cross-iteration fragment prefetch,
// cp.async chunks interleaved into the mma stream (volatile asm preserves
// source order, so interleaving here is the scheduler).
// ---------------------------------------------------------------------------
#define BM 128
#define BN 128
#define BKH 64                          // halfs per stage-k (four k16 steps)
#define RSH 72                          // A / NT-B padded row stride (halfs)
#define RBH 136                         // NN-B padded row stride (halfs)
#define ATILE_BYTES (128 * RSH * 2)     // 18432
#define NSTAGE 3
#define SMEM_MAX (NSTAGE * (ATILE_BYTES + 128 * RSH * 2))   // 110592 (TRB variant)

template<typename Tout, bool TRB>
__global__ __launch_bounds__(128, 2)
void h_gemm(const __half* __restrict__ Ag, const __half* __restrict__ Bg,
            Tout* __restrict__ Cg, int K,
            long lda, long ldb, long ldc,
            long sAb, long sAh, long sBb, long sBh, long sCb, long sCh,
            int Hdiv, float alpha, const float* __restrict__ bias)
{
    constexpr uint32_t BTILE_BYTES = TRB ? (128 * RSH * 2) : (64 * RBH * 2);
    constexpr uint32_t STAGE_BYTES = ATILE_BYTES + BTILE_BYTES;

    extern __shared__ __half smem[];
    const uint32_t sbase = smem_u32(smem);

    const int tid  = threadIdx.x;
    const int wid  = tid >> 5;
    const int lane = tid & 31;
    const int wm   = wid >> 1;         // 0..1 -> 64-row slab
    const int wn   = wid & 1;          // 0..1 -> 64-col slab
    const int lg   = lane >> 2;        // 0..7
    const int lr   = lane & 3;         // 0..3

    const int zb = blockIdx.z / Hdiv;
    const int zh = blockIdx.z % Hdiv;
    const __half* A = Ag + zb * sAb + zh * sAh;
    const __half* B = Bg + zb * sBb + zh * sBh;
    Tout*         C = Cg + zb * sCb + zh * sCh;

    const int m0 = blockIdx.y * BM;
    const int n0 = blockIdx.x * BN;

    // A ldmatrix base (per-lane byte offset within a stage)
    const int arow = lane & 15;
    const int acol = (lane >> 4) << 3;
    const uint32_t aoff = ((wm * 64 + arow) * RSH + acol) * 2;

    // B ldmatrix base
    uint32_t boff;
    if constexpr (TRB) {
        const int brow = (lane & 7) | ((lane >> 4) << 3);
        const int bcol = ((lane >> 3) & 1) << 3;
        boff = ATILE_BYTES + ((wn * 64 + brow) * RSH + bcol) * 2;
    } else {
        const int krow = (lane & 7) + 8 * ((lane >> 3) & 1);
        const int ncol = wn * 64 + 8 * (lane >> 4);
        boff = ATILE_BYTES + krow * (RBH * 2) + ncol * 2;
    }

    float acc[4][8][4];
#pragma unroll
    for (int i = 0; i < 4; ++i)
#pragma unroll
        for (int j = 0; j < 8; ++j)
#pragma unroll
            for (int l = 0; l < 4; ++l) acc[i][j][l] = 0.f;

    const int NT = K / BKH;

    // one quarter of a stage load: 2 A-chunks + 2 B-chunks per thread (j=0..3)
    auto cp_chunk = [&](int kt, int j) {
        const int ring = kt % NSTAGE;
        const uint32_t base = sbase + ring * STAGE_BYTES;
        const int k0 = kt * BKH;
#pragma unroll
        for (int i = 2 * j; i < 2 * j + 2; ++i) {
            int id = tid + i * 128;
            int row = id >> 3, ch = id & 7;
            CP_ASYNC16(base + row * (RSH * 2) + ch * 16,
                       A + (size_t)(m0 + row) * lda + k0 + ch * 8);
        }
        if constexpr (TRB) {
#pragma unroll
            for (int i = 2 * j; i < 2 * j + 2; ++i) {
                int id = tid + i * 128;
                int row = id >> 3, ch = id & 7;
                CP_ASYNC16(base + ATILE_BYTES + row * (RSH * 2) + ch * 16,
                           B + (size_t)(n0 + row) * ldb + k0 + ch * 8);
            }
        } else {
#pragma unroll
            for (int i = 2 * j; i < 2 * j + 2; ++i) {
                int id = tid + i * 128;
                int row = id >> 4, ch = id & 15;
                CP_ASYNC16(base + ATILE_BYTES + row * (RBH * 2) + ch * 16,
                           B + (size_t)(k0 + row) * ldb + n0 + ch * 8);
            }
        }
    };

    auto load_stage = [&](int kt) {
#pragma unroll
        for (int j = 0; j < 4; ++j) cp_chunk(kt, j);
        CP_COMMIT();
    };

    // fragment loader: frags for k16-chunk ks (0..3) of the stage at 'stg'
    auto ldm_all = [&](uint32_t stg, int ks, uint32_t af[4][4], uint32_t bf[8][2]) {
#pragma unroll
        for (int mt = 0; mt < 4; ++mt)
            ldm_x4(af[mt][0], af[mt][1], af[mt][2], af[mt][3],
                   stg + aoff + mt * (16 * RSH * 2) + ks * 32);
        if constexpr (TRB) {
#pragma unroll
            for (int np = 0; np < 4; ++np)
                ldm_x4(bf[2 * np][0], bf[2 * np][1], bf[2 * np + 1][0], bf[2 * np + 1][1],
                       stg + boff + np * (16 * RSH * 2) + ks * 32);
        } else {
#pragma unroll
            for (int np = 0; np < 4; ++np)
                ldm_x4_t(bf[2 * np][0], bf[2 * np][1], bf[2 * np + 1][0], bf[2 * np + 1][1],
                         stg + boff + ks * (16 * RBH * 2) + np * 32);
        }
    };

    // one quarter of an mma phase: fixed mt row, all 8 nt (8 HMMA)
    auto mma_quarter = [&](uint32_t af[4][4], uint32_t bf[8][2], int mt) {
#pragma unroll
        for (int nt = 0; nt < 8; ++nt)
            mma_f16(acc[mt][nt][0], acc[mt][nt][1], acc[mt][nt][2], acc[mt][nt][3],
                    af[mt][0], af[mt][1], af[mt][2], af[mt][3],
                    bf[nt][0], bf[nt][1]);
    };

    auto mma_all = [&](uint32_t af[4][4], uint32_t bf[8][2]) {
#pragma unroll
        for (int mt = 0; mt < 4; ++mt) mma_quarter(af, bf, mt);
    };

    load_stage(0); load_stage(1);

    // Prologue: stage 0 complete + published; preload (kt=0, ks=0) frags.
    CP_WAIT1();
    __syncthreads();

    uint32_t afA[4][4], bfA[8][2], afB[4][4], bfB[8][2];
    ldm_all(sbase, 0, afA, bfA);

    for (int kt = 0; kt < NT; ++kt) {
        const uint32_t stg = sbase + (kt % NSTAGE) * STAGE_BYTES;
        const bool doLoad = (kt + 2 < NT);

        // phase ks0: cp.async chunks for stage kt+2 interleaved between
        // 8-HMMA groups (volatile asm order == issue order; this threads LSU
        // work into the tensor-stall shadow instead of a starving burst).
        ldm_all(stg, 1, afB, bfB);
        mma_quarter(afA, bfA, 0);  if (doLoad) cp_chunk(kt + 2, 0);
        mma_quarter(afA, bfA, 1);  if (doLoad) cp_chunk(kt + 2, 1);
        mma_quarter(afA, bfA, 2);  if (doLoad) cp_chunk(kt + 2, 2);
        mma_quarter(afA, bfA, 3);  if (doLoad) cp_chunk(kt + 2, 3);
        CP_COMMIT();   // exactly one group per body (keeps wait_group math)

        // phase ks1
        ldm_all(stg, 2, afA, bfA);
        mma_all(afB, bfB);

        // phase ks2
        ldm_all(stg, 3, afB, bfB);
        mma_all(afA, bfA);

        // stage kt+1 complete + published before prefetching from it
        CP_WAIT1();
        __syncthreads();

        // phase ks3 + cross-iteration prefetch of (kt+1, ks0)
        const int ktn = (kt + 1 < NT) ? kt + 1 : kt;
        ldm_all(sbase + (ktn % NSTAGE) * STAGE_BYTES, 0, afA, bfA);
        mma_all(afB, bfB);
    }

    // epilogue
#pragma unroll
    for (int mt = 0; mt < 4; ++mt) {
#pragma unroll
        for (int nt = 0; nt < 8; ++nt) {
            const int r0 = m0 + wm * 64 + mt * 16 + lg;
            const int c0 = n0 + wn * 64 + nt * 8 + 2 * lr;
            float b0v = 0.f, b1v = 0.f;
            if (bias) { b0v = bias[c0]; b1v = bias[c0 + 1]; }
            float v00 = alpha * acc[mt][nt][0] + b0v;
            float v01 = alpha * acc[mt][nt][1] + b1v;
            float v10 = alpha * acc[mt][nt][2] + b0v;
            float v11 = alpha * acc[mt][nt][3] + b1v;
            if constexpr (sizeof(Tout) == 4) {
                *(float2*)((float*)C + (size_t)r0 * ldc + c0)       = make_float2(v00, v01);
                *(float2*)((float*)C + (size_t)(r0 + 8) * ldc + c0) = make_float2(v10, v11);
            } else {
                *(__half2*)((__half*)C + (size_t)r0 * ldc + c0)       = __float22half2_rn(make_float2(v00, v01));
                *(__half2*)((__half*)C + (size_t)(r0 + 8) * ldc + c0) = __float22half2_rn(make_float2(v10, v11));
            }
        }
    }
}

// fp32 -> fp16 elementwise (vectorized x2)
__global__ void conv_h(const float* __restrict__ in, __half* __restrict__ out, int n2)
{
    int i = blockIdx.x * blockDim.x + threadIdx.x;
    if (i < n2) {
        float2 v = *(const float2*)(in + 2 * i);
        *(__half2*)(out + 2 * i) = __float22half2_rn(v);
    }
}

// ---------------------------------------------------------------------------
// Row softmax in place on fp16 logits. 256 thr, 2048 cols.
// ---------------------------------------------------------------------------
__global__ void softmax_rows(__half* __restrict__ P)
{
    __half* q = P + (size_t)blockIdx.x * SEQ;
    const int tid = threadIdx.x;

    float2 v[4];
    float mx = -1e30f;
#pragma unroll
    for (int i = 0; i < 4; ++i) {
        v[i] = __half22float2(*(const __half2*)(q + 2 * tid + 512 * i));
        mx = fmaxf(mx, fmaxf(v[i].x, v[i].y));
    }
    __shared__ float red[256];
    red[tid] = mx; __syncthreads();
    for (int s = 128; s > 0; s >>= 1) { if (tid < s) red[tid] = fmaxf(red[tid], red[tid + s]); __syncthreads(); }
    mx = red[0]; __syncthreads();
    float sum = 0.f;
#pragma unroll
    for (int i = 0; i < 4; ++i) {
        v[i].x = __expf(v[i].x - mx); v[i].y = __expf(v[i].y - mx);
        sum += v[i].x + v[i].y;
    }
    red[tid] = sum; __syncthreads();
    for (int s = 128; s > 0; s >>= 1) { if (tid < s) red[tid] += red[tid + s]; __syncthreads(); }
    const float inv = 1.f / red[0];
#pragma unroll
    for (int i = 0; i < 4; ++i)
        *(__half2*)(q + 2 * tid + 512 * i) =
            __float22half2_rn(make_float2(v[i].x * inv, v[i].y * inv));
}

// ---------------------------------------------------------------------------
// Launch — graph fork/join: V path overlaps the softmax window.
// ---------------------------------------------------------------------------
extern "C" void kernel_launch(void* const* d_in, const int* in_sizes, int n_in,
                              void* d_out, int out_size)
{
    const float* x  = (const float*)d_in[0];
    const float* Wq = (const float*)d_in[1];
    const float* bq = (const float*)d_in[2];
    const float* Wk = (const float*)d_in[3];
    const float* bk = (const float*)d_in[4];
    const float* Wv = (const float*)d_in[5];
    const float* bv = (const float*)d_in[6];
    const float* Wo = (const float*)d_in[7];
    const float* bo = (const float*)d_in[8];
    float* out = (float*)d_out;

    __half *pXh, *pQh, *pKh, *pVh, *pPh, *pAOh, *pWqh, *pWkh, *pWvh, *pWoh;
    cudaGetSymbolAddress((void**)&pXh,  g_Xh);
    cudaGetSymbolAddress((void**)&pQh,  g_Qh);
    cudaGetSymbolAddress((void**)&pKh,  g_Kh);
    cudaGetSymbolAddress((void**)&pVh,  g_Vh);
    cudaGetSymbolAddress((void**)&pPh,  g_Ph);
    cudaGetSymbolAddress((void**)&pAOh, g_AOh);
    cudaGetSymbolAddress((void**)&pWqh, g_Wqh);
    cudaGetSymbolAddress((void**)&pWkh, g_Wkh);
    cudaGetSymbolAddress((void**)&pWvh, g_Wvh);
    cudaGetSymbolAddress((void**)&pWoh, g_Woh);

    cudaFuncSetAttribute((const void*)h_gemm<__half, false>, cudaFuncAttributeMaxDynamicSharedMemorySize, SMEM_MAX);
    cudaFuncSetAttribute((const void*)h_gemm<__half, true>,  cudaFuncAttributeMaxDynamicSharedMemorySize, SMEM_MAX);
    cudaFuncSetAttribute((const void*)h_gemm<float, false>,  cudaFuncAttributeMaxDynamicSharedMemorySize, SMEM_MAX);

    // Side stream + events (host objects, created once; no device memory).
    static cudaStream_t s1 = nullptr;
    static cudaEvent_t evFork = nullptr, evJoin = nullptr;
    if (s1 == nullptr) {
        cudaStreamCreateWithFlags(&s1, cudaStreamNonBlocking);
        cudaEventCreateWithFlags(&evFork, cudaEventDisableTiming);
        cudaEventCreateWithFlags(&evJoin, cudaEventDisableTiming);
    }

    const float scale = 1.0f / sqrtf((float)EMBD);

    // 0) convert x + Wq + Wk (main stream). Wv/Wo convert later on side stream.
    conv_h<<<(MROWS * EMBD / 2 + 255) / 256, 256>>>(x,  pXh,  MROWS * EMBD / 2);
    conv_h<<<(EMBD * HE / 2 + 255) / 256, 256>>>(Wq, pWqh, EMBD * HE / 2);
    conv_h<<<(EMBD * HE / 2 + 255) / 256, 256>>>(Wk, pWkh, EMBD * HE / 2);

    // 1-2) Q, K projections (NN: B = W [512 x 4096])
    {
        dim3 g(HE / BN, MROWS / BM, 1);
        h_gemm<__half, false><<<g, 128, SMEM_MAX>>>(pXh, pWqh, pQh, EMBD, EMBD, HE, HE,
                                                    0, 0, 0, 0, 0, 0, 1, 1.f, bq);
        h_gemm<__half, false><<<g, 128, SMEM_MAX>>>(pXh, pWkh, pKh, EMBD, EMBD, HE, HE,
                                                    0, 0, 0, 0, 0, 0, 1, 1.f, bk);
    }

    // 3) logits = scale * Q K^T -> fp16 (NT)
    {
        dim3 g(SEQ / BN, SEQ / BM, BATCHN * HEADS);
        h_gemm<__half, true><<<g, 128, SMEM_MAX>>>(pQh, pKh, pPh, EMBD, HE, HE, SEQ,
                                                   (long)SEQ * HE, (long)EMBD,
                                                   (long)SEQ * HE, (long)EMBD,
                                                   (long)HEADS * SEQ * SEQ, (long)SEQ * SEQ,
                                                   HEADS, scale, nullptr);
    }

    // Fork AFTER scores: V path co-runs with the memory-bound softmax.
    cudaEventRecord(evFork, 0);
    cudaStreamWaitEvent(s1, evFork, 0);

    // side stream: conv Wv -> V projection -> conv Wo
    conv_h<<<(EMBD * HE / 2 + 255) / 256, 256, 0, s1>>>(Wv, pWvh, EMBD * HE / 2);
    {
        dim3 g(HE / BN, MROWS / BM, 1);
        h_gemm<__half, false><<<g, 128, SMEM_MAX, s1>>>(pXh, pWvh, pVh, EMBD, EMBD, HE, HE,
                                                        0, 0, 0, 0, 0, 0, 1, 1.f, bv);
    }
    conv_h<<<(HE * EMBD / 2 + 255) / 256, 256, 0, s1>>>(Wo, pWoh, HE * EMBD / 2);
    cudaEventRecord(evJoin, s1);

    // main stream: softmax in place (fp16), concurrent with V path
    softmax_rows<<<BATCHN * HEADS * SEQ, 256>>>(pPh);

    // join before AV
    cudaStreamWaitEvent(0, evJoin, 0);

    // 4) AO = P @ V (NN: B = V [s x emb] per head)
    {
        dim3 g(EMBD / BN, SEQ / BM, BATCHN * HEADS);
        h_gemm<__half, false><<<g, 128, SMEM_MAX>>>(pPh, pVh, pAOh, SEQ, SEQ, HE, HE,
                                                    (long)HEADS * SEQ * SEQ, (long)SEQ * SEQ,
                                                    (long)SEQ * HE, (long)EMBD,
                                                    (long)SEQ * HE, (long)EMBD,
                                                    HEADS, 1.f, nullptr);
    }

    // 5) out = AO @ Wo + bo (NN: B = Wo [4096 x 512])
    {
        dim3 g(EMBD / BN, MROWS / BM, 1);
        h_gemm<float, false><<<g, 128, SMEM_MAX>>>(pAOh, pWoh, out, HE, HE, EMBD, EMBD,
                                                   0, 0, 0, 0, 0, 0, 1, 1.f, bo);
    }
}

// round 12
// speedup vs baseline: 7.4871x; 1.0014x over previous
#include <cuda_runtime.h>
#include <cuda_fp16.h>
#include <math.h>
#include <stdint.h>

#define BATCHN 4
#define SEQ    2048
#define EMBD   512
#define HEADS  8
#define HE     4096            // HEADS * EMBD
#define MROWS  8192            // BATCHN * SEQ

// ---------------------------------------------------------------------------
// Scratch (allocation-free: device globals)
// ---------------------------------------------------------------------------
__device__ __half g_Xh [(size_t)MROWS * EMBD];
__device__ __half g_Qh [(size_t)MROWS * HE];
__device__ __half g_Kh [(size_t)MROWS * HE];
__device__ __half g_Vh [(size_t)MROWS * HE];
__device__ __half g_Ph [(size_t)BATCHN * HEADS * SEQ * SEQ];   // fp16 logits -> probs
__device__ __half g_AOh[(size_t)MROWS * HE];
__device__ __half g_Wqh[(size_t)EMBD * HE];
__device__ __half g_Wkh[(size_t)EMBD * HE];
__device__ __half g_Wvh[(size_t)EMBD * HE];
__device__ __half g_Woh[(size_t)HE * EMBD];

// ---------------------------------------------------------------------------
// helpers
// ---------------------------------------------------------------------------
__device__ __forceinline__ uint32_t smem_u32(const void* p) {
    uint32_t a;
    asm("{ .reg .u64 t; cvta.to.shared.u64 t, %1; cvt.u32.u64 %0, t; }" : "=r"(a) : "l"(p));
    return a;
}
__device__ __forceinline__ void mma_f16(float& c0, float& c1, float& c2, float& c3,
                                        uint32_t a0, uint32_t a1, uint32_t a2, uint32_t a3,
                                        uint32_t b0, uint32_t b1) {
    asm volatile("mma.sync.aligned.m16n8k16.row.col.f32.f16.f16.f32 "
                 "{%0,%1,%2,%3},{%4,%5,%6,%7},{%8,%9},{%0,%1,%2,%3};"
                 : "+f"(c0), "+f"(c1), "+f"(c2), "+f"(c3)
                 : "r"(a0), "r"(a1), "r"(a2), "r"(a3), "r"(b0), "r"(b1));
}
__device__ __forceinline__ void ldm_x4(uint32_t& r0, uint32_t& r1, uint32_t& r2,
                                       uint32_t& r3, uint32_t addr) {
    asm volatile("ldmatrix.sync.aligned.m8n8.x4.shared.b16 {%0,%1,%2,%3}, [%4];"
                 : "=r"(r0), "=r"(r1), "=r"(r2), "=r"(r3) : "r"(addr));
}
__device__ __forceinline__ void ldm_x4_t(uint32_t& r0, uint32_t& r1, uint32_t& r2,
                                         uint32_t& r3, uint32_t addr) {
    asm volatile("ldmatrix.sync.aligned.m8n8.x4.trans.shared.b16 {%0,%1,%2,%3}, [%4];"
                 : "=r"(r0), "=r"(r1), "=r"(r2), "=r"(r3) : "r"(addr));
}
#define CP_ASYNC16(s, g)  asm volatile("cp.async.cg.shared.global [%0], [%1], 16;" :: "r"(s), "l"(g) : "memory")
#define CP_COMMIT()       asm volatile("cp.async.commit_group;" ::: "memory")
#define CP_WAIT1()        asm volatile("cp.async.wait_group 1;" ::: "memory")

// ---------------------------------------------------------------------------
// fp16 GEMM, fp32 accum: C[M,N] = alpha * A[M,K] * op(B) (+ bias)
//   TRB=true : B is [N,K] (K-major)  -> C = A B^T   (non-trans ldmatrix)
//   TRB=false: B is [K,N] (N-major)  -> C = A B     (trans ldmatrix)
// CTA 256x128xBK64(halfs), 256 threads (1 CTA/SM), warp grid 4(M)x2(N),
// warp tile 64x64 (4x8 m16n8k16), 3-stage cp.async, cross-iteration
// fragment prefetch, cp.async interleaved into the mma stream.
// Rationale: doubles tensor work per kt (2048 cyc) while smem crossbar
// traffic stays ~1408 cyc -> tensor pipe becomes the binding resource.
// ---------------------------------------------------------------------------
#define BM 256
#define BN 128
#define BKH 64                          // halfs per stage-k (four k16 steps)
#define RSH 72                          // A / NT-B padded row stride (halfs)
#define RBH 136                         // NN-B padded row stride (halfs)
#define ATILE_BYTES (BM * RSH * 2)      // 36864
#define NSTAGE 3
#define SMEM_MAX (NSTAGE * (ATILE_BYTES + 128 * RSH * 2))   // 165888 (TRB variant)

template<typename Tout, bool TRB>
__global__ __launch_bounds__(256, 1)
void h_gemm(const __half* __restrict__ Ag, const __half* __restrict__ Bg,
            Tout* __restrict__ Cg, int K,
            long lda, long ldb, long ldc,
            long sAb, long sAh, long sBb, long sBh, long sCb, long sCh,
            int Hdiv, float alpha, const float* __restrict__ bias)
{
    constexpr uint32_t BTILE_BYTES = TRB ? (128 * RSH * 2) : (64 * RBH * 2);
    constexpr uint32_t STAGE_BYTES = ATILE_BYTES + BTILE_BYTES;

    extern __shared__ __half smem[];
    const uint32_t sbase = smem_u32(smem);

    const int tid  = threadIdx.x;
    const int wid  = tid >> 5;
    const int lane = tid & 31;
    const int wm   = wid >> 1;         // 0..3 -> 64-row slab
    const int wn   = wid & 1;          // 0..1 -> 64-col slab
    const int lg   = lane >> 2;        // 0..7
    const int lr   = lane & 3;         // 0..3

    const int zb = blockIdx.z / Hdiv;
    const int zh = blockIdx.z % Hdiv;
    const __half* A = Ag + zb * sAb + zh * sAh;
    const __half* B = Bg + zb * sBb + zh * sBh;
    Tout*         C = Cg + zb * sCb + zh * sCh;

    const int m0 = blockIdx.y * BM;
    const int n0 = blockIdx.x * BN;

    // A ldmatrix base (per-lane byte offset within a stage)
    const int arow = lane & 15;
    const int acol = (lane >> 4) << 3;
    const uint32_t aoff = ((wm * 64 + arow) * RSH + acol) * 2;

    // B ldmatrix base
    uint32_t boff;
    if constexpr (TRB) {
        const int brow = (lane & 7) | ((lane >> 4) << 3);
        const int bcol = ((lane >> 3) & 1) << 3;
        boff = ATILE_BYTES + ((wn * 64 + brow) * RSH + bcol) * 2;
    } else {
        const int krow = (lane & 7) + 8 * ((lane >> 3) & 1);
        const int ncol = wn * 64 + 8 * (lane >> 4);
        boff = ATILE_BYTES + krow * (RBH * 2) + ncol * 2;
    }

    float acc[4][8][4];
#pragma unroll
    for (int i = 0; i < 4; ++i)
#pragma unroll
        for (int j = 0; j < 8; ++j)
#pragma unroll
            for (int l = 0; l < 4; ++l) acc[i][j][l] = 0.f;

    const int NT = K / BKH;

    // one quarter of a stage load (j=0..3): A 2 chunks + B 1 chunk per thread
    auto cp_chunk = [&](int kt, int j) {
        const int ring = kt % NSTAGE;
        const uint32_t base = sbase + ring * STAGE_BYTES;
        const int k0 = kt * BKH;
        // A: 256 rows x 64 halfs (128B), 8 x 16B chunks per row; 2048 chunks
#pragma unroll
        for (int i = 2 * j; i < 2 * j + 2; ++i) {
            int id = tid + i * 256;
            int row = id >> 3, ch = id & 7;
            CP_ASYNC16(base + row * (RSH * 2) + ch * 16,
                       A + (size_t)(m0 + row) * lda + k0 + ch * 8);
        }
        if constexpr (TRB) {
            // B: 128 n-rows x 64 halfs; 1024 chunks
            {
                int id = tid + j * 256;
                int row = id >> 3, ch = id & 7;
                CP_ASYNC16(base + ATILE_BYTES + row * (RSH * 2) + ch * 16,
                           B + (size_t)(n0 + row) * ldb + k0 + ch * 8);
            }
        } else {
            // B: 64 k-rows x 128 halfs (256B), 16 x 16B chunks/row; 1024 chunks
            {
                int id = tid + j * 256;
                int row = id >> 4, ch = id & 15;
                CP_ASYNC16(base + ATILE_BYTES + row * (RBH * 2) + ch * 16,
                           B + (size_t)(k0 + row) * ldb + n0 + ch * 8);
            }
        }
    };

    auto load_stage = [&](int kt) {
#pragma unroll
        for (int j = 0; j < 4; ++j) cp_chunk(kt, j);
        CP_COMMIT();
    };

    // fragment loader: frags for k16-chunk ks (0..3) of the stage at 'stg'
    auto ldm_all = [&](uint32_t stg, int ks, uint32_t af[4][4], uint32_t bf[8][2]) {
#pragma unroll
        for (int mt = 0; mt < 4; ++mt)
            ldm_x4(af[mt][0], af[mt][1], af[mt][2], af[mt][3],
                   stg + aoff + mt * (16 * RSH * 2) + ks * 32);
        if constexpr (TRB) {
#pragma unroll
            for (int np = 0; np < 4; ++np)
                ldm_x4(bf[2 * np][0], bf[2 * np][1], bf[2 * np + 1][0], bf[2 * np + 1][1],
                       stg + boff + np * (16 * RSH * 2) + ks * 32);
        } else {
#pragma unroll
            for (int np = 0; np < 4; ++np)
                ldm_x4_t(bf[2 * np][0], bf[2 * np][1], bf[2 * np + 1][0], bf[2 * np + 1][1],
                         stg + boff + ks * (16 * RBH * 2) + np * 32);
        }
    };

    // one quarter of an mma phase: fixed mt row, all 8 nt (8 HMMA)
    auto mma_quarter = [&](uint32_t af[4][4], uint32_t bf[8][2], int mt) {
#pragma unroll
        for (int nt = 0; nt < 8; ++nt)
            mma_f16(acc[mt][nt][0], acc[mt][nt][1], acc[mt][nt][2], acc[mt][nt][3],
                    af[mt][0], af[mt][1], af[mt][2], af[mt][3],
                    bf[nt][0], bf[nt][1]);
    };

    auto mma_all = [&](uint32_t af[4][4], uint32_t bf[8][2]) {
#pragma unroll
        for (int mt = 0; mt < 4; ++mt) mma_quarter(af, bf, mt);
    };

    load_stage(0); load_stage(1);

    // Prologue: stage 0 complete + published; preload (kt=0, ks=0) frags.
    CP_WAIT1();
    __syncthreads();

    uint32_t afA[4][4], bfA[8][2], afB[4][4], bfB[8][2];
    ldm_all(sbase, 0, afA, bfA);

    for (int kt = 0; kt < NT; ++kt) {
        const uint32_t stg = sbase + (kt % NSTAGE) * STAGE_BYTES;
        const bool doLoad = (kt + 2 < NT);

        // phase ks0 with interleaved cp.async for stage kt+2
        ldm_all(stg, 1, afB, bfB);
        mma_quarter(afA, bfA, 0);  if (doLoad) cp_chunk(kt + 2, 0);
        mma_quarter(afA, bfA, 1);  if (doLoad) cp_chunk(kt + 2, 1);
        mma_quarter(afA, bfA, 2);  if (doLoad) cp_chunk(kt + 2, 2);
        mma_quarter(afA, bfA, 3);  if (doLoad) cp_chunk(kt + 2, 3);
        CP_COMMIT();   // exactly one group per body (keeps wait_group math)

        // phase ks1
        ldm_all(stg, 2, afA, bfA);
        mma_all(afB, bfB);

        // phase ks2
        ldm_all(stg, 3, afB, bfB);
        mma_all(afA, bfA);

        // stage kt+1 complete + published before prefetching from it
        CP_WAIT1();
        __syncthreads();

        // phase ks3 + cross-iteration prefetch of (kt+1, ks0)
        const int ktn = (kt + 1 < NT) ? kt + 1 : kt;
        ldm_all(sbase + (ktn % NSTAGE) * STAGE_BYTES, 0, afA, bfA);
        mma_all(afB, bfB);
    }

    // epilogue
#pragma unroll
    for (int mt = 0; mt < 4; ++mt) {
#pragma unroll
        for (int nt = 0; nt < 8; ++nt) {
            const int r0 = m0 + wm * 64 + mt * 16 + lg;
            const int c0 = n0 + wn * 64 + nt * 8 + 2 * lr;
            float b0v = 0.f, b1v = 0.f;
            if (bias) { b0v = bias[c0]; b1v = bias[c0 + 1]; }
            float v00 = alpha * acc[mt][nt][0] + b0v;
            float v01 = alpha * acc[mt][nt][1] + b1v;
            float v10 = alpha * acc[mt][nt][2] + b0v;
            float v11 = alpha * acc[mt][nt][3] + b1v;
            if constexpr (sizeof(Tout) == 4) {
                *(float2*)((float*)C + (size_t)r0 * ldc + c0)       = make_float2(v00, v01);
                *(float2*)((float*)C + (size_t)(r0 + 8) * ldc + c0) = make_float2(v10, v11);
            } else {
                *(__half2*)((__half*)C + (size_t)r0 * ldc + c0)       = __float22half2_rn(make_float2(v00, v01));
                *(__half2*)((__half*)C + (size_t)(r0 + 8) * ldc + c0) = __float22half2_rn(make_float2(v10, v11));
            }
        }
    }
}

// fp32 -> fp16 elementwise (vectorized x2)
__global__ void conv_h(const float* __restrict__ in, __half* __restrict__ out, int n2)
{
    int i = blockIdx.x * blockDim.x + threadIdx.x;
    if (i < n2) {
        float2 v = *(const float2*)(in + 2 * i);
        *(__half2*)(out + 2 * i) = __float22half2_rn(v);
    }
}

// ---------------------------------------------------------------------------
// Row softmax in place on fp16 logits. 256 thr, 2048 cols.
// ---------------------------------------------------------------------------
__global__ void softmax_rows(__half* __restrict__ P)
{
    __half* q = P + (size_t)blockIdx.x * SEQ;
    const int tid = threadIdx.x;

    float2 v[4];
    float mx = -1e30f;
#pragma unroll
    for (int i = 0; i < 4; ++i) {
        v[i] = __half22float2(*(const __half2*)(q + 2 * tid + 512 * i));
        mx = fmaxf(mx, fmaxf(v[i].x, v[i].y));
    }
    __shared__ float red[256];
    red[tid] = mx; __syncthreads();
    for (int s = 128; s > 0; s >>= 1) { if (tid < s) red[tid] = fmaxf(red[tid], red[tid + s]); __syncthreads(); }
    mx = red[0]; __syncthreads();
    float sum = 0.f;
#pragma unroll
    for (int i = 0; i < 4; ++i) {
        v[i].x = __expf(v[i].x - mx); v[i].y = __expf(v[i].y - mx);
        sum += v[i].x + v[i].y;
    }
    red[tid] = sum; __syncthreads();
    for (int s = 128; s > 0; s >>= 1) { if (tid < s) red[tid] += red[tid + s]; __syncthreads(); }
    const float inv = 1.f / red[0];
#pragma unroll
    for (int i = 0; i < 4; ++i)
        *(__half2*)(q + 2 * tid + 512 * i) =
            __float22half2_rn(make_float2(v[i].x * inv, v[i].y * inv));
}

// ---------------------------------------------------------------------------
// Launch — graph fork/join: V path overlaps the softmax window.
// ---------------------------------------------------------------------------
extern "C" void kernel_launch(void* const* d_in, const int* in_sizes, int n_in,
                              void* d_out, int out_size)
{
    const float* x  = (const float*)d_in[0];
    const float* Wq = (const float*)d_in[1];
    const float* bq = (const float*)d_in[2];
    const float* Wk = (const float*)d_in[3];
    const float* bk = (const float*)d_in[4];
    const float* Wv = (const float*)d_in[5];
    const float* bv = (const float*)d_in[6];
    const float* Wo = (const float*)d_in[7];
    const float* bo = (const float*)d_in[8];
    float* out = (float*)d_out;

    __half *pXh, *pQh, *pKh, *pVh, *pPh, *pAOh, *pWqh, *pWkh, *pWvh, *pWoh;
    cudaGetSymbolAddress((void**)&pXh,  g_Xh);
    cudaGetSymbolAddress((void**)&pQh,  g_Qh);
    cudaGetSymbolAddress((void**)&pKh,  g_Kh);
    cudaGetSymbolAddress((void**)&pVh,  g_Vh);
    cudaGetSymbolAddress((void**)&pPh,  g_Ph);
    cudaGetSymbolAddress((void**)&pAOh, g_AOh);
    cudaGetSymbolAddress((void**)&pWqh, g_Wqh);
    cudaGetSymbolAddress((void**)&pWkh, g_Wkh);
    cudaGetSymbolAddress((void**)&pWvh, g_Wvh);
    cudaGetSymbolAddress((void**)&pWoh, g_Woh);

    cudaFuncSetAttribute((const void*)h_gemm<__half, false>, cudaFuncAttributeMaxDynamicSharedMemorySize, SMEM_MAX);
    cudaFuncSetAttribute((const void*)h_gemm<__half, true>,  cudaFuncAttributeMaxDynamicSharedMemorySize, SMEM_MAX);
    cudaFuncSetAttribute((const void*)h_gemm<float, false>,  cudaFuncAttributeMaxDynamicSharedMemorySize, SMEM_MAX);

    // Side stream + events (host objects, created once; no device memory).
    static cudaStream_t s1 = nullptr;
    static cudaEvent_t evFork = nullptr, evJoin = nullptr;
    if (s1 == nullptr) {
        cudaStreamCreateWithFlags(&s1, cudaStreamNonBlocking);
        cudaEventCreateWithFlags(&evFork, cudaEventDisableTiming);
        cudaEventCreateWithFlags(&evJoin, cudaEventDisableTiming);
    }

    const float scale = 1.0f / sqrtf((float)EMBD);

    // 0) convert x + Wq + Wk (main stream). Wv/Wo convert later on side stream.
    conv_h<<<(MROWS * EMBD / 2 + 255) / 256, 256>>>(x,  pXh,  MROWS * EMBD / 2);
    conv_h<<<(EMBD * HE / 2 + 255) / 256, 256>>>(Wq, pWqh, EMBD * HE / 2);
    conv_h<<<(EMBD * HE / 2 + 255) / 256, 256>>>(Wk, pWkh, EMBD * HE / 2);

    // 1-2) Q, K projections (NN: B = W [512 x 4096])
    {
        dim3 g(HE / BN, MROWS / BM, 1);
        h_gemm<__half, false><<<g, 256, SMEM_MAX>>>(pXh, pWqh, pQh, EMBD, EMBD, HE, HE,
                                                    0, 0, 0, 0, 0, 0, 1, 1.f, bq);
        h_gemm<__half, false><<<g, 256, SMEM_MAX>>>(pXh, pWkh, pKh, EMBD, EMBD, HE, HE,
                                                    0, 0, 0, 0, 0, 0, 1, 1.f, bk);
    }

    // 3) logits = scale * Q K^T -> fp16 (NT)
    {
        dim3 g(SEQ / BN, SEQ / BM, BATCHN * HEADS);
        h_gemm<__half, true><<<g, 256, SMEM_MAX>>>(pQh, pKh, pPh, EMBD, HE, HE, SEQ,
                                                   (long)SEQ * HE, (long)EMBD,
                                                   (long)SEQ * HE, (long)EMBD,
                                                   (long)HEADS * SEQ * SEQ, (long)SEQ * SEQ,
                                                   HEADS, scale, nullptr);
    }

    // Fork AFTER scores: V path co-runs with the memory-bound softmax.
    cudaEventRecord(evFork, 0);
    cudaStreamWaitEvent(s1, evFork, 0);

    // side stream: conv Wv -> V projection -> conv Wo
    conv_h<<<(EMBD * HE / 2 + 255) / 256, 256, 0, s1>>>(Wv, pWvh, EMBD * HE / 2);
    {
        dim3 g(HE / BN, MROWS / BM, 1);
        h_gemm<__half, false><<<g, 256, SMEM_MAX, s1>>>(pXh, pWvh, pVh, EMBD, EMBD, HE, HE,
                                                        0, 0, 0, 0, 0, 0, 1, 1.f, bv);
    }
    conv_h<<<(HE * EMBD / 2 + 255) / 256, 256, 0, s1>>>(Wo, pWoh, HE * EMBD / 2);
    cudaEventRecord(evJoin, s1);

    // main stream: softmax in place (fp16), concurrent with V path
    softmax_rows<<<BATCHN * HEADS * SEQ, 256>>>(pPh);

    // join before AV
    cudaStreamWaitEvent(0, evJoin, 0);

    // 4) AO = P @ V (NN: B = V [s x emb] per head)
    {
        dim3 g(EMBD / BN, SEQ / BM, BATCHN * HEADS);
        h_gemm<__half, false><<<g, 256, SMEM_MAX>>>(pPh, pVh, pAOh, SEQ, SEQ, HE, HE,
                                                    (long)HEADS * SEQ * SEQ, (long)SEQ * SEQ,
                                                    (long)SEQ * HE, (long)EMBD,
                                                    (long)SEQ * HE, (long)EMBD,
                                                    HEADS, 1.f, nullptr);
    }

    // 5) out = AO @ Wo + bo (NN: B = Wo [4096 x 512])
    {
        dim3 g(EMBD / BN, MROWS / BM, 1);
        h_gemm<float, false><<<g, 256, SMEM_MAX>>>(pAOh, pWoh, out, HE, HE, EMBD, EMBD,
                                                   0, 0, 0, 0, 0, 0, 1, 1.f, bo);
    }
}